// round 7
// baseline (speedup 1.0000x reference)
#include <cuda_runtime.h>
#include <cuda_bf16.h>

#define kT 20000
#define kE 300
#define kS 400
#define kH 150
#define NSPANS (10 * kT - 45)
#define TOKW 452    // padded row stride: cols 0:150 Ha, 150:300 A, 300:450 B
#define TOKN 450    // logical width
#define H1P 160     // padded h1 row

typedef unsigned long long ull;

// Scratch (allocation-free rule: __device__ globals)
__device__ float g_tok[(size_t)kT * TOKW];
__device__ float g_Hb[(size_t)kT * kH];
__device__ float g_E[(size_t)kT * kH];
__device__ float g_attn[kT];
__device__ __nv_bfloat16 g_H1h[(size_t)NSPANS * H1P];
__device__ __nv_bfloat16 g_H1l[(size_t)NSPANS * H1P];
__device__ __nv_bfloat16 g_W2s[2 * H1P * H1P];
__device__ float g_b2p[H1P];
__device__ float g_w3p[H1P];

static __device__ __forceinline__ unsigned sm_u32(const void* p) {
    return (unsigned)__cvta_generic_to_shared(p);
}
static __device__ __forceinline__ unsigned pack_bf2(__nv_bfloat16 a, __nv_bfloat16 b) {
    unsigned r;
    unsigned short ua = *(unsigned short*)&a, ub = *(unsigned short*)&b;
    asm("mov.b32 %0, {%1, %2};" : "=r"(r) : "h"(ua), "h"(ub));
    return r;
}

// ---------------------------------------------------------------------------
// Generic split-bf16 tensor-core GEMM, f32 in / f32 out.
// C[M x N] = A[M x K] @ B[K x N], B given as up to 3 col segments of width 150.
// Block tile 128M x 160N, K in steps of 16, 8 warps (4M x 2N), double-buffered.
// NOTE: requires lda % 4 == 0 (A row stride 16B-aligned for float4 loads).
// ---------------------------------------------------------------------------
#define MBM 128
#define MBN 160
#define MBK 16

__global__ __launch_bounds__(256) void mma_gemm(
    int M, int N, int K,
    const float* __restrict__ A, int lda,
    const float* __restrict__ B0, const float* __restrict__ B1,
    const float* __restrict__ B2,
    const float* __restrict__ bias0, const float* __restrict__ bias1,
    int relu_mask,
    float* __restrict__ C, int ldc)
{
    __shared__ __align__(16) __nv_bfloat16 As[2][2][128 * 24];
    __shared__ __align__(16) __nv_bfloat16 Bs[2][2][16 * 168];

    int tid = threadIdx.x;
    int m0 = blockIdx.x * MBM, n0 = blockIdx.y * MBN;
    int wid = tid >> 5, lane = tid & 31;
    int warpM = wid & 3, warpN = wid >> 2;

    float Cr[2][10][4] = {};
    int nsteps = (K + MBK - 1) / MBK;

    auto stage = [&](int ks, int buf) {
        int k0 = ks * MBK;
        // A: 128 rows x 4 quads of 4 k-values
        #pragma unroll 2
        for (int c = tid; c < 512; c += 256) {
            int r = c >> 2, q = c & 3;
            int kk = k0 + q * 4;
            int row = min(m0 + r, M - 1);
            float4 v;
            if (kk + 3 < K) {
                v = *(const float4*)&A[(size_t)row * lda + kk];
            } else {
                float* vp = (float*)&v;
                #pragma unroll
                for (int i = 0; i < 4; i++)
                    vp[i] = (kk + i < K) ? A[(size_t)row * lda + kk + i] : 0.f;
            }
            float* vp = (float*)&v;
            __nv_bfloat16 h[4], l[4];
            #pragma unroll
            for (int i = 0; i < 4; i++) {
                h[i] = __float2bfloat16_rn(vp[i]);
                l[i] = __float2bfloat16_rn(vp[i] - __bfloat162float(h[i]));
            }
            uint2 sh = {pack_bf2(h[0], h[1]), pack_bf2(h[2], h[3])};
            uint2 sl = {pack_bf2(l[0], l[1]), pack_bf2(l[2], l[3])};
            *(uint2*)&As[buf][0][r * 24 + q * 4] = sh;
            *(uint2*)&As[buf][1][r * 24 + q * 4] = sl;
        }
        // B: 16 k-rows x 80 col-pairs
        #pragma unroll 5
        for (int c = tid; c < 1280; c += 256) {
            int row = c / 80, p = c % 80;
            int nloc = p * 2;
            int n = n0 + nloc;
            int kk = k0 + row;
            float v0 = 0.f, v1 = 0.f;
            if (kk < K && n < N) {
                int seg = n / 150, nn = n - seg * 150;
                const float* Bp = (seg == 0) ? B0 : ((seg == 1) ? B1 : B2);
                v0 = Bp[(size_t)kk * 150 + nn];
                if (n + 1 < N) v1 = Bp[(size_t)kk * 150 + nn + 1];
            }
            __nv_bfloat16 h0 = __float2bfloat16_rn(v0);
            __nv_bfloat16 h1 = __float2bfloat16_rn(v1);
            __nv_bfloat16 l0 = __float2bfloat16_rn(v0 - __bfloat162float(h0));
            __nv_bfloat16 l1 = __float2bfloat16_rn(v1 - __bfloat162float(h1));
            *(unsigned*)&Bs[buf][0][row * 168 + nloc] = pack_bf2(h0, h1);
            *(unsigned*)&Bs[buf][1][row * 168 + nloc] = pack_bf2(l0, l1);
        }
    };

    stage(0, 0);
    __syncthreads();

    for (int ks = 0; ks < nsteps; ks++) {
        int buf = ks & 1;
        if (ks + 1 < nsteps) stage(ks + 1, buf ^ 1);

        unsigned a[2][2][4];
        #pragma unroll
        for (int sp = 0; sp < 2; sp++)
            #pragma unroll
            for (int mf = 0; mf < 2; mf++) {
                unsigned addr = sm_u32(
                    &As[buf][sp][(warpM * 32 + mf * 16 + (lane & 15)) * 24 +
                                 (lane >> 4) * 8]);
                asm volatile(
                    "ldmatrix.sync.aligned.m8n8.x4.shared.b16 {%0,%1,%2,%3}, [%4];"
                    : "=r"(a[sp][mf][0]), "=r"(a[sp][mf][1]),
                      "=r"(a[sp][mf][2]), "=r"(a[sp][mf][3])
                    : "r"(addr));
            }

        #pragma unroll
        for (int np = 0; np < 5; np++) {
            int nbase = warpN * 80 + np * 16;
            unsigned bh[4], bl[4];
            {
                unsigned addr = sm_u32(
                    &Bs[buf][0][(lane & 15) * 168 + nbase + (lane >> 4) * 8]);
                asm volatile(
                    "ldmatrix.sync.aligned.m8n8.x4.trans.shared.b16 {%0,%1,%2,%3}, [%4];"
                    : "=r"(bh[0]), "=r"(bh[1]), "=r"(bh[2]), "=r"(bh[3])
                    : "r"(addr));
            }
            {
                unsigned addr = sm_u32(
                    &Bs[buf][1][(lane & 15) * 168 + nbase + (lane >> 4) * 8]);
                asm volatile(
                    "ldmatrix.sync.aligned.m8n8.x4.trans.shared.b16 {%0,%1,%2,%3}, [%4];"
                    : "=r"(bl[0]), "=r"(bl[1]), "=r"(bl[2]), "=r"(bl[3])
                    : "r"(addr));
            }
            #pragma unroll
            for (int mf = 0; mf < 2; mf++) {
                float* c0 = Cr[mf][2 * np];
                float* c1 = Cr[mf][2 * np + 1];
                asm volatile(
                    "mma.sync.aligned.m16n8k16.row.col.f32.bf16.bf16.f32 "
                    "{%0,%1,%2,%3},{%4,%5,%6,%7},{%8,%9},{%0,%1,%2,%3};"
                    : "+f"(c0[0]), "+f"(c0[1]), "+f"(c0[2]), "+f"(c0[3])
                    : "r"(a[0][mf][0]), "r"(a[0][mf][1]), "r"(a[0][mf][2]),
                      "r"(a[0][mf][3]), "r"(bh[0]), "r"(bh[1]));
                asm volatile(
                    "mma.sync.aligned.m16n8k16.row.col.f32.bf16.bf16.f32 "
                    "{%0,%1,%2,%3},{%4,%5,%6,%7},{%8,%9},{%0,%1,%2,%3};"
                    : "+f"(c1[0]), "+f"(c1[1]), "+f"(c1[2]), "+f"(c1[3])
                    : "r"(a[0][mf][0]), "r"(a[0][mf][1]), "r"(a[0][mf][2]),
                      "r"(a[0][mf][3]), "r"(bh[2]), "r"(bh[3]));
                asm volatile(
                    "mma.sync.aligned.m16n8k16.row.col.f32.bf16.bf16.f32 "
                    "{%0,%1,%2,%3},{%4,%5,%6,%7},{%8,%9},{%0,%1,%2,%3};"
                    : "+f"(c0[0]), "+f"(c0[1]), "+f"(c0[2]), "+f"(c0[3])
                    : "r"(a[1][mf][0]), "r"(a[1][mf][1]), "r"(a[1][mf][2]),
                      "r"(a[1][mf][3]), "r"(bh[0]), "r"(bh[1]));
                asm volatile(
                    "mma.sync.aligned.m16n8k16.row.col.f32.bf16.bf16.f32 "
                    "{%0,%1,%2,%3},{%4,%5,%6,%7},{%8,%9},{%0,%1,%2,%3};"
                    : "+f"(c1[0]), "+f"(c1[1]), "+f"(c1[2]), "+f"(c1[3])
                    : "r"(a[1][mf][0]), "r"(a[1][mf][1]), "r"(a[1][mf][2]),
                      "r"(a[1][mf][3]), "r"(bh[2]), "r"(bh[3]));
                asm volatile(
                    "mma.sync.aligned.m16n8k16.row.col.f32.bf16.bf16.f32 "
                    "{%0,%1,%2,%3},{%4,%5,%6,%7},{%8,%9},{%0,%1,%2,%3};"
                    : "+f"(c0[0]), "+f"(c0[1]), "+f"(c0[2]), "+f"(c0[3])
                    : "r"(a[0][mf][0]), "r"(a[0][mf][1]), "r"(a[0][mf][2]),
                      "r"(a[0][mf][3]), "r"(bl[0]), "r"(bl[1]));
                asm volatile(
                    "mma.sync.aligned.m16n8k16.row.col.f32.bf16.bf16.f32 "
                    "{%0,%1,%2,%3},{%4,%5,%6,%7},{%8,%9},{%0,%1,%2,%3};"
                    : "+f"(c1[0]), "+f"(c1[1]), "+f"(c1[2]), "+f"(c1[3])
                    : "r"(a[0][mf][0]), "r"(a[0][mf][1]), "r"(a[0][mf][2]),
                      "r"(a[0][mf][3]), "r"(bl[2]), "r"(bl[3]));
            }
        }
        __syncthreads();
    }

    // epilogue: f32 out with per-segment bias/relu
    int tq = lane & 3, g = lane >> 2;
    #pragma unroll
    for (int mf = 0; mf < 2; mf++) {
        int mr0 = m0 + warpM * 32 + mf * 16 + g;
        #pragma unroll
        for (int nf = 0; nf < 10; nf++) {
            int n = n0 + warpN * 80 + nf * 8 + tq * 2;
            if (n >= N) continue;
            int seg = n / 150;
            float* c = Cr[mf][nf];
            float bb0 = 0.f, bb1 = 0.f;
            if (seg == 0 && bias0) { bb0 = bias0[n]; bb1 = bias0[n + 1]; }
            if (seg == 1 && bias1) { bb0 = bias1[n - 150]; bb1 = bias1[n - 149]; }
            bool rl = (relu_mask >> seg) & 1;
            float v0 = c[0] + bb0, v1 = c[1] + bb1;
            float v2 = c[2] + bb0, v3 = c[3] + bb1;
            if (rl) {
                v0 = fmaxf(v0, 0.f); v1 = fmaxf(v1, 0.f);
                v2 = fmaxf(v2, 0.f); v3 = fmaxf(v3, 0.f);
            }
            bool n1ok = (n + 1 < N);
            if (mr0 < M) {
                C[(size_t)mr0 * ldc + n] = v0;
                if (n1ok) C[(size_t)mr0 * ldc + n + 1] = v1;
            }
            if (mr0 + 8 < M) {
                C[(size_t)(mr0 + 8) * ldc + n] = v2;
                if (n1ok) C[(size_t)(mr0 + 8) * ldc + n + 1] = v3;
            }
        }
    }
}

// ---------------------------------------------------------------------------
// Attention output layer (warp per token)
// ---------------------------------------------------------------------------
__global__ void attn_out_kernel(const float* __restrict__ Hb,
                                const float* __restrict__ W3,
                                const float* __restrict__ b3,
                                float* __restrict__ out, int M)
{
    int gwarp = (blockIdx.x * blockDim.x + threadIdx.x) >> 5;
    int lane = threadIdx.x & 31;
    if (gwarp >= M) return;
    float acc = 0.f;
    #pragma unroll
    for (int k = lane; k < kH; k += 32)
        acc = fmaf(Hb[(size_t)gwarp * kH + k], W3[k], acc);
    #pragma unroll
    for (int o = 16; o > 0; o >>= 1)
        acc += __shfl_down_sync(0xffffffffu, acc, o);
    if (lane == 0) out[gwarp] = acc + b3[0];
}

// ---------------------------------------------------------------------------
// Prep: split W2 into padded bf16 hi/lo [160][160], pad b2/W3.
// ---------------------------------------------------------------------------
__global__ void prep_kernel(const float* __restrict__ W2,
                            const float* __restrict__ b2,
                            const float* __restrict__ W3,
                            __nv_bfloat16* __restrict__ W2s,
                            float* __restrict__ b2p, float* __restrict__ w3p)
{
    int i = blockIdx.x * blockDim.x + threadIdx.x;
    if (i < H1P * H1P) {
        int r = i / H1P, c = i % H1P;
        float w = (r < kH && c < kH) ? W2[r * kH + c] : 0.f;
        __nv_bfloat16 hi = __float2bfloat16(w);
        __nv_bfloat16 lo = __float2bfloat16(w - __bfloat162float(hi));
        W2s[i] = hi;
        W2s[H1P * H1P + i] = lo;
    }
    if (i < H1P) {
        b2p[i] = (i < kH) ? b2[i] : 0.f;
        w3p[i] = (i < kH) ? W3[i] : 0.f;
    }
}

// ---------------------------------------------------------------------------
// h1 assembly: width-specialized, 8 spans per batch, writes split-bf16 H1.
// ---------------------------------------------------------------------------
#define CH 8

__global__ __launch_bounds__(160) void h1_kernel(
    const float* __restrict__ attn,
    const float* __restrict__ tok,
    const float* __restrict__ Em,
    __nv_bfloat16* __restrict__ H1h, __nv_bfloat16* __restrict__ H1l)
{
    int n = blockIdx.y + 1;
    int S = kT - n + 1;
    int chunk = (S + gridDim.x - 1) / gridDim.x;
    int sa = blockIdx.x * chunk;
    int sb = min(sa + chunk, S);
    int off = (n - 1) * (kT + 1) - (n * (n - 1)) / 2;

    int h = threadIdx.x;
    bool act = h < kH;

    __shared__ float Esm[17][160];
    __shared__ float sw[CH][10];

    for (int s0 = sa; s0 < sb; s0 += CH) {
        int nsp = min(CH, sb - s0);
        int rows = n + nsp - 1;

        if (act)
            for (int r = 0; r < rows; r++)
                Esm[r][h] = Em[(size_t)(s0 + r) * kH + h];

        if (h < nsp) {
            int s = s0 + h;
            float w[10];
            float mx = -1e30f;
            for (int j = 0; j < n; j++) {
                float v = attn[s + j];
                w[j] = v;
                mx = fmaxf(mx, v);
            }
            float sum = 0.f;
            for (int j = 0; j < n; j++) {
                float e = __expf(w[j] - mx);
                w[j] = e;
                sum += e;
            }
            float inv = 1.f / sum;
            for (int j = 0; j < n; j++) sw[h][j] = w[j] * inv;
        }
        __syncthreads();

        if (act) {
            for (int sp = 0; sp < nsp; sp++) {
                int s = s0 + sp;
                float v = tok[(size_t)s * TOKW + 150 + h]
                        + tok[(size_t)(s + n - 1) * TOKW + 300 + h];
                for (int j = 0; j < n; j++)
                    v = fmaf(sw[sp][j], Esm[sp + j][h], v);
                v = fmaxf(v, 0.f);
                __nv_bfloat16 hi = __float2bfloat16(v);
                __nv_bfloat16 lo = __float2bfloat16(v - __bfloat162float(hi));
                size_t idx = (size_t)(off + s0 + sp) * H1P + h;
                H1h[idx] = hi;
                H1l[idx] = lo;
            }
        } else {
            for (int sp = 0; sp < nsp; sp++) {
                size_t idx = (size_t)(off + s0 + sp) * H1P + h;
                H1h[idx] = __float2bfloat16(0.f);
                H1l[idx] = __float2bfloat16(0.f);
            }
        }
        __syncthreads();
    }
}

// ---------------------------------------------------------------------------
// Score GEMM on tensor cores: split-bf16 3-product, fused relu/W3 epilogue.
// ---------------------------------------------------------------------------
#define SCBM 128

__global__ __launch_bounds__(256, 1) void score_mma(
    const __nv_bfloat16* __restrict__ H1h, const __nv_bfloat16* __restrict__ H1l,
    const __nv_bfloat16* __restrict__ W2s,
    const float* __restrict__ b2p, const float* __restrict__ w3p,
    const float* __restrict__ b3,
    float* __restrict__ out, int M)
{
    __shared__ __align__(16) __nv_bfloat16 As[2][2][128 * 24];
    __shared__ __align__(16) __nv_bfloat16 Bs[2][2][16 * 168];
    __shared__ float red[128][2];

    int tid = threadIdx.x;
    int m0 = blockIdx.x * SCBM;
    int wid = tid >> 5, lane = tid & 31;
    int warpM = wid & 3, warpN = wid >> 2;

    float C[2][10][4] = {};

    auto stage = [&](int ks, int buf) {
        int k0 = ks * 16;
        #pragma unroll
        for (int c = tid; c < 512; c += 256) {
            int sp = c >> 8, tt = c & 255, r = tt >> 1, half = tt & 1;
            int mrow = min(m0 + r, M - 1);
            const __nv_bfloat16* src =
                (sp ? H1l : H1h) + (size_t)mrow * H1P + k0 + half * 8;
            *(int4*)&As[buf][sp][r * 24 + half * 8] = *(const int4*)src;
        }
        for (int c = tid; c < 640; c += 256) {
            int sp = c / 320, cc = c % 320, row = cc / 20, offc = cc % 20;
            const __nv_bfloat16* src =
                W2s + (size_t)sp * H1P * H1P + (size_t)(k0 + row) * H1P + offc * 8;
            *(int4*)&Bs[buf][sp][row * 168 + offc * 8] = *(const int4*)src;
        }
    };

    stage(0, 0);
    __syncthreads();

    for (int ks = 0; ks < 10; ks++) {
        int buf = ks & 1;
        if (ks < 9) stage(ks + 1, buf ^ 1);

        unsigned a[2][2][4];
        #pragma unroll
        for (int sp = 0; sp < 2; sp++)
            #pragma unroll
            for (int mf = 0; mf < 2; mf++) {
                unsigned addr = sm_u32(
                    &As[buf][sp][(warpM * 32 + mf * 16 + (lane & 15)) * 24 +
                                 (lane >> 4) * 8]);
                asm volatile(
                    "ldmatrix.sync.aligned.m8n8.x4.shared.b16 {%0,%1,%2,%3}, [%4];"
                    : "=r"(a[sp][mf][0]), "=r"(a[sp][mf][1]),
                      "=r"(a[sp][mf][2]), "=r"(a[sp][mf][3])
                    : "r"(addr));
            }

        #pragma unroll
        for (int np = 0; np < 5; np++) {
            int nbase = warpN * 80 + np * 16;
            unsigned bh[4], bl[4];
            {
                unsigned addr = sm_u32(
                    &Bs[buf][0][(lane & 15) * 168 + nbase + (lane >> 4) * 8]);
                asm volatile(
                    "ldmatrix.sync.aligned.m8n8.x4.trans.shared.b16 {%0,%1,%2,%3}, [%4];"
                    : "=r"(bh[0]), "=r"(bh[1]), "=r"(bh[2]), "=r"(bh[3])
                    : "r"(addr));
            }
            {
                unsigned addr = sm_u32(
                    &Bs[buf][1][(lane & 15) * 168 + nbase + (lane >> 4) * 8]);
                asm volatile(
                    "ldmatrix.sync.aligned.m8n8.x4.trans.shared.b16 {%0,%1,%2,%3}, [%4];"
                    : "=r"(bl[0]), "=r"(bl[1]), "=r"(bl[2]), "=r"(bl[3])
                    : "r"(addr));
            }
            #pragma unroll
            for (int mf = 0; mf < 2; mf++) {
                float* c0 = C[mf][2 * np];
                float* c1 = C[mf][2 * np + 1];
                asm volatile(
                    "mma.sync.aligned.m16n8k16.row.col.f32.bf16.bf16.f32 "
                    "{%0,%1,%2,%3},{%4,%5,%6,%7},{%8,%9},{%0,%1,%2,%3};"
                    : "+f"(c0[0]), "+f"(c0[1]), "+f"(c0[2]), "+f"(c0[3])
                    : "r"(a[0][mf][0]), "r"(a[0][mf][1]), "r"(a[0][mf][2]),
                      "r"(a[0][mf][3]), "r"(bh[0]), "r"(bh[1]));
                asm volatile(
                    "mma.sync.aligned.m16n8k16.row.col.f32.bf16.bf16.f32 "
                    "{%0,%1,%2,%3},{%4,%5,%6,%7},{%8,%9},{%0,%1,%2,%3};"
                    : "+f"(c1[0]), "+f"(c1[1]), "+f"(c1[2]), "+f"(c1[3])
                    : "r"(a[0][mf][0]), "r"(a[0][mf][1]), "r"(a[0][mf][2]),
                      "r"(a[0][mf][3]), "r"(bh[2]), "r"(bh[3]));
                asm volatile(
                    "mma.sync.aligned.m16n8k16.row.col.f32.bf16.bf16.f32 "
                    "{%0,%1,%2,%3},{%4,%5,%6,%7},{%8,%9},{%0,%1,%2,%3};"
                    : "+f"(c0[0]), "+f"(c0[1]), "+f"(c0[2]), "+f"(c0[3])
                    : "r"(a[1][mf][0]), "r"(a[1][mf][1]), "r"(a[1][mf][2]),
                      "r"(a[1][mf][3]), "r"(bh[0]), "r"(bh[1]));
                asm volatile(
                    "mma.sync.aligned.m16n8k16.row.col.f32.bf16.bf16.f32 "
                    "{%0,%1,%2,%3},{%4,%5,%6,%7},{%8,%9},{%0,%1,%2,%3};"
                    : "+f"(c1[0]), "+f"(c1[1]), "+f"(c1[2]), "+f"(c1[3])
                    : "r"(a[1][mf][0]), "r"(a[1][mf][1]), "r"(a[1][mf][2]),
                      "r"(a[1][mf][3]), "r"(bh[2]), "r"(bh[3]));
                asm volatile(
                    "mma.sync.aligned.m16n8k16.row.col.f32.bf16.bf16.f32 "
                    "{%0,%1,%2,%3},{%4,%5,%6,%7},{%8,%9},{%0,%1,%2,%3};"
                    : "+f"(c0[0]), "+f"(c0[1]), "+f"(c0[2]), "+f"(c0[3])
                    : "r"(a[0][mf][0]), "r"(a[0][mf][1]), "r"(a[0][mf][2]),
                      "r"(a[0][mf][3]), "r"(bl[0]), "r"(bl[1]));
                asm volatile(
                    "mma.sync.aligned.m16n8k16.row.col.f32.bf16.bf16.f32 "
                    "{%0,%1,%2,%3},{%4,%5,%6,%7},{%8,%9},{%0,%1,%2,%3};"
                    : "+f"(c1[0]), "+f"(c1[1]), "+f"(c1[2]), "+f"(c1[3])
                    : "r"(a[0][mf][0]), "r"(a[0][mf][1]), "r"(a[0][mf][2]),
                      "r"(a[0][mf][3]), "r"(bl[2]), "r"(bl[3]));
            }
        }
        __syncthreads();
    }

    int tq = lane & 3, g = lane >> 2;
    #pragma unroll
    for (int mf = 0; mf < 2; mf++) {
        float v0 = 0.f, v1 = 0.f;
        #pragma unroll
        for (int nf = 0; nf < 10; nf++) {
            int col = warpN * 80 + nf * 8 + tq * 2;
            float bb0 = __ldg(&b2p[col]), bb1 = __ldg(&b2p[col + 1]);
            float ww0 = __ldg(&w3p[col]), ww1 = __ldg(&w3p[col + 1]);
            float* c = C[mf][nf];
            v0 = fmaf(fmaxf(c[0] + bb0, 0.f), ww0, v0);
            v0 = fmaf(fmaxf(c[1] + bb1, 0.f), ww1, v0);
            v1 = fmaf(fmaxf(c[2] + bb0, 0.f), ww0, v1);
            v1 = fmaf(fmaxf(c[3] + bb1, 0.f), ww1, v1);
        }
        v0 += __shfl_xor_sync(0xffffffffu, v0, 1);
        v0 += __shfl_xor_sync(0xffffffffu, v0, 2);
        v1 += __shfl_xor_sync(0xffffffffu, v1, 1);
        v1 += __shfl_xor_sync(0xffffffffu, v1, 2);
        if (tq == 0) {
            red[warpM * 32 + mf * 16 + g][warpN] = v0;
            red[warpM * 32 + mf * 16 + g + 8][warpN] = v1;
        }
    }
    __syncthreads();
    if (tid < SCBM) {
        int m = m0 + tid;
        if (m < M) out[m] = red[tid][0] + red[tid][1] + b3[0];
    }
}

// ---------------------------------------------------------------------------
extern "C" void kernel_launch(void* const* d_in, const int* in_sizes, int n_in,
                              void* d_out, int out_size)
{
    const float* embeds = (const float*)d_in[0];
    const float* states = (const float*)d_in[1];
    const float* aW1 = (const float*)d_in[2];
    const float* ab1 = (const float*)d_in[3];
    const float* aW2 = (const float*)d_in[4];
    const float* ab2 = (const float*)d_in[5];
    const float* aW3 = (const float*)d_in[6];
    const float* ab3 = (const float*)d_in[7];
    const float* sW1 = (const float*)d_in[8];
    const float* sb1 = (const float*)d_in[9];
    const float* sW2 = (const float*)d_in[10];
    const float* sb2 = (const float*)d_in[11];
    const float* sW3 = (const float*)d_in[12];
    const float* sb3 = (const float*)d_in[13];
    float* out = (float*)d_out;

    float *tok, *Hb, *E, *attn, *b2p, *w3p;
    __nv_bfloat16 *H1h, *H1l, *W2s;
    cudaGetSymbolAddress((void**)&tok, g_tok);
    cudaGetSymbolAddress((void**)&Hb, g_Hb);
    cudaGetSymbolAddress((void**)&E, g_E);
    cudaGetSymbolAddress((void**)&attn, g_attn);
    cudaGetSymbolAddress((void**)&H1h, g_H1h);
    cudaGetSymbolAddress((void**)&H1l, g_H1l);
    cudaGetSymbolAddress((void**)&W2s, g_W2s);
    cudaGetSymbolAddress((void**)&b2p, g_b2p);
    cudaGetSymbolAddress((void**)&w3p, g_w3p);

    prep_kernel<<<(H1P * H1P + 255) / 256, 256>>>(sW2, sb2, sW3, W2s, b2p, w3p);

    int mt = (kT + MBM - 1) / MBM;  // 157

    // E = embeds @ sW1[800:1100]   (M=20000, N=150, K=300, lda=300 ok)
    mma_gemm<<<dim3(mt, 1), 256>>>(kT, kH, kE, embeds, kE,
                                   sW1 + (size_t)800 * kH, nullptr, nullptr,
                                   nullptr, nullptr, 0, E, kH);
    // fused token GEMM: [Ha | A | B]  (lda=400 ok, ldc=452 padded)
    mma_gemm<<<dim3(mt, 3), 256>>>(kT, TOKN, kS, states, kS,
                                   aW1, sW1, sW1 + (size_t)400 * kH,
                                   ab1, sb1, 1, tok, TOKW);
    // Hb = relu(Ha @ aW2 + ab2)   (lda=452 now 16B-aligned)
    mma_gemm<<<dim3(mt, 1), 256>>>(kT, kH, kH, tok, TOKW,
                                   aW2, nullptr, nullptr,
                                   ab2, nullptr, 1, Hb, kH);

    attn_out_kernel<<<(kT + 7) / 8, 256>>>(Hb, aW3, ab3, attn, kT);

    h1_kernel<<<dim3(592, 10), 160>>>(attn, tok, E, H1h, H1l);

    score_mma<<<(NSPANS + SCBM - 1) / SCBM, 256>>>(H1h, H1l, W2s, b2p, w3p,
                                                   sb3, out, NSPANS);
}

// round 8
// speedup vs baseline: 1.1215x; 1.1215x over previous
#include <cuda_runtime.h>
#include <cuda_bf16.h>

#define kT 20000
#define kE 300
#define kS 400
#define kH 150
#define NSPANS (10 * kT - 45)
#define TOKW 452    // padded row stride: cols 0:150 Ha, 150:300 A, 300:450 B
#define TOKN 450    // logical width
#define H1P 160     // padded h1 row

typedef unsigned long long ull;

// Scratch (allocation-free rule: __device__ globals)
__device__ float g_tok[(size_t)kT * TOKW];
__device__ float g_Hb[(size_t)kT * kH];
__device__ float g_E[(size_t)kT * kH];
__device__ float g_attn[kT];
__device__ __nv_bfloat16 g_H1h[(size_t)NSPANS * H1P];
__device__ __nv_bfloat16 g_H1l[(size_t)NSPANS * H1P];
__device__ __nv_bfloat16 g_W2s[2 * H1P * H1P];
__device__ float g_b2p[H1P];
__device__ float g_w3p[H1P];

static __device__ __forceinline__ unsigned sm_u32(const void* p) {
    return (unsigned)__cvta_generic_to_shared(p);
}
static __device__ __forceinline__ unsigned pack_bf2(__nv_bfloat16 a, __nv_bfloat16 b) {
    unsigned r;
    unsigned short ua = *(unsigned short*)&a, ub = *(unsigned short*)&b;
    asm("mov.b32 %0, {%1, %2};" : "=r"(r) : "h"(ua), "h"(ub));
    return r;
}

// 6 MMAs: 3-product split-bf16 into two n-frag accumulators
#define MMA6(c0, c1, A0, A1, BH, BL)                                          \
    asm volatile("mma.sync.aligned.m16n8k16.row.col.f32.bf16.bf16.f32 "       \
                 "{%0,%1,%2,%3},{%4,%5,%6,%7},{%8,%9},{%0,%1,%2,%3};"         \
                 : "+f"(c0[0]), "+f"(c0[1]), "+f"(c0[2]), "+f"(c0[3])         \
                 : "r"(A0[0]), "r"(A0[1]), "r"(A0[2]), "r"(A0[3]),            \
                   "r"(BH[0]), "r"(BH[1]));                                   \
    asm volatile("mma.sync.aligned.m16n8k16.row.col.f32.bf16.bf16.f32 "       \
                 "{%0,%1,%2,%3},{%4,%5,%6,%7},{%8,%9},{%0,%1,%2,%3};"         \
                 : "+f"(c1[0]), "+f"(c1[1]), "+f"(c1[2]), "+f"(c1[3])         \
                 : "r"(A0[0]), "r"(A0[1]), "r"(A0[2]), "r"(A0[3]),            \
                   "r"(BH[2]), "r"(BH[3]));                                   \
    asm volatile("mma.sync.aligned.m16n8k16.row.col.f32.bf16.bf16.f32 "       \
                 "{%0,%1,%2,%3},{%4,%5,%6,%7},{%8,%9},{%0,%1,%2,%3};"         \
                 : "+f"(c0[0]), "+f"(c0[1]), "+f"(c0[2]), "+f"(c0[3])         \
                 : "r"(A1[0]), "r"(A1[1]), "r"(A1[2]), "r"(A1[3]),            \
                   "r"(BH[0]), "r"(BH[1]));                                   \
    asm volatile("mma.sync.aligned.m16n8k16.row.col.f32.bf16.bf16.f32 "       \
                 "{%0,%1,%2,%3},{%4,%5,%6,%7},{%8,%9},{%0,%1,%2,%3};"         \
                 : "+f"(c1[0]), "+f"(c1[1]), "+f"(c1[2]), "+f"(c1[3])         \
                 : "r"(A1[0]), "r"(A1[1]), "r"(A1[2]), "r"(A1[3]),            \
                   "r"(BH[2]), "r"(BH[3]));                                   \
    asm volatile("mma.sync.aligned.m16n8k16.row.col.f32.bf16.bf16.f32 "       \
                 "{%0,%1,%2,%3},{%4,%5,%6,%7},{%8,%9},{%0,%1,%2,%3};"         \
                 : "+f"(c0[0]), "+f"(c0[1]), "+f"(c0[2]), "+f"(c0[3])         \
                 : "r"(A0[0]), "r"(A0[1]), "r"(A0[2]), "r"(A0[3]),            \
                   "r"(BL[0]), "r"(BL[1]));                                   \
    asm volatile("mma.sync.aligned.m16n8k16.row.col.f32.bf16.bf16.f32 "       \
                 "{%0,%1,%2,%3},{%4,%5,%6,%7},{%8,%9},{%0,%1,%2,%3};"         \
                 : "+f"(c1[0]), "+f"(c1[1]), "+f"(c1[2]), "+f"(c1[3])         \
                 : "r"(A0[0]), "r"(A0[1]), "r"(A0[2]), "r"(A0[3]),            \
                   "r"(BL[2]), "r"(BL[3]));

// ---------------------------------------------------------------------------
// Generic split-bf16 tensor-core GEMM, f32 in / f32 out.
// Block tile 64M x 160N, 8 warps (4M x 2N), double-buffered, 2 blocks/SM.
// Requires lda % 4 == 0.
// ---------------------------------------------------------------------------
#define MBM 64
#define MBN 160
#define MBK 16

__global__ __launch_bounds__(256, 2) void mma_gemm(
    int M, int N, int K,
    const float* __restrict__ A, int lda,
    const float* __restrict__ B0, const float* __restrict__ B1,
    const float* __restrict__ B2,
    const float* __restrict__ bias0, const float* __restrict__ bias1,
    int relu_mask,
    float* __restrict__ C, int ldc)
{
    __shared__ __align__(16) __nv_bfloat16 As[2][2][MBM * 24];
    __shared__ __align__(16) __nv_bfloat16 Bs[2][2][16 * 168];

    int tid = threadIdx.x;
    int m0 = blockIdx.x * MBM, n0 = blockIdx.y * MBN;
    int wid = tid >> 5, lane = tid & 31;
    int warpM = wid & 3, warpN = wid >> 2;

    float Cr[10][4] = {};
    int nsteps = (K + MBK - 1) / MBK;

    auto stage = [&](int ks, int buf) {
        int k0 = ks * MBK;
        // A: 64 rows x 4 quads of 4 k-values -> 256 chunks (1 per thread)
        {
            int r = tid >> 2, q = tid & 3;
            int kk = k0 + q * 4;
            int row = min(m0 + r, M - 1);
            float4 v;
            if (kk + 3 < K) {
                v = *(const float4*)&A[(size_t)row * lda + kk];
            } else {
                float* vp = (float*)&v;
                #pragma unroll
                for (int i = 0; i < 4; i++)
                    vp[i] = (kk + i < K) ? A[(size_t)row * lda + kk + i] : 0.f;
            }
            float* vp = (float*)&v;
            __nv_bfloat16 h[4], l[4];
            #pragma unroll
            for (int i = 0; i < 4; i++) {
                h[i] = __float2bfloat16_rn(vp[i]);
                l[i] = __float2bfloat16_rn(vp[i] - __bfloat162float(h[i]));
            }
            uint2 sh = {pack_bf2(h[0], h[1]), pack_bf2(h[2], h[3])};
            uint2 sl = {pack_bf2(l[0], l[1]), pack_bf2(l[2], l[3])};
            *(uint2*)&As[buf][0][r * 24 + q * 4] = sh;
            *(uint2*)&As[buf][1][r * 24 + q * 4] = sl;
        }
        // B: 16 k-rows x 80 col-pairs -> 1280 chunks
        #pragma unroll 5
        for (int c = tid; c < 1280; c += 256) {
            int row = c / 80, p = c % 80;
            int nloc = p * 2;
            int n = n0 + nloc;
            int kk = k0 + row;
            float v0 = 0.f, v1 = 0.f;
            if (kk < K && n < N) {
                int seg = n / 150, nn = n - seg * 150;
                const float* Bp = (seg == 0) ? B0 : ((seg == 1) ? B1 : B2);
                v0 = Bp[(size_t)kk * 150 + nn];
                if (n + 1 < N) v1 = Bp[(size_t)kk * 150 + nn + 1];
            }
            __nv_bfloat16 h0 = __float2bfloat16_rn(v0);
            __nv_bfloat16 h1 = __float2bfloat16_rn(v1);
            __nv_bfloat16 l0 = __float2bfloat16_rn(v0 - __bfloat162float(h0));
            __nv_bfloat16 l1 = __float2bfloat16_rn(v1 - __bfloat162float(h1));
            *(unsigned*)&Bs[buf][0][row * 168 + nloc] = pack_bf2(h0, h1);
            *(unsigned*)&Bs[buf][1][row * 168 + nloc] = pack_bf2(l0, l1);
        }
    };

    stage(0, 0);
    __syncthreads();

    for (int ks = 0; ks < nsteps; ks++) {
        int buf = ks & 1;
        if (ks + 1 < nsteps) stage(ks + 1, buf ^ 1);

        unsigned a[2][4];
        #pragma unroll
        for (int sp = 0; sp < 2; sp++) {
            unsigned addr = sm_u32(
                &As[buf][sp][(warpM * 16 + (lane & 15)) * 24 + (lane >> 4) * 8]);
            asm volatile(
                "ldmatrix.sync.aligned.m8n8.x4.shared.b16 {%0,%1,%2,%3}, [%4];"
                : "=r"(a[sp][0]), "=r"(a[sp][1]), "=r"(a[sp][2]), "=r"(a[sp][3])
                : "r"(addr));
        }

        #pragma unroll
        for (int np = 0; np < 5; np++) {
            int nbase = warpN * 80 + np * 16;
            unsigned bh[4], bl[4];
            {
                unsigned addr = sm_u32(
                    &Bs[buf][0][(lane & 15) * 168 + nbase + (lane >> 4) * 8]);
                asm volatile(
                    "ldmatrix.sync.aligned.m8n8.x4.trans.shared.b16 {%0,%1,%2,%3}, [%4];"
                    : "=r"(bh[0]), "=r"(bh[1]), "=r"(bh[2]), "=r"(bh[3])
                    : "r"(addr));
            }
            {
                unsigned addr = sm_u32(
                    &Bs[buf][1][(lane & 15) * 168 + nbase + (lane >> 4) * 8]);
                asm volatile(
                    "ldmatrix.sync.aligned.m8n8.x4.trans.shared.b16 {%0,%1,%2,%3}, [%4];"
                    : "=r"(bl[0]), "=r"(bl[1]), "=r"(bl[2]), "=r"(bl[3])
                    : "r"(addr));
            }
            float* c0 = Cr[2 * np];
            float* c1 = Cr[2 * np + 1];
            MMA6(c0, c1, a[0], a[1], bh, bl);
        }
        __syncthreads();
    }

    // epilogue
    int tq = lane & 3, g = lane >> 2;
    int mr0 = m0 + warpM * 16 + g;
    #pragma unroll
    for (int nf = 0; nf < 10; nf++) {
        int n = n0 + warpN * 80 + nf * 8 + tq * 2;
        if (n >= N) continue;
        int seg = n / 150;
        float* c = Cr[nf];
        float bb0 = 0.f, bb1 = 0.f;
        if (seg == 0 && bias0) { bb0 = bias0[n]; bb1 = bias0[n + 1]; }
        if (seg == 1 && bias1) { bb0 = bias1[n - 150]; bb1 = bias1[n - 149]; }
        bool rl = (relu_mask >> seg) & 1;
        float v0 = c[0] + bb0, v1 = c[1] + bb1;
        float v2 = c[2] + bb0, v3 = c[3] + bb1;
        if (rl) {
            v0 = fmaxf(v0, 0.f); v1 = fmaxf(v1, 0.f);
            v2 = fmaxf(v2, 0.f); v3 = fmaxf(v3, 0.f);
        }
        bool n1ok = (n + 1 < N);
        if (mr0 < M) {
            C[(size_t)mr0 * ldc + n] = v0;
            if (n1ok) C[(size_t)mr0 * ldc + n + 1] = v1;
        }
        if (mr0 + 8 < M) {
            C[(size_t)(mr0 + 8) * ldc + n] = v2;
            if (n1ok) C[(size_t)(mr0 + 8) * ldc + n + 1] = v3;
        }
    }
}

// ---------------------------------------------------------------------------
// Attention output layer (warp per token)
// ---------------------------------------------------------------------------
__global__ void attn_out_kernel(const float* __restrict__ Hb,
                                const float* __restrict__ W3,
                                const float* __restrict__ b3,
                                float* __restrict__ out, int M)
{
    int gwarp = (blockIdx.x * blockDim.x + threadIdx.x) >> 5;
    int lane = threadIdx.x & 31;
    if (gwarp >= M) return;
    float acc = 0.f;
    #pragma unroll
    for (int k = lane; k < kH; k += 32)
        acc = fmaf(Hb[(size_t)gwarp * kH + k], W3[k], acc);
    #pragma unroll
    for (int o = 16; o > 0; o >>= 1)
        acc += __shfl_down_sync(0xffffffffu, acc, o);
    if (lane == 0) out[gwarp] = acc + b3[0];
}

// ---------------------------------------------------------------------------
// Prep: split W2 into padded bf16 hi/lo [160][160], pad b2/W3.
// ---------------------------------------------------------------------------
__global__ void prep_kernel(const float* __restrict__ W2,
                            const float* __restrict__ b2,
                            const float* __restrict__ W3,
                            __nv_bfloat16* __restrict__ W2s,
                            float* __restrict__ b2p, float* __restrict__ w3p)
{
    int i = blockIdx.x * blockDim.x + threadIdx.x;
    if (i < H1P * H1P) {
        int r = i / H1P, c = i % H1P;
        float w = (r < kH && c < kH) ? W2[r * kH + c] : 0.f;
        __nv_bfloat16 hi = __float2bfloat16(w);
        __nv_bfloat16 lo = __float2bfloat16(w - __bfloat162float(hi));
        W2s[i] = hi;
        W2s[H1P * H1P + i] = lo;
    }
    if (i < H1P) {
        b2p[i] = (i < kH) ? b2[i] : 0.f;
        w3p[i] = (i < kH) ? W3[i] : 0.f;
    }
}

// ---------------------------------------------------------------------------
// h1 assembly: width-specialized, 8 spans per batch, writes split-bf16 H1.
// ---------------------------------------------------------------------------
#define CH 8

__global__ __launch_bounds__(160) void h1_kernel(
    const float* __restrict__ attn,
    const float* __restrict__ tok,
    const float* __restrict__ Em,
    __nv_bfloat16* __restrict__ H1h, __nv_bfloat16* __restrict__ H1l)
{
    int n = blockIdx.y + 1;
    int S = kT - n + 1;
    int chunk = (S + gridDim.x - 1) / gridDim.x;
    int sa = blockIdx.x * chunk;
    int sb = min(sa + chunk, S);
    int off = (n - 1) * (kT + 1) - (n * (n - 1)) / 2;

    int h = threadIdx.x;
    bool act = h < kH;

    __shared__ float Esm[17][160];
    __shared__ float sw[CH][10];

    for (int s0 = sa; s0 < sb; s0 += CH) {
        int nsp = min(CH, sb - s0);
        int rows = n + nsp - 1;

        if (act)
            for (int r = 0; r < rows; r++)
                Esm[r][h] = Em[(size_t)(s0 + r) * kH + h];

        if (h < nsp) {
            int s = s0 + h;
            float w[10];
            float mx = -1e30f;
            for (int j = 0; j < n; j++) {
                float v = attn[s + j];
                w[j] = v;
                mx = fmaxf(mx, v);
            }
            float sum = 0.f;
            for (int j = 0; j < n; j++) {
                float e = __expf(w[j] - mx);
                w[j] = e;
                sum += e;
            }
            float inv = 1.f / sum;
            for (int j = 0; j < n; j++) sw[h][j] = w[j] * inv;
        }
        __syncthreads();

        if (act) {
            for (int sp = 0; sp < nsp; sp++) {
                int s = s0 + sp;
                float v = tok[(size_t)s * TOKW + 150 + h]
                        + tok[(size_t)(s + n - 1) * TOKW + 300 + h];
                for (int j = 0; j < n; j++)
                    v = fmaf(sw[sp][j], Esm[sp + j][h], v);
                v = fmaxf(v, 0.f);
                __nv_bfloat16 hi = __float2bfloat16(v);
                __nv_bfloat16 lo = __float2bfloat16(v - __bfloat162float(hi));
                size_t idx = (size_t)(off + s0 + sp) * H1P + h;
                H1h[idx] = hi;
                H1l[idx] = lo;
            }
        } else {
            for (int sp = 0; sp < nsp; sp++) {
                size_t idx = (size_t)(off + s0 + sp) * H1P + h;
                H1h[idx] = __float2bfloat16(0.f);
                H1l[idx] = __float2bfloat16(0.f);
            }
        }
        __syncthreads();
    }
}

// ---------------------------------------------------------------------------
// Score GEMM on tensor cores: 64M x 160N tile, 2 blocks/SM, split-bf16
// 3-product, fused relu/W3 epilogue.
// ---------------------------------------------------------------------------
#define SCBM 64

__global__ __launch_bounds__(256, 2) void score_mma(
    const __nv_bfloat16* __restrict__ H1h, const __nv_bfloat16* __restrict__ H1l,
    const __nv_bfloat16* __restrict__ W2s,
    const float* __restrict__ b2p, const float* __restrict__ w3p,
    const float* __restrict__ b3,
    float* __restrict__ out, int M)
{
    __shared__ __align__(16) __nv_bfloat16 As[2][2][SCBM * 24];
    __shared__ __align__(16) __nv_bfloat16 Bs[2][2][16 * 168];
    __shared__ float red[SCBM][2];

    int tid = threadIdx.x;
    int m0 = blockIdx.x * SCBM;
    int wid = tid >> 5, lane = tid & 31;
    int warpM = wid & 3, warpN = wid >> 2;

    float C[10][4] = {};

    auto stage = [&](int ks, int buf) {
        int k0 = ks * 16;
        // A: 2 splits x 64 rows x 2 halves = 256 chunks (1 per thread)
        {
            int sp = tid >> 7, tt = tid & 127, r = tt >> 1, half = tt & 1;
            int mrow = min(m0 + r, M - 1);
            const __nv_bfloat16* src =
                (sp ? H1l : H1h) + (size_t)mrow * H1P + k0 + half * 8;
            *(int4*)&As[buf][sp][r * 24 + half * 8] = *(const int4*)src;
        }
        for (int c = tid; c < 640; c += 256) {
            int sp = c / 320, cc = c % 320, row = cc / 20, offc = cc % 20;
            const __nv_bfloat16* src =
                W2s + (size_t)sp * H1P * H1P + (size_t)(k0 + row) * H1P + offc * 8;
            *(int4*)&Bs[buf][sp][row * 168 + offc * 8] = *(const int4*)src;
        }
    };

    stage(0, 0);
    __syncthreads();

    for (int ks = 0; ks < 10; ks++) {
        int buf = ks & 1;
        if (ks < 9) stage(ks + 1, buf ^ 1);

        unsigned a[2][4];
        #pragma unroll
        for (int sp = 0; sp < 2; sp++) {
            unsigned addr = sm_u32(
                &As[buf][sp][(warpM * 16 + (lane & 15)) * 24 + (lane >> 4) * 8]);
            asm volatile(
                "ldmatrix.sync.aligned.m8n8.x4.shared.b16 {%0,%1,%2,%3}, [%4];"
                : "=r"(a[sp][0]), "=r"(a[sp][1]), "=r"(a[sp][2]), "=r"(a[sp][3])
                : "r"(addr));
        }

        #pragma unroll
        for (int np = 0; np < 5; np++) {
            int nbase = warpN * 80 + np * 16;
            unsigned bh[4], bl[4];
            {
                unsigned addr = sm_u32(
                    &Bs[buf][0][(lane & 15) * 168 + nbase + (lane >> 4) * 8]);
                asm volatile(
                    "ldmatrix.sync.aligned.m8n8.x4.trans.shared.b16 {%0,%1,%2,%3}, [%4];"
                    : "=r"(bh[0]), "=r"(bh[1]), "=r"(bh[2]), "=r"(bh[3])
                    : "r"(addr));
            }
            {
                unsigned addr = sm_u32(
                    &Bs[buf][1][(lane & 15) * 168 + nbase + (lane >> 4) * 8]);
                asm volatile(
                    "ldmatrix.sync.aligned.m8n8.x4.trans.shared.b16 {%0,%1,%2,%3}, [%4];"
                    : "=r"(bl[0]), "=r"(bl[1]), "=r"(bl[2]), "=r"(bl[3])
                    : "r"(addr));
            }
            float* c0 = C[2 * np];
            float* c1 = C[2 * np + 1];
            MMA6(c0, c1, a[0], a[1], bh, bl);
        }
        __syncthreads();
    }

    // fused epilogue: sum_h relu(C + b2)*W3
    int tq = lane & 3, g = lane >> 2;
    float v0 = 0.f, v1 = 0.f;
    #pragma unroll
    for (int nf = 0; nf < 10; nf++) {
        int col = warpN * 80 + nf * 8 + tq * 2;
        float bb0 = __ldg(&b2p[col]), bb1 = __ldg(&b2p[col + 1]);
        float ww0 = __ldg(&w3p[col]), ww1 = __ldg(&w3p[col + 1]);
        float* c = C[nf];
        v0 = fmaf(fmaxf(c[0] + bb0, 0.f), ww0, v0);
        v0 = fmaf(fmaxf(c[1] + bb1, 0.f), ww1, v0);
        v1 = fmaf(fmaxf(c[2] + bb0, 0.f), ww0, v1);
        v1 = fmaf(fmaxf(c[3] + bb1, 0.f), ww1, v1);
    }
    v0 += __shfl_xor_sync(0xffffffffu, v0, 1);
    v0 += __shfl_xor_sync(0xffffffffu, v0, 2);
    v1 += __shfl_xor_sync(0xffffffffu, v1, 1);
    v1 += __shfl_xor_sync(0xffffffffu, v1, 2);
    if (tq == 0) {
        if (warpN == 0) {
            red[warpM * 16 + g][0] = v0;
            red[warpM * 16 + g + 8][0] = v1;
        } else {
            red[warpM * 16 + g][1] = v0;
            red[warpM * 16 + g + 8][1] = v1;
        }
    }
    __syncthreads();
    if (tid < SCBM) {
        int m = m0 + tid;
        if (m < M) out[m] = red[tid][0] + red[tid][1] + b3[0];
    }
}

// ---------------------------------------------------------------------------
extern "C" void kernel_launch(void* const* d_in, const int* in_sizes, int n_in,
                              void* d_out, int out_size)
{
    const float* embeds = (const float*)d_in[0];
    const float* states = (const float*)d_in[1];
    const float* aW1 = (const float*)d_in[2];
    const float* ab1 = (const float*)d_in[3];
    const float* aW2 = (const float*)d_in[4];
    const float* ab2 = (const float*)d_in[5];
    const float* aW3 = (const float*)d_in[6];
    const float* ab3 = (const float*)d_in[7];
    const float* sW1 = (const float*)d_in[8];
    const float* sb1 = (const float*)d_in[9];
    const float* sW2 = (const float*)d_in[10];
    const float* sb2 = (const float*)d_in[11];
    const float* sW3 = (const float*)d_in[12];
    const float* sb3 = (const float*)d_in[13];
    float* out = (float*)d_out;

    float *tok, *Hb, *E, *attn, *b2p, *w3p;
    __nv_bfloat16 *H1h, *H1l, *W2s;
    cudaGetSymbolAddress((void**)&tok, g_tok);
    cudaGetSymbolAddress((void**)&Hb, g_Hb);
    cudaGetSymbolAddress((void**)&E, g_E);
    cudaGetSymbolAddress((void**)&attn, g_attn);
    cudaGetSymbolAddress((void**)&H1h, g_H1h);
    cudaGetSymbolAddress((void**)&H1l, g_H1l);
    cudaGetSymbolAddress((void**)&W2s, g_W2s);
    cudaGetSymbolAddress((void**)&b2p, g_b2p);
    cudaGetSymbolAddress((void**)&w3p, g_w3p);

    prep_kernel<<<(H1P * H1P + 255) / 256, 256>>>(sW2, sb2, sW3, W2s, b2p, w3p);

    int mt = (kT + MBM - 1) / MBM;  // 313

    // E = embeds @ sW1[800:1100]
    mma_gemm<<<dim3(mt, 1), 256>>>(kT, kH, kE, embeds, kE,
                                   sW1 + (size_t)800 * kH, nullptr, nullptr,
                                   nullptr, nullptr, 0, E, kH);
    // fused token GEMM: [Ha | A | B]
    mma_gemm<<<dim3(mt, 3), 256>>>(kT, TOKN, kS, states, kS,
                                   aW1, sW1, sW1 + (size_t)400 * kH,
                                   ab1, sb1, 1, tok, TOKW);
    // Hb = relu(Ha @ aW2 + ab2)
    mma_gemm<<<dim3(mt, 1), 256>>>(kT, kH, kH, tok, TOKW,
                                   aW2, nullptr, nullptr,
                                   ab2, nullptr, 1, Hb, kH);

    attn_out_kernel<<<(kT + 7) / 8, 256>>>(Hb, aW3, ab3, attn, kT);

    h1_kernel<<<dim3(592, 10), 160>>>(attn, tok, E, H1h, H1l);

    score_mma<<<(NSPANS + SCBM - 1) / SCBM, 256>>>(H1h, H1l, W2s, b2p, w3p,
                                                   sb3, out, NSPANS);
}

// round 9
// speedup vs baseline: 1.9578x; 1.7457x over previous
#include <cuda_runtime.h>
#include <cuda_bf16.h>

#define kT 20000
#define kE 300
#define kS 400
#define kH 150
#define NSPANS (10 * kT - 45)
#define TOKW 452    // padded f32 row: cols 0:150 unused(Ha), 150:300 A, 300:450 B
#define H1P 160

typedef unsigned long long ull;

// Scratch (allocation-free rule: __device__ globals; zero-initialized)
__device__ float g_tok[(size_t)kT * TOKW];
__device__ float g_Hb[(size_t)kT * kH];
__device__ float g_E[(size_t)kT * kH];
__device__ float g_attn[kT];
__device__ __nv_bfloat16 g_Ss[2 * (size_t)kT * kS];        // split states
__device__ __nv_bfloat16 g_Es[2 * (size_t)kT * 304];       // split embeds (pad 304)
__device__ __nv_bfloat16 g_Has[(size_t)kT * H1P];          // Ha hi
__device__ __nv_bfloat16 g_Hal[(size_t)kT * H1P];          // Ha lo
__device__ __nv_bfloat16 g_Wtok[2 * 400 * 480];            // [aW1|sW1A|sW1B] padded
__device__ __nv_bfloat16 g_WE[2 * 304 * 160];
__device__ __nv_bfloat16 g_Wa2[2 * 160 * 160];
__device__ __nv_bfloat16 g_W2s[2 * 160 * 160];
__device__ __nv_bfloat16 g_H1h[(size_t)NSPANS * H1P];
__device__ __nv_bfloat16 g_H1l[(size_t)NSPANS * H1P];
__device__ float g_b2p[H1P];
__device__ float g_w3p[H1P];

static __device__ __forceinline__ unsigned sm_u32(const void* p) {
    return (unsigned)__cvta_generic_to_shared(p);
}
static __device__ __forceinline__ unsigned pack_bf2(__nv_bfloat16 a, __nv_bfloat16 b) {
    unsigned r;
    unsigned short ua = *(unsigned short*)&a, ub = *(unsigned short*)&b;
    asm("mov.b32 %0, {%1, %2};" : "=r"(r) : "h"(ua), "h"(ub));
    return r;
}

#define MMA6(c0, c1, A0, A1, BH, BL)                                          \
    asm volatile("mma.sync.aligned.m16n8k16.row.col.f32.bf16.bf16.f32 "       \
                 "{%0,%1,%2,%3},{%4,%5,%6,%7},{%8,%9},{%0,%1,%2,%3};"         \
                 : "+f"(c0[0]), "+f"(c0[1]), "+f"(c0[2]), "+f"(c0[3])         \
                 : "r"(A0[0]), "r"(A0[1]), "r"(A0[2]), "r"(A0[3]),            \
                   "r"(BH[0]), "r"(BH[1]));                                   \
    asm volatile("mma.sync.aligned.m16n8k16.row.col.f32.bf16.bf16.f32 "       \
                 "{%0,%1,%2,%3},{%4,%5,%6,%7},{%8,%9},{%0,%1,%2,%3};"         \
                 : "+f"(c1[0]), "+f"(c1[1]), "+f"(c1[2]), "+f"(c1[3])         \
                 : "r"(A0[0]), "r"(A0[1]), "r"(A0[2]), "r"(A0[3]),            \
                   "r"(BH[2]), "r"(BH[3]));                                   \
    asm volatile("mma.sync.aligned.m16n8k16.row.col.f32.bf16.bf16.f32 "       \
                 "{%0,%1,%2,%3},{%4,%5,%6,%7},{%8,%9},{%0,%1,%2,%3};"         \
                 : "+f"(c0[0]), "+f"(c0[1]), "+f"(c0[2]), "+f"(c0[3])         \
                 : "r"(A1[0]), "r"(A1[1]), "r"(A1[2]), "r"(A1[3]),            \
                   "r"(BH[0]), "r"(BH[1]));                                   \
    asm volatile("mma.sync.aligned.m16n8k16.row.col.f32.bf16.bf16.f32 "       \
                 "{%0,%1,%2,%3},{%4,%5,%6,%7},{%8,%9},{%0,%1,%2,%3};"         \
                 : "+f"(c1[0]), "+f"(c1[1]), "+f"(c1[2]), "+f"(c1[3])         \
                 : "r"(A1[0]), "r"(A1[1]), "r"(A1[2]), "r"(A1[3]),            \
                   "r"(BH[2]), "r"(BH[3]));                                   \
    asm volatile("mma.sync.aligned.m16n8k16.row.col.f32.bf16.bf16.f32 "       \
                 "{%0,%1,%2,%3},{%4,%5,%6,%7},{%8,%9},{%0,%1,%2,%3};"         \
                 : "+f"(c0[0]), "+f"(c0[1]), "+f"(c0[2]), "+f"(c0[3])         \
                 : "r"(A0[0]), "r"(A0[1]), "r"(A0[2]), "r"(A0[3]),            \
                   "r"(BL[0]), "r"(BL[1]));                                   \
    asm volatile("mma.sync.aligned.m16n8k16.row.col.f32.bf16.bf16.f32 "       \
                 "{%0,%1,%2,%3},{%4,%5,%6,%7},{%8,%9},{%0,%1,%2,%3};"         \
                 : "+f"(c1[0]), "+f"(c1[1]), "+f"(c1[2]), "+f"(c1[3])         \
                 : "r"(A0[0]), "r"(A0[1]), "r"(A0[2]), "r"(A0[3]),            \
                   "r"(BL[2]), "r"(BL[3]));

// ---------------------------------------------------------------------------
// Prep: pad+split a [K x 150] f32 weight into [Kpad x 160] bf16 hi/lo planes.
// ---------------------------------------------------------------------------
__global__ void pad_split_w(const float* __restrict__ src, int K, int Kpad,
                            int ldd, __nv_bfloat16* __restrict__ dh,
                            __nv_bfloat16* __restrict__ dl)
{
    int i = blockIdx.x * blockDim.x + threadIdx.x;
    if (i >= Kpad * 160) return;
    int k = i / 160, c = i - k * 160;
    float w = (k < K && c < 150) ? src[k * 150 + c] : 0.f;
    __nv_bfloat16 hi = __float2bfloat16_rn(w);
    __nv_bfloat16 lo = __float2bfloat16_rn(w - __bfloat162float(hi));
    dh[(size_t)k * ldd + c] = hi;
    dl[(size_t)k * ldd + c] = lo;
}

__global__ void pad_vec(const float* __restrict__ b2, const float* __restrict__ W3,
                        float* __restrict__ b2p, float* __restrict__ w3p)
{
    int i = threadIdx.x;
    if (i < H1P) {
        b2p[i] = (i < kH) ? b2[i] : 0.f;
        w3p[i] = (i < kH) ? W3[i] : 0.f;
    }
}

// ---------------------------------------------------------------------------
// Split activation matrix f32 [M x K] -> bf16 hi/lo [M x ldd] (4 elems/thread)
// ---------------------------------------------------------------------------
__global__ void conv_split(const float* __restrict__ src, int M, int K, int ldd,
                           __nv_bfloat16* __restrict__ dh,
                           __nv_bfloat16* __restrict__ dl)
{
    int i = blockIdx.x * blockDim.x + threadIdx.x;
    int q4 = K >> 2;
    if (i >= M * q4) return;
    int row = i / q4, q = i - row * q4;
    float4 v = *(const float4*)&src[(size_t)row * K + q * 4];
    float* vp = (float*)&v;
    __nv_bfloat16 h[4], l[4];
    #pragma unroll
    for (int j = 0; j < 4; j++) {
        h[j] = __float2bfloat16_rn(vp[j]);
        l[j] = __float2bfloat16_rn(vp[j] - __bfloat162float(h[j]));
    }
    uint2 sh = {pack_bf2(h[0], h[1]), pack_bf2(h[2], h[3])};
    uint2 sl = {pack_bf2(l[0], l[1]), pack_bf2(l[2], l[3])};
    *(uint2*)&dh[(size_t)row * ldd + q * 4] = sh;
    *(uint2*)&dl[(size_t)row * ldd + q * 4] = sl;
}

// ---------------------------------------------------------------------------
// Split-bf16 tensor-core GEMM, pre-converted operands (copy-only staging).
// 64M x 160N tile, 8 warps (4Mx2N), double-buffered, 2 blocks/SM.
// B: pre-padded [Kpad x ldb] hi/lo planes; segment = blockIdx.y (n0=seg*160).
// Output: f32 C at col seg*150+nloc (nloc<150), OR (seg==0 && Csh) split bf16.
// ---------------------------------------------------------------------------
#define MBM 64

__global__ __launch_bounds__(256, 2) void mma_gemm_pre(
    int M, int nsteps,
    const __nv_bfloat16* __restrict__ Ah, const __nv_bfloat16* __restrict__ Al,
    int lda,
    const __nv_bfloat16* __restrict__ Bh, const __nv_bfloat16* __restrict__ Bl,
    int ldb,
    const float* __restrict__ bias0, const float* __restrict__ bias1,
    int relu_mask,
    float* __restrict__ C, int ldc,
    __nv_bfloat16* __restrict__ Csh, __nv_bfloat16* __restrict__ Csl)
{
    __shared__ __align__(16) __nv_bfloat16 As[2][2][MBM * 24];
    __shared__ __align__(16) __nv_bfloat16 Bs[2][2][16 * 168];

    int tid = threadIdx.x;
    int m0 = blockIdx.x * MBM;
    int seg = blockIdx.y;
    int n0 = seg * 160;
    int wid = tid >> 5, lane = tid & 31;
    int warpM = wid & 3, warpN = wid >> 2;

    float Cr[10][4] = {};

    auto stage = [&](int ks, int buf) {
        int k0 = ks * 16;
        {
            int sp = tid >> 7, tt = tid & 127, r = tt >> 1, half = tt & 1;
            int row = min(m0 + r, M - 1);
            const __nv_bfloat16* src =
                (sp ? Al : Ah) + (size_t)row * lda + k0 + half * 8;
            *(int4*)&As[buf][sp][r * 24 + half * 8] = *(const int4*)src;
        }
        #pragma unroll 3
        for (int c = tid; c < 640; c += 256) {
            int sp = c / 320, cc = c % 320, row = cc / 20, offc = cc % 20;
            const __nv_bfloat16* src =
                (sp ? Bl : Bh) + (size_t)(k0 + row) * ldb + n0 + offc * 8;
            *(int4*)&Bs[buf][sp][row * 168 + offc * 8] = *(const int4*)src;
        }
    };

    stage(0, 0);
    __syncthreads();

    for (int ks = 0; ks < nsteps; ks++) {
        int buf = ks & 1;
        if (ks + 1 < nsteps) stage(ks + 1, buf ^ 1);

        unsigned a[2][4];
        #pragma unroll
        for (int sp = 0; sp < 2; sp++) {
            unsigned addr = sm_u32(
                &As[buf][sp][(warpM * 16 + (lane & 15)) * 24 + (lane >> 4) * 8]);
            asm volatile(
                "ldmatrix.sync.aligned.m8n8.x4.shared.b16 {%0,%1,%2,%3}, [%4];"
                : "=r"(a[sp][0]), "=r"(a[sp][1]), "=r"(a[sp][2]), "=r"(a[sp][3])
                : "r"(addr));
        }

        #pragma unroll
        for (int np = 0; np < 5; np++) {
            int nbase = warpN * 80 + np * 16;
            unsigned bh[4], bl[4];
            {
                unsigned addr = sm_u32(
                    &Bs[buf][0][(lane & 15) * 168 + nbase + (lane >> 4) * 8]);
                asm volatile(
                    "ldmatrix.sync.aligned.m8n8.x4.trans.shared.b16 {%0,%1,%2,%3}, [%4];"
                    : "=r"(bh[0]), "=r"(bh[1]), "=r"(bh[2]), "=r"(bh[3])
                    : "r"(addr));
            }
            {
                unsigned addr = sm_u32(
                    &Bs[buf][1][(lane & 15) * 168 + nbase + (lane >> 4) * 8]);
                asm volatile(
                    "ldmatrix.sync.aligned.m8n8.x4.trans.shared.b16 {%0,%1,%2,%3}, [%4];"
                    : "=r"(bl[0]), "=r"(bl[1]), "=r"(bl[2]), "=r"(bl[3])
                    : "r"(addr));
            }
            float* c0 = Cr[2 * np];
            float* c1 = Cr[2 * np + 1];
            MMA6(c0, c1, a[0], a[1], bh, bl);
        }
        __syncthreads();
    }

    // epilogue
    int tq = lane & 3, g = lane >> 2;
    int mr0 = m0 + warpM * 16 + g;
    bool rl = (relu_mask >> seg) & 1;
    const float* bias = (seg == 0) ? bias0 : ((seg == 1) ? bias1 : nullptr);
    bool splitOut = (seg == 0) && (Csh != nullptr);
    #pragma unroll
    for (int nf = 0; nf < 10; nf++) {
        int nloc = warpN * 80 + nf * 8 + tq * 2;
        float* c = Cr[nf];
        if (nloc >= 150) {
            if (splitOut) {  // zero the bf16 pad cols 150..159
                __nv_bfloat16 z = __float2bfloat16(0.f);
                if (mr0 < M) {
                    Csh[(size_t)mr0 * H1P + nloc] = z;  Csl[(size_t)mr0 * H1P + nloc] = z;
                    Csh[(size_t)mr0 * H1P + nloc + 1] = z; Csl[(size_t)mr0 * H1P + nloc + 1] = z;
                }
                if (mr0 + 8 < M) {
                    Csh[(size_t)(mr0 + 8) * H1P + nloc] = z;  Csl[(size_t)(mr0 + 8) * H1P + nloc] = z;
                    Csh[(size_t)(mr0 + 8) * H1P + nloc + 1] = z; Csl[(size_t)(mr0 + 8) * H1P + nloc + 1] = z;
                }
            }
            continue;
        }
        float bb0 = 0.f, bb1 = 0.f;
        if (bias) { bb0 = bias[nloc]; bb1 = bias[nloc + 1]; }
        float v0 = c[0] + bb0, v1 = c[1] + bb1;
        float v2 = c[2] + bb0, v3 = c[3] + bb1;
        if (rl) {
            v0 = fmaxf(v0, 0.f); v1 = fmaxf(v1, 0.f);
            v2 = fmaxf(v2, 0.f); v3 = fmaxf(v3, 0.f);
        }
        if (splitOut) {
            float vv[4] = {v0, v1, v2, v3};
            #pragma unroll
            for (int q = 0; q < 4; q++) {
                int m = (q < 2) ? mr0 : mr0 + 8;
                if (m >= M) continue;
                int n = nloc + (q & 1);
                __nv_bfloat16 hi = __float2bfloat16_rn(vv[q]);
                __nv_bfloat16 lo = __float2bfloat16_rn(vv[q] - __bfloat162float(hi));
                Csh[(size_t)m * H1P + n] = hi;
                Csl[(size_t)m * H1P + n] = lo;
            }
        } else {
            int n = seg * 150 + nloc;
            if (mr0 < M) {
                C[(size_t)mr0 * ldc + n] = v0;
                C[(size_t)mr0 * ldc + n + 1] = v1;
            }
            if (mr0 + 8 < M) {
                C[(size_t)(mr0 + 8) * ldc + n] = v2;
                C[(size_t)(mr0 + 8) * ldc + n + 1] = v3;
            }
        }
    }
}

// ---------------------------------------------------------------------------
// Attention output layer (warp per token)
// ---------------------------------------------------------------------------
__global__ void attn_out_kernel(const float* __restrict__ Hb,
                                const float* __restrict__ W3,
                                const float* __restrict__ b3,
                                float* __restrict__ out, int M)
{
    int gwarp = (blockIdx.x * blockDim.x + threadIdx.x) >> 5;
    int lane = threadIdx.x & 31;
    if (gwarp >= M) return;
    float acc = 0.f;
    #pragma unroll
    for (int k = lane; k < kH; k += 32)
        acc = fmaf(Hb[(size_t)gwarp * kH + k], W3[k], acc);
    #pragma unroll
    for (int o = 16; o > 0; o >>= 1)
        acc += __shfl_down_sync(0xffffffffu, acc, o);
    if (lane == 0) out[gwarp] = acc + b3[0];
}

// ---------------------------------------------------------------------------
// h1 assembly: width-specialized, 8 spans per batch, writes split-bf16 H1.
// ---------------------------------------------------------------------------
#define CH 8

__global__ __launch_bounds__(160) void h1_kernel(
    const float* __restrict__ attn,
    const float* __restrict__ tok,
    const float* __restrict__ Em,
    __nv_bfloat16* __restrict__ H1h, __nv_bfloat16* __restrict__ H1l)
{
    int n = blockIdx.y + 1;
    int S = kT - n + 1;
    int chunk = (S + gridDim.x - 1) / gridDim.x;
    int sa = blockIdx.x * chunk;
    int sb = min(sa + chunk, S);
    int off = (n - 1) * (kT + 1) - (n * (n - 1)) / 2;

    int h = threadIdx.x;
    bool act = h < kH;

    __shared__ float Esm[17][160];
    __shared__ float sw[CH][10];

    for (int s0 = sa; s0 < sb; s0 += CH) {
        int nsp = min(CH, sb - s0);
        int rows = n + nsp - 1;

        if (act)
            for (int r = 0; r < rows; r++)
                Esm[r][h] = Em[(size_t)(s0 + r) * kH + h];

        if (h < nsp) {
            int s = s0 + h;
            float w[10];
            float mx = -1e30f;
            for (int j = 0; j < n; j++) {
                float v = attn[s + j];
                w[j] = v;
                mx = fmaxf(mx, v);
            }
            float sum = 0.f;
            for (int j = 0; j < n; j++) {
                float e = __expf(w[j] - mx);
                w[j] = e;
                sum += e;
            }
            float inv = 1.f / sum;
            for (int j = 0; j < n; j++) sw[h][j] = w[j] * inv;
        }
        __syncthreads();

        if (act) {
            for (int sp = 0; sp < nsp; sp++) {
                int s = s0 + sp;
                float v = tok[(size_t)s * TOKW + 150 + h]
                        + tok[(size_t)(s + n - 1) * TOKW + 300 + h];
                for (int j = 0; j < n; j++)
                    v = fmaf(sw[sp][j], Esm[sp + j][h], v);
                v = fmaxf(v, 0.f);
                __nv_bfloat16 hi = __float2bfloat16(v);
                __nv_bfloat16 lo = __float2bfloat16(v - __bfloat162float(hi));
                size_t idx = (size_t)(off + s0 + sp) * H1P + h;
                H1h[idx] = hi;
                H1l[idx] = lo;
            }
        } else {
            for (int sp = 0; sp < nsp; sp++) {
                size_t idx = (size_t)(off + s0 + sp) * H1P + h;
                H1h[idx] = __float2bfloat16(0.f);
                H1l[idx] = __float2bfloat16(0.f);
            }
        }
        __syncthreads();
    }
}

// ---------------------------------------------------------------------------
// Score GEMM on tensor cores: 64M x 160N tile, 2 blocks/SM, split-bf16
// 3-product, fused relu/W3 epilogue.
// ---------------------------------------------------------------------------
#define SCBM 64

__global__ __launch_bounds__(256, 2) void score_mma(
    const __nv_bfloat16* __restrict__ H1h, const __nv_bfloat16* __restrict__ H1l,
    const __nv_bfloat16* __restrict__ W2s,
    const float* __restrict__ b2p, const float* __restrict__ w3p,
    const float* __restrict__ b3,
    float* __restrict__ out, int M)
{
    __shared__ __align__(16) __nv_bfloat16 As[2][2][SCBM * 24];
    __shared__ __align__(16) __nv_bfloat16 Bs[2][2][16 * 168];
    __shared__ float red[SCBM][2];

    int tid = threadIdx.x;
    int m0 = blockIdx.x * SCBM;
    int wid = tid >> 5, lane = tid & 31;
    int warpM = wid & 3, warpN = wid >> 2;

    float C[10][4] = {};

    auto stage = [&](int ks, int buf) {
        int k0 = ks * 16;
        {
            int sp = tid >> 7, tt = tid & 127, r = tt >> 1, half = tt & 1;
            int mrow = min(m0 + r, M - 1);
            const __nv_bfloat16* src =
                (sp ? H1l : H1h) + (size_t)mrow * H1P + k0 + half * 8;
            *(int4*)&As[buf][sp][r * 24 + half * 8] = *(const int4*)src;
        }
        for (int c = tid; c < 640; c += 256) {
            int sp = c / 320, cc = c % 320, row = cc / 20, offc = cc % 20;
            const __nv_bfloat16* src =
                W2s + (size_t)sp * H1P * H1P + (size_t)(k0 + row) * H1P + offc * 8;
            *(int4*)&Bs[buf][sp][row * 168 + offc * 8] = *(const int4*)src;
        }
    };

    stage(0, 0);
    __syncthreads();

    for (int ks = 0; ks < 10; ks++) {
        int buf = ks & 1;
        if (ks < 9) stage(ks + 1, buf ^ 1);

        unsigned a[2][4];
        #pragma unroll
        for (int sp = 0; sp < 2; sp++) {
            unsigned addr = sm_u32(
                &As[buf][sp][(warpM * 16 + (lane & 15)) * 24 + (lane >> 4) * 8]);
            asm volatile(
                "ldmatrix.sync.aligned.m8n8.x4.shared.b16 {%0,%1,%2,%3}, [%4];"
                : "=r"(a[sp][0]), "=r"(a[sp][1]), "=r"(a[sp][2]), "=r"(a[sp][3])
                : "r"(addr));
        }

        #pragma unroll
        for (int np = 0; np < 5; np++) {
            int nbase = warpN * 80 + np * 16;
            unsigned bh[4], bl[4];
            {
                unsigned addr = sm_u32(
                    &Bs[buf][0][(lane & 15) * 168 + nbase + (lane >> 4) * 8]);
                asm volatile(
                    "ldmatrix.sync.aligned.m8n8.x4.trans.shared.b16 {%0,%1,%2,%3}, [%4];"
                    : "=r"(bh[0]), "=r"(bh[1]), "=r"(bh[2]), "=r"(bh[3])
                    : "r"(addr));
            }
            {
                unsigned addr = sm_u32(
                    &Bs[buf][1][(lane & 15) * 168 + nbase + (lane >> 4) * 8]);
                asm volatile(
                    "ldmatrix.sync.aligned.m8n8.x4.trans.shared.b16 {%0,%1,%2,%3}, [%4];"
                    : "=r"(bl[0]), "=r"(bl[1]), "=r"(bl[2]), "=r"(bl[3])
                    : "r"(addr));
            }
            float* c0 = C[2 * np];
            float* c1 = C[2 * np + 1];
            MMA6(c0, c1, a[0], a[1], bh, bl);
        }
        __syncthreads();
    }

    int tq = lane & 3, g = lane >> 2;
    float v0 = 0.f, v1 = 0.f;
    #pragma unroll
    for (int nf = 0; nf < 10; nf++) {
        int col = warpN * 80 + nf * 8 + tq * 2;
        float bb0 = __ldg(&b2p[col]), bb1 = __ldg(&b2p[col + 1]);
        float ww0 = __ldg(&w3p[col]), ww1 = __ldg(&w3p[col + 1]);
        float* c = C[nf];
        v0 = fmaf(fmaxf(c[0] + bb0, 0.f), ww0, v0);
        v0 = fmaf(fmaxf(c[1] + bb1, 0.f), ww1, v0);
        v1 = fmaf(fmaxf(c[2] + bb0, 0.f), ww0, v1);
        v1 = fmaf(fmaxf(c[3] + bb1, 0.f), ww1, v1);
    }
    v0 += __shfl_xor_sync(0xffffffffu, v0, 1);
    v0 += __shfl_xor_sync(0xffffffffu, v0, 2);
    v1 += __shfl_xor_sync(0xffffffffu, v1, 1);
    v1 += __shfl_xor_sync(0xffffffffu, v1, 2);
    if (tq == 0) {
        red[warpM * 16 + g][warpN] = v0;
        red[warpM * 16 + g + 8][warpN] = v1;
    }
    __syncthreads();
    if (tid < SCBM) {
        int m = m0 + tid;
        if (m < M) out[m] = red[tid][0] + red[tid][1] + b3[0];
    }
}

// ---------------------------------------------------------------------------
extern "C" void kernel_launch(void* const* d_in, const int* in_sizes, int n_in,
                              void* d_out, int out_size)
{
    const float* embeds = (const float*)d_in[0];
    const float* states = (const float*)d_in[1];
    const float* aW1 = (const float*)d_in[2];
    const float* ab1 = (const float*)d_in[3];
    const float* aW2 = (const float*)d_in[4];
    const float* ab2 = (const float*)d_in[5];
    const float* aW3 = (const float*)d_in[6];
    const float* ab3 = (const float*)d_in[7];
    const float* sW1 = (const float*)d_in[8];
    const float* sb1 = (const float*)d_in[9];
    const float* sW2 = (const float*)d_in[10];
    const float* sb2 = (const float*)d_in[11];
    const float* sW3 = (const float*)d_in[12];
    const float* sb3 = (const float*)d_in[13];
    float* out = (float*)d_out;

    float *tok, *Hb, *E, *attn, *b2p, *w3p;
    __nv_bfloat16 *Ss, *Es, *Has, *Hal, *Wtok, *WE, *Wa2, *W2s, *H1h, *H1l;
    cudaGetSymbolAddress((void**)&tok, g_tok);
    cudaGetSymbolAddress((void**)&Hb, g_Hb);
    cudaGetSymbolAddress((void**)&E, g_E);
    cudaGetSymbolAddress((void**)&attn, g_attn);
    cudaGetSymbolAddress((void**)&Ss, g_Ss);
    cudaGetSymbolAddress((void**)&Es, g_Es);
    cudaGetSymbolAddress((void**)&Has, g_Has);
    cudaGetSymbolAddress((void**)&Hal, g_Hal);
    cudaGetSymbolAddress((void**)&Wtok, g_Wtok);
    cudaGetSymbolAddress((void**)&WE, g_WE);
    cudaGetSymbolAddress((void**)&Wa2, g_Wa2);
    cudaGetSymbolAddress((void**)&W2s, g_W2s);
    cudaGetSymbolAddress((void**)&H1h, g_H1h);
    cudaGetSymbolAddress((void**)&H1l, g_H1l);
    cudaGetSymbolAddress((void**)&b2p, g_b2p);
    cudaGetSymbolAddress((void**)&w3p, g_w3p);

    const size_t PLtok = (size_t)400 * 480;
    const size_t PLE = (size_t)304 * 160;
    const size_t PL2 = (size_t)160 * 160;

    // weight prep (tiny)
    pad_split_w<<<(400 * 160 + 255) / 256, 256>>>(aW1, 400, 400, 480,
                                                  Wtok, Wtok + PLtok);
    pad_split_w<<<(400 * 160 + 255) / 256, 256>>>(sW1, 400, 400, 480,
                                                  Wtok + 160, Wtok + PLtok + 160);
    pad_split_w<<<(400 * 160 + 255) / 256, 256>>>(sW1 + (size_t)400 * kH, 400, 400, 480,
                                                  Wtok + 320, Wtok + PLtok + 320);
    pad_split_w<<<(304 * 160 + 255) / 256, 256>>>(sW1 + (size_t)800 * kH, 300, 304, 160,
                                                  WE, WE + PLE);
    pad_split_w<<<(160 * 160 + 255) / 256, 256>>>(aW2, 150, 160, 160,
                                                  Wa2, Wa2 + PL2);
    pad_split_w<<<(160 * 160 + 255) / 256, 256>>>(sW2, 150, 160, 160,
                                                  W2s, W2s + PL2);
    pad_vec<<<1, H1P>>>(sb2, sW3, b2p, w3p);

    // activation splits
    conv_split<<<(kT * 100 + 255) / 256, 256>>>(states, kT, kS, kS,
                                                Ss, Ss + (size_t)kT * kS);
    conv_split<<<(kT * 75 + 255) / 256, 256>>>(embeds, kT, kE, 304,
                                               Es, Es + (size_t)kT * 304);

    int mt = (kT + MBM - 1) / MBM;  // 313

    // E = embeds @ sW1[800:1100]   (K=300 -> 19 steps)
    mma_gemm_pre<<<dim3(mt, 1), 256>>>(kT, 19, Es, Es + (size_t)kT * 304, 304,
                                       WE, WE + PLE, 160,
                                       nullptr, nullptr, 0, E, kH,
                                       nullptr, nullptr);
    // tok GEMM: seg0 Ha (-> split bf16 Has/Hal), seg1 A(+sb1), seg2 B  (K=400 -> 25)
    mma_gemm_pre<<<dim3(mt, 3), 256>>>(kT, 25, Ss, Ss + (size_t)kT * kS, kS,
                                       Wtok, Wtok + PLtok, 480,
                                       ab1, sb1, 1, tok, TOKW,
                                       Has, Hal);
    // Hb = relu(Ha @ aW2 + ab2)   (K=150 -> 10 steps, padded operands)
    mma_gemm_pre<<<dim3(mt, 1), 256>>>(kT, 10, Has, Hal, H1P,
                                       Wa2, Wa2 + PL2, 160,
                                       ab2, nullptr, 1, Hb, kH,
                                       nullptr, nullptr);

    attn_out_kernel<<<(kT + 7) / 8, 256>>>(Hb, aW3, ab3, attn, kT);

    h1_kernel<<<dim3(592, 10), 160>>>(attn, tok, E, H1h, H1l);

    score_mma<<<(NSPANS + SCBM - 1) / SCBM, 256>>>(H1h, H1l, W2s, b2p, w3p,
                                                   sb3, out, NSPANS);
}

// round 10
// speedup vs baseline: 2.0521x; 1.0482x over previous
#include <cuda_runtime.h>
#include <cuda_bf16.h>

#define kT 20000
#define kE 300
#define kS 400
#define kH 150
#define NSPANS (10 * kT - 45)
#define TOKW 452    // padded f32 row: 150:300 A, 300:450 B (cols 0:150 unused)
#define H1P 160

typedef unsigned long long ull;

// Scratch (allocation-free rule: __device__ globals; zero-initialized)
__device__ float g_tok[(size_t)kT * TOKW];
__device__ float g_E[(size_t)kT * kH];
__device__ float g_attn[kT];
__device__ __nv_bfloat16 g_Ss[2 * (size_t)kT * kS];        // split states
__device__ __nv_bfloat16 g_Es[2 * (size_t)kT * 304];       // split embeds (pad 304)
__device__ __nv_bfloat16 g_Has[(size_t)kT * H1P];          // Ha hi
__device__ __nv_bfloat16 g_Hal[(size_t)kT * H1P];          // Ha lo
__device__ __nv_bfloat16 g_Wtok[2 * 400 * 480];            // [aW1|sW1A|sW1B] padded
__device__ __nv_bfloat16 g_WE[2 * 304 * 160];
__device__ __nv_bfloat16 g_Wa2[2 * 160 * 160];
__device__ __nv_bfloat16 g_W2s[2 * 160 * 160];
__device__ float g_ab2p[H1P];
__device__ float g_aw3p[H1P];
__device__ float g_sb2p[H1P];
__device__ float g_sw3p[H1P];

static __device__ __forceinline__ unsigned sm_u32(const void* p) {
    return (unsigned)__cvta_generic_to_shared(p);
}
static __device__ __forceinline__ unsigned pack_bf2(__nv_bfloat16 a, __nv_bfloat16 b) {
    unsigned r;
    unsigned short ua = *(unsigned short*)&a, ub = *(unsigned short*)&b;
    asm("mov.b32 %0, {%1, %2};" : "=r"(r) : "h"(ua), "h"(ub));
    return r;
}

#define MMA6(c0, c1, A0, A1, BH, BL)                                          \
    asm volatile("mma.sync.aligned.m16n8k16.row.col.f32.bf16.bf16.f32 "       \
                 "{%0,%1,%2,%3},{%4,%5,%6,%7},{%8,%9},{%0,%1,%2,%3};"         \
                 : "+f"(c0[0]), "+f"(c0[1]), "+f"(c0[2]), "+f"(c0[3])         \
                 : "r"(A0[0]), "r"(A0[1]), "r"(A0[2]), "r"(A0[3]),            \
                   "r"(BH[0]), "r"(BH[1]));                                   \
    asm volatile("mma.sync.aligned.m16n8k16.row.col.f32.bf16.bf16.f32 "       \
                 "{%0,%1,%2,%3},{%4,%5,%6,%7},{%8,%9},{%0,%1,%2,%3};"         \
                 : "+f"(c1[0]), "+f"(c1[1]), "+f"(c1[2]), "+f"(c1[3])         \
                 : "r"(A0[0]), "r"(A0[1]), "r"(A0[2]), "r"(A0[3]),            \
                   "r"(BH[2]), "r"(BH[3]));                                   \
    asm volatile("mma.sync.aligned.m16n8k16.row.col.f32.bf16.bf16.f32 "       \
                 "{%0,%1,%2,%3},{%4,%5,%6,%7},{%8,%9},{%0,%1,%2,%3};"         \
                 : "+f"(c0[0]), "+f"(c0[1]), "+f"(c0[2]), "+f"(c0[3])         \
                 : "r"(A1[0]), "r"(A1[1]), "r"(A1[2]), "r"(A1[3]),            \
                   "r"(BH[0]), "r"(BH[1]));                                   \
    asm volatile("mma.sync.aligned.m16n8k16.row.col.f32.bf16.bf16.f32 "       \
                 "{%0,%1,%2,%3},{%4,%5,%6,%7},{%8,%9},{%0,%1,%2,%3};"         \
                 : "+f"(c1[0]), "+f"(c1[1]), "+f"(c1[2]), "+f"(c1[3])         \
                 : "r"(A1[0]), "r"(A1[1]), "r"(A1[2]), "r"(A1[3]),            \
                   "r"(BH[2]), "r"(BH[3]));                                   \
    asm volatile("mma.sync.aligned.m16n8k16.row.col.f32.bf16.bf16.f32 "       \
                 "{%0,%1,%2,%3},{%4,%5,%6,%7},{%8,%9},{%0,%1,%2,%3};"         \
                 : "+f"(c0[0]), "+f"(c0[1]), "+f"(c0[2]), "+f"(c0[3])         \
                 : "r"(A0[0]), "r"(A0[1]), "r"(A0[2]), "r"(A0[3]),            \
                   "r"(BL[0]), "r"(BL[1]));                                   \
    asm volatile("mma.sync.aligned.m16n8k16.row.col.f32.bf16.bf16.f32 "       \
                 "{%0,%1,%2,%3},{%4,%5,%6,%7},{%8,%9},{%0,%1,%2,%3};"         \
                 : "+f"(c1[0]), "+f"(c1[1]), "+f"(c1[2]), "+f"(c1[3])         \
                 : "r"(A0[0]), "r"(A0[1]), "r"(A0[2]), "r"(A0[3]),            \
                   "r"(BL[2]), "r"(BL[3]));

// ---------------------------------------------------------------------------
// One-shot prep: all weight splits + padded vectors in a single launch.
// ---------------------------------------------------------------------------
static __device__ __forceinline__ void wsplit(
    float w, __nv_bfloat16* dh, __nv_bfloat16* dl, size_t idx)
{
    __nv_bfloat16 hi = __float2bfloat16_rn(w);
    dh[idx] = hi;
    dl[idx] = __float2bfloat16_rn(w - __bfloat162float(hi));
}

__global__ void prep_all(
    const float* __restrict__ aW1, const float* __restrict__ sW1,
    const float* __restrict__ aW2, const float* __restrict__ sW2,
    const float* __restrict__ ab2, const float* __restrict__ aW3,
    const float* __restrict__ sb2, const float* __restrict__ sW3,
    __nv_bfloat16* __restrict__ Wtok, __nv_bfloat16* __restrict__ WE,
    __nv_bfloat16* __restrict__ Wa2, __nv_bfloat16* __restrict__ W2s,
    float* __restrict__ ab2p, float* __restrict__ aw3p,
    float* __restrict__ sb2p, float* __restrict__ sw3p)
{
    const int NT = 400 * 160, NE = 304 * 160, N2 = 160 * 160;
    int i = blockIdx.x * blockDim.x + threadIdx.x;
    if (i < 3 * NT) {
        int t = i / NT, r = i - t * NT;
        int k = r / 160, c = r - k * 160;
        const float* src = (t == 0) ? aW1 : ((t == 1) ? sW1 : sW1 + 400 * 150);
        float w = (c < 150) ? src[(size_t)k * 150 + c] : 0.f;
        wsplit(w, Wtok, Wtok + (size_t)400 * 480, (size_t)k * 480 + t * 160 + c);
        return;
    }
    i -= 3 * NT;
    if (i < NE) {
        int k = i / 160, c = i - k * 160;
        float w = (k < 300 && c < 150) ? sW1[(size_t)(800 + k) * 150 + c] : 0.f;
        wsplit(w, WE, WE + (size_t)304 * 160, i);
        return;
    }
    i -= NE;
    if (i < N2) {
        int k = i / 160, c = i - k * 160;
        float w = (k < 150 && c < 150) ? aW2[(size_t)k * 150 + c] : 0.f;
        wsplit(w, Wa2, Wa2 + N2, i);
        return;
    }
    i -= N2;
    if (i < N2) {
        int k = i / 160, c = i - k * 160;
        float w = (k < 150 && c < 150) ? sW2[(size_t)k * 150 + c] : 0.f;
        wsplit(w, W2s, W2s + N2, i);
        return;
    }
    i -= N2;
    if (i < H1P) {
        ab2p[i] = (i < 150) ? ab2[i] : 0.f;
        aw3p[i] = (i < 150) ? aW3[i] : 0.f;
        sb2p[i] = (i < 150) ? sb2[i] : 0.f;
        sw3p[i] = (i < 150) ? sW3[i] : 0.f;
    }
}

// ---------------------------------------------------------------------------
// Split activation matrix f32 [M x K] -> bf16 hi/lo [M x ldd]
// ---------------------------------------------------------------------------
__global__ void conv_split(const float* __restrict__ src, int M, int K, int ldd,
                           __nv_bfloat16* __restrict__ dh,
                           __nv_bfloat16* __restrict__ dl)
{
    int i = blockIdx.x * blockDim.x + threadIdx.x;
    int q4 = K >> 2;
    if (i >= M * q4) return;
    int row = i / q4, q = i - row * q4;
    float4 v = *(const float4*)&src[(size_t)row * K + q * 4];
    float* vp = (float*)&v;
    __nv_bfloat16 h[4], l[4];
    #pragma unroll
    for (int j = 0; j < 4; j++) {
        h[j] = __float2bfloat16_rn(vp[j]);
        l[j] = __float2bfloat16_rn(vp[j] - __bfloat162float(h[j]));
    }
    uint2 sh = {pack_bf2(h[0], h[1]), pack_bf2(h[2], h[3])};
    uint2 sl = {pack_bf2(l[0], l[1]), pack_bf2(l[2], l[3])};
    *(uint2*)&dh[(size_t)row * ldd + q * 4] = sh;
    *(uint2*)&dl[(size_t)row * ldd + q * 4] = sl;
}

// ---------------------------------------------------------------------------
// Split-bf16 tensor-core GEMM, pre-converted operands (copy-only staging).
// 64M x 160N tile, 8 warps (4Mx2N), double-buffered, 2 blocks/SM.
// ---------------------------------------------------------------------------
#define MBM 64

__global__ __launch_bounds__(256, 2) void mma_gemm_pre(
    int M, int nsteps,
    const __nv_bfloat16* __restrict__ Ah, const __nv_bfloat16* __restrict__ Al,
    int lda,
    const __nv_bfloat16* __restrict__ Bh, const __nv_bfloat16* __restrict__ Bl,
    int ldb,
    const float* __restrict__ bias0, const float* __restrict__ bias1,
    int relu_mask,
    float* __restrict__ C, int ldc,
    __nv_bfloat16* __restrict__ Csh, __nv_bfloat16* __restrict__ Csl)
{
    __shared__ __align__(16) __nv_bfloat16 As[2][2][MBM * 24];
    __shared__ __align__(16) __nv_bfloat16 Bs[2][2][16 * 168];

    int tid = threadIdx.x;
    int m0 = blockIdx.x * MBM;
    int seg = blockIdx.y;
    int n0 = seg * 160;
    int wid = tid >> 5, lane = tid & 31;
    int warpM = wid & 3, warpN = wid >> 2;

    float Cr[10][4] = {};

    auto stage = [&](int ks, int buf) {
        int k0 = ks * 16;
        {
            int sp = tid >> 7, tt = tid & 127, r = tt >> 1, half = tt & 1;
            int row = min(m0 + r, M - 1);
            const __nv_bfloat16* src =
                (sp ? Al : Ah) + (size_t)row * lda + k0 + half * 8;
            *(int4*)&As[buf][sp][r * 24 + half * 8] = *(const int4*)src;
        }
        #pragma unroll 3
        for (int c = tid; c < 640; c += 256) {
            int sp = c / 320, cc = c % 320, row = cc / 20, offc = cc % 20;
            const __nv_bfloat16* src =
                (sp ? Bl : Bh) + (size_t)(k0 + row) * ldb + n0 + offc * 8;
            *(int4*)&Bs[buf][sp][row * 168 + offc * 8] = *(const int4*)src;
        }
    };

    stage(0, 0);
    __syncthreads();

    for (int ks = 0; ks < nsteps; ks++) {
        int buf = ks & 1;
        if (ks + 1 < nsteps) stage(ks + 1, buf ^ 1);

        unsigned a[2][4];
        #pragma unroll
        for (int sp = 0; sp < 2; sp++) {
            unsigned addr = sm_u32(
                &As[buf][sp][(warpM * 16 + (lane & 15)) * 24 + (lane >> 4) * 8]);
            asm volatile(
                "ldmatrix.sync.aligned.m8n8.x4.shared.b16 {%0,%1,%2,%3}, [%4];"
                : "=r"(a[sp][0]), "=r"(a[sp][1]), "=r"(a[sp][2]), "=r"(a[sp][3])
                : "r"(addr));
        }

        #pragma unroll
        for (int np = 0; np < 5; np++) {
            int nbase = warpN * 80 + np * 16;
            unsigned bh[4], bl[4];
            {
                unsigned addr = sm_u32(
                    &Bs[buf][0][(lane & 15) * 168 + nbase + (lane >> 4) * 8]);
                asm volatile(
                    "ldmatrix.sync.aligned.m8n8.x4.trans.shared.b16 {%0,%1,%2,%3}, [%4];"
                    : "=r"(bh[0]), "=r"(bh[1]), "=r"(bh[2]), "=r"(bh[3])
                    : "r"(addr));
            }
            {
                unsigned addr = sm_u32(
                    &Bs[buf][1][(lane & 15) * 168 + nbase + (lane >> 4) * 8]);
                asm volatile(
                    "ldmatrix.sync.aligned.m8n8.x4.trans.shared.b16 {%0,%1,%2,%3}, [%4];"
                    : "=r"(bl[0]), "=r"(bl[1]), "=r"(bl[2]), "=r"(bl[3])
                    : "r"(addr));
            }
            float* c0 = Cr[2 * np];
            float* c1 = Cr[2 * np + 1];
            MMA6(c0, c1, a[0], a[1], bh, bl);
        }
        __syncthreads();
    }

    // epilogue
    int tq = lane & 3, g = lane >> 2;
    int mr0 = m0 + warpM * 16 + g;
    bool rl = (relu_mask >> seg) & 1;
    const float* bias = (seg == 0) ? bias0 : ((seg == 1) ? bias1 : nullptr);
    bool splitOut = (seg == 0) && (Csh != nullptr);
    #pragma unroll
    for (int nf = 0; nf < 10; nf++) {
        int nloc = warpN * 80 + nf * 8 + tq * 2;
        float* c = Cr[nf];
        if (nloc >= 150) {
            if (splitOut) {
                __nv_bfloat16 z = __float2bfloat16(0.f);
                if (mr0 < M) {
                    Csh[(size_t)mr0 * H1P + nloc] = z;  Csl[(size_t)mr0 * H1P + nloc] = z;
                    Csh[(size_t)mr0 * H1P + nloc + 1] = z; Csl[(size_t)mr0 * H1P + nloc + 1] = z;
                }
                if (mr0 + 8 < M) {
                    Csh[(size_t)(mr0 + 8) * H1P + nloc] = z;  Csl[(size_t)(mr0 + 8) * H1P + nloc] = z;
                    Csh[(size_t)(mr0 + 8) * H1P + nloc + 1] = z; Csl[(size_t)(mr0 + 8) * H1P + nloc + 1] = z;
                }
            }
            continue;
        }
        float bb0 = 0.f, bb1 = 0.f;
        if (bias) { bb0 = bias[nloc]; bb1 = bias[nloc + 1]; }
        float v0 = c[0] + bb0, v1 = c[1] + bb1;
        float v2 = c[2] + bb0, v3 = c[3] + bb1;
        if (rl) {
            v0 = fmaxf(v0, 0.f); v1 = fmaxf(v1, 0.f);
            v2 = fmaxf(v2, 0.f); v3 = fmaxf(v3, 0.f);
        }
        if (splitOut) {
            float vv[4] = {v0, v1, v2, v3};
            #pragma unroll
            for (int q = 0; q < 4; q++) {
                int m = (q < 2) ? mr0 : mr0 + 8;
                if (m >= M) continue;
                int n = nloc + (q & 1);
                __nv_bfloat16 hi = __float2bfloat16_rn(vv[q]);
                __nv_bfloat16 lo = __float2bfloat16_rn(vv[q] - __bfloat162float(hi));
                Csh[(size_t)m * H1P + n] = hi;
                Csl[(size_t)m * H1P + n] = lo;
            }
        } else {
            int n = seg * 150 + nloc;
            if (mr0 < M) {
                C[(size_t)mr0 * ldc + n] = v0;
                C[(size_t)mr0 * ldc + n + 1] = v1;
            }
            if (mr0 + 8 < M) {
                C[(size_t)(mr0 + 8) * ldc + n] = v2;
                C[(size_t)(mr0 + 8) * ldc + n + 1] = v3;
            }
        }
    }
}

// ---------------------------------------------------------------------------
// score_mma: H[M x 160](split) @ W[160 x 160](split) with fused
// out[m] = sum_col relu(C + b2)*W3 + b3.  Used for the attention tail.
// ---------------------------------------------------------------------------
#define SCBM 64

__global__ __launch_bounds__(256, 2) void score_mma(
    const __nv_bfloat16* __restrict__ H1h, const __nv_bfloat16* __restrict__ H1l,
    const __nv_bfloat16* __restrict__ W2s,
    const float* __restrict__ b2p, const float* __restrict__ w3p,
    const float* __restrict__ b3,
    float* __restrict__ out, int M)
{
    __shared__ __align__(16) __nv_bfloat16 As[2][2][SCBM * 24];
    __shared__ __align__(16) __nv_bfloat16 Bs[2][2][16 * 168];
    __shared__ float red[SCBM][2];

    int tid = threadIdx.x;
    int m0 = blockIdx.x * SCBM;
    int wid = tid >> 5, lane = tid & 31;
    int warpM = wid & 3, warpN = wid >> 2;

    float C[10][4] = {};

    auto stage = [&](int ks, int buf) {
        int k0 = ks * 16;
        {
            int sp = tid >> 7, tt = tid & 127, r = tt >> 1, half = tt & 1;
            int mrow = min(m0 + r, M - 1);
            const __nv_bfloat16* src =
                (sp ? H1l : H1h) + (size_t)mrow * H1P + k0 + half * 8;
            *(int4*)&As[buf][sp][r * 24 + half * 8] = *(const int4*)src;
        }
        for (int c = tid; c < 640; c += 256) {
            int sp = c / 320, cc = c % 320, row = cc / 20, offc = cc % 20;
            const __nv_bfloat16* src =
                W2s + (size_t)sp * H1P * H1P + (size_t)(k0 + row) * H1P + offc * 8;
            *(int4*)&Bs[buf][sp][row * 168 + offc * 8] = *(const int4*)src;
        }
    };

    stage(0, 0);
    __syncthreads();

    for (int ks = 0; ks < 10; ks++) {
        int buf = ks & 1;
        if (ks < 9) stage(ks + 1, buf ^ 1);

        unsigned a[2][4];
        #pragma unroll
        for (int sp = 0; sp < 2; sp++) {
            unsigned addr = sm_u32(
                &As[buf][sp][(warpM * 16 + (lane & 15)) * 24 + (lane >> 4) * 8]);
            asm volatile(
                "ldmatrix.sync.aligned.m8n8.x4.shared.b16 {%0,%1,%2,%3}, [%4];"
                : "=r"(a[sp][0]), "=r"(a[sp][1]), "=r"(a[sp][2]), "=r"(a[sp][3])
                : "r"(addr));
        }

        #pragma unroll
        for (int np = 0; np < 5; np++) {
            int nbase = warpN * 80 + np * 16;
            unsigned bh[4], bl[4];
            {
                unsigned addr = sm_u32(
                    &Bs[buf][0][(lane & 15) * 168 + nbase + (lane >> 4) * 8]);
                asm volatile(
                    "ldmatrix.sync.aligned.m8n8.x4.trans.shared.b16 {%0,%1,%2,%3}, [%4];"
                    : "=r"(bh[0]), "=r"(bh[1]), "=r"(bh[2]), "=r"(bh[3])
                    : "r"(addr));
            }
            {
                unsigned addr = sm_u32(
                    &Bs[buf][1][(lane & 15) * 168 + nbase + (lane >> 4) * 8]);
                asm volatile(
                    "ldmatrix.sync.aligned.m8n8.x4.trans.shared.b16 {%0,%1,%2,%3}, [%4];"
                    : "=r"(bl[0]), "=r"(bl[1]), "=r"(bl[2]), "=r"(bl[3])
                    : "r"(addr));
            }
            float* c0 = C[2 * np];
            float* c1 = C[2 * np + 1];
            MMA6(c0, c1, a[0], a[1], bh, bl);
        }
        __syncthreads();
    }

    int tq = lane & 3, g = lane >> 2;
    float v0 = 0.f, v1 = 0.f;
    #pragma unroll
    for (int nf = 0; nf < 10; nf++) {
        int col = warpN * 80 + nf * 8 + tq * 2;
        float bb0 = __ldg(&b2p[col]), bb1 = __ldg(&b2p[col + 1]);
        float ww0 = __ldg(&w3p[col]), ww1 = __ldg(&w3p[col + 1]);
        float* c = C[nf];
        v0 = fmaf(fmaxf(c[0] + bb0, 0.f), ww0, v0);
        v0 = fmaf(fmaxf(c[1] + bb1, 0.f), ww1, v0);
        v1 = fmaf(fmaxf(c[2] + bb0, 0.f), ww0, v1);
        v1 = fmaf(fmaxf(c[3] + bb1, 0.f), ww1, v1);
    }
    v0 += __shfl_xor_sync(0xffffffffu, v0, 1);
    v0 += __shfl_xor_sync(0xffffffffu, v0, 2);
    v1 += __shfl_xor_sync(0xffffffffu, v1, 1);
    v1 += __shfl_xor_sync(0xffffffffu, v1, 2);
    if (tq == 0) {
        red[warpM * 16 + g][warpN] = v0;
        red[warpM * 16 + g + 8][warpN] = v1;
    }
    __syncthreads();
    if (tid < SCBM) {
        int m = m0 + tid;
        if (m < M) out[m] = red[tid][0] + red[tid][1] + b3[0];
    }
}

// ---------------------------------------------------------------------------
// Fused span kernel: per block, 64 same-width spans.
// Phase 1: softmax pool + h1 assembly straight into smem (split-bf16,
//          ldmatrix layout). Phase 2: 10-step MMA vs W2 + fused epilogue.
// Dynamic smem: As_all 61440B | Bs 21504B | red 512B = 83456B (2 blocks/SM).
// ---------------------------------------------------------------------------
#define AS_SP 15360   // bf16 elems per split plane: 10*64*24
#define BS_OFF 61440
#define RED_OFF 82944

__global__ __launch_bounds__(256, 2) void fused_span(
    const float* __restrict__ attn,
    const float* __restrict__ tok,
    const float* __restrict__ E,
    const __nv_bfloat16* __restrict__ W2s,
    const float* __restrict__ b2p, const float* __restrict__ w3p,
    const float* __restrict__ b3,
    float* __restrict__ out)
{
    extern __shared__ __align__(16) char smem[];
    __nv_bfloat16* As_all = (__nv_bfloat16*)smem;
    __nv_bfloat16* Bs = (__nv_bfloat16*)(smem + BS_OFF);
    float* red = (float*)(smem + RED_OFF);   // [64][2]

    int tid = threadIdx.x;
    int wid = tid >> 5, lane = tid & 31;
    int n = blockIdx.y + 1;
    int S = kT - n + 1;
    int base = blockIdx.x * 64;
    int off = (n - 1) * (kT + 1) - (n * (n - 1)) / 2;

    auto stageB = [&](int ks, int buf) {
        int k0 = ks * 16;
        for (int c = tid; c < 640; c += 256) {
            int sp = c / 320, cc = c % 320, row = cc / 20, offc = cc % 20;
            const __nv_bfloat16* src =
                W2s + (size_t)sp * (H1P * H1P) + (size_t)(k0 + row) * H1P + offc * 8;
            *(int4*)&Bs[(buf * 2 + sp) * 2688 + row * 168 + offc * 8] =
                *(const int4*)src;
        }
    };
    stageB(0, 0);

    // ---- phase 1: build split-bf16 h1 tile (warp = 8 spans, lanes = cols) ----
    for (int i = 0; i < 8; i++) {
        int sl = wid * 8 + i;
        int s = base + sl;
        bool valid = s < S;
        float acc[5];
        if (valid) {
            int e = s + n - 1;
            // warp softmax: lane j < n holds w_j
            float av = (lane < n) ? attn[s + lane] : -1e30f;
            float mx = av;
            #pragma unroll
            for (int o = 16; o > 0; o >>= 1)
                mx = fmaxf(mx, __shfl_xor_sync(0xffffffffu, mx, o));
            float ev = (lane < n) ? __expf(av - mx) : 0.f;
            float sum = ev;
            #pragma unroll
            for (int o = 16; o > 0; o >>= 1)
                sum += __shfl_xor_sync(0xffffffffu, sum, o);
            float wv = ev / sum;
            #pragma unroll
            for (int ch = 0; ch < 5; ch++) {
                int c = ch * 32 + lane;
                acc[ch] = (c < 150)
                    ? tok[(size_t)s * TOKW + 150 + c] + tok[(size_t)e * TOKW + 300 + c]
                    : 0.f;
            }
            for (int j = 0; j < n; j++) {
                float wj = __shfl_sync(0xffffffffu, wv, j);
                const float* Er = E + (size_t)(s + j) * kH;
                #pragma unroll
                for (int ch = 0; ch < 5; ch++) {
                    int c = ch * 32 + lane;
                    if (c < 150) acc[ch] = fmaf(wj, Er[c], acc[ch]);
                }
            }
        } else {
            #pragma unroll
            for (int ch = 0; ch < 5; ch++) acc[ch] = 0.f;
        }
        #pragma unroll
        for (int ch = 0; ch < 5; ch++) {
            int c = ch * 32 + lane;
            float v = (c < 150 && valid) ? fmaxf(acc[ch], 0.f) : 0.f;
            __nv_bfloat16 hi = __float2bfloat16_rn(v);
            __nv_bfloat16 lo = __float2bfloat16_rn(v - __bfloat162float(hi));
            int idx = (c >> 4) * 1536 + sl * 24 + ((c >> 3) & 1) * 8 + (c & 7);
            As_all[idx] = hi;
            As_all[AS_SP + idx] = lo;
        }
    }
    __syncthreads();

    // ---- phase 2: MMA vs W2 ----
    int warpM = wid & 3, warpN = wid >> 2;
    float C[10][4] = {};

    for (int ks = 0; ks < 10; ks++) {
        int buf = ks & 1;
        if (ks < 9) stageB(ks + 1, buf ^ 1);

        unsigned a[2][4];
        #pragma unroll
        for (int sp = 0; sp < 2; sp++) {
            unsigned addr = sm_u32(
                &As_all[sp * AS_SP + ks * 1536 +
                        (warpM * 16 + (lane & 15)) * 24 + (lane >> 4) * 8]);
            asm volatile(
                "ldmatrix.sync.aligned.m8n8.x4.shared.b16 {%0,%1,%2,%3}, [%4];"
                : "=r"(a[sp][0]), "=r"(a[sp][1]), "=r"(a[sp][2]), "=r"(a[sp][3])
                : "r"(addr));
        }

        #pragma unroll
        for (int np = 0; np < 5; np++) {
            int nbase = warpN * 80 + np * 16;
            unsigned bh[4], bl[4];
            {
                unsigned addr = sm_u32(
                    &Bs[(buf * 2 + 0) * 2688 + (lane & 15) * 168 + nbase +
                        (lane >> 4) * 8]);
                asm volatile(
                    "ldmatrix.sync.aligned.m8n8.x4.trans.shared.b16 {%0,%1,%2,%3}, [%4];"
                    : "=r"(bh[0]), "=r"(bh[1]), "=r"(bh[2]), "=r"(bh[3])
                    : "r"(addr));
            }
            {
                unsigned addr = sm_u32(
                    &Bs[(buf * 2 + 1) * 2688 + (lane & 15) * 168 + nbase +
                        (lane >> 4) * 8]);
                asm volatile(
                    "ldmatrix.sync.aligned.m8n8.x4.trans.shared.b16 {%0,%1,%2,%3}, [%4];"
                    : "=r"(bl[0]), "=r"(bl[1]), "=r"(bl[2]), "=r"(bl[3])
                    : "r"(addr));
            }
            float* c0 = C[2 * np];
            float* c1 = C[2 * np + 1];
            MMA6(c0, c1, a[0], a[1], bh, bl);
        }
        __syncthreads();
    }

    // ---- fused epilogue ----
    int tq = lane & 3, g = lane >> 2;
    float v0 = 0.f, v1 = 0.f;
    #pragma unroll
    for (int nf = 0; nf < 10; nf++) {
        int col = warpN * 80 + nf * 8 + tq * 2;
        float bb0 = __ldg(&b2p[col]), bb1 = __ldg(&b2p[col + 1]);
        float ww0 = __ldg(&w3p[col]), ww1 = __ldg(&w3p[col + 1]);
        float* c = C[nf];
        v0 = fmaf(fmaxf(c[0] + bb0, 0.f), ww0, v0);
        v0 = fmaf(fmaxf(c[1] + bb1, 0.f), ww1, v0);
        v1 = fmaf(fmaxf(c[2] + bb0, 0.f), ww0, v1);
        v1 = fmaf(fmaxf(c[3] + bb1, 0.f), ww1, v1);
    }
    v0 += __shfl_xor_sync(0xffffffffu, v0, 1);
    v0 += __shfl_xor_sync(0xffffffffu, v0, 2);
    v1 += __shfl_xor_sync(0xffffffffu, v1, 1);
    v1 += __shfl_xor_sync(0xffffffffu, v1, 2);
    if (tq == 0) {
        red[(warpM * 16 + g) * 2 + warpN] = v0;
        red[(warpM * 16 + g + 8) * 2 + warpN] = v1;
    }
    __syncthreads();
    if (tid < 64) {
        int m = base + tid;
        if (m < S) out[off + m] = red[tid * 2] + red[tid * 2 + 1] + b3[0];
    }
}

// ---------------------------------------------------------------------------
extern "C" void kernel_launch(void* const* d_in, const int* in_sizes, int n_in,
                              void* d_out, int out_size)
{
    const float* embeds = (const float*)d_in[0];
    const float* states = (const float*)d_in[1];
    const float* aW1 = (const float*)d_in[2];
    const float* ab1 = (const float*)d_in[3];
    const float* aW2 = (const float*)d_in[4];
    const float* ab2 = (const float*)d_in[5];
    const float* aW3 = (const float*)d_in[6];
    const float* ab3 = (const float*)d_in[7];
    const float* sW1 = (const float*)d_in[8];
    const float* sb1 = (const float*)d_in[9];
    const float* sW2 = (const float*)d_in[10];
    const float* sb2 = (const float*)d_in[11];
    const float* sW3 = (const float*)d_in[12];
    const float* sb3 = (const float*)d_in[13];
    float* out = (float*)d_out;

    float *tok, *E, *attn, *ab2p, *aw3p, *sb2p, *sw3p;
    __nv_bfloat16 *Ss, *Es, *Has, *Hal, *Wtok, *WE, *Wa2, *W2s;
    cudaGetSymbolAddress((void**)&tok, g_tok);
    cudaGetSymbolAddress((void**)&E, g_E);
    cudaGetSymbolAddress((void**)&attn, g_attn);
    cudaGetSymbolAddress((void**)&Ss, g_Ss);
    cudaGetSymbolAddress((void**)&Es, g_Es);
    cudaGetSymbolAddress((void**)&Has, g_Has);
    cudaGetSymbolAddress((void**)&Hal, g_Hal);
    cudaGetSymbolAddress((void**)&Wtok, g_Wtok);
    cudaGetSymbolAddress((void**)&WE, g_WE);
    cudaGetSymbolAddress((void**)&Wa2, g_Wa2);
    cudaGetSymbolAddress((void**)&W2s, g_W2s);
    cudaGetSymbolAddress((void**)&ab2p, g_ab2p);
    cudaGetSymbolAddress((void**)&aw3p, g_aw3p);
    cudaGetSymbolAddress((void**)&sb2p, g_sb2p);
    cudaGetSymbolAddress((void**)&sw3p, g_sw3p);

    static bool attr_set = false;
    if (!attr_set) {
        cudaFuncSetAttribute(fused_span,
                             cudaFuncAttributeMaxDynamicSharedMemorySize, 83456);
        attr_set = true;
    }

    // 1. all weight prep in one launch
    {
        int total = 3 * 400 * 160 + 304 * 160 + 2 * 160 * 160 + H1P;
        prep_all<<<(total + 255) / 256, 256>>>(aW1, sW1, aW2, sW2, ab2, aW3,
                                               sb2, sW3, Wtok, WE, Wa2, W2s,
                                               ab2p, aw3p, sb2p, sw3p);
    }
    // 2-3. activation splits
    conv_split<<<(kT * 100 + 255) / 256, 256>>>(states, kT, kS, kS,
                                                Ss, Ss + (size_t)kT * kS);
    conv_split<<<(kT * 75 + 255) / 256, 256>>>(embeds, kT, kE, 304,
                                               Es, Es + (size_t)kT * 304);

    int mt = (kT + MBM - 1) / MBM;  // 313

    // 4. E = embeds @ sW1[800:1100]   (19 k-steps)
    mma_gemm_pre<<<dim3(mt, 1), 256>>>(kT, 19, Es, Es + (size_t)kT * 304, 304,
                                       WE, WE + (size_t)304 * 160, 160,
                                       nullptr, nullptr, 0, E, kH,
                                       nullptr, nullptr);
    // 5. tok GEMM: seg0 Ha(->split), seg1 A(+sb1), seg2 B   (25 k-steps)
    mma_gemm_pre<<<dim3(mt, 3), 256>>>(kT, 25, Ss, Ss + (size_t)kT * kS, kS,
                                       Wtok, Wtok + (size_t)400 * 480, 480,
                                       ab1, sb1, 1, tok, TOKW,
                                       Has, Hal);
    // 6. attention tail: attn[t] = sum_h relu(Ha·aW2+ab2)·aW3 + ab3
    score_mma<<<(kT + SCBM - 1) / SCBM, 256>>>(Has, Hal, Wa2, ab2p, aw3p,
                                               ab3, attn, kT);
    // 7. fused span scoring (h1 assembly + score GEMM + epilogue)
    fused_span<<<dim3(313, 10), 256, 83456>>>(attn, tok, E, W2s, sb2p, sw3p,
                                              sb3, out);
}

// round 11
// speedup vs baseline: 2.8050x; 1.3669x over previous
#include <cuda_runtime.h>
#include <cuda_bf16.h>

#define kT 20000
#define kE 300
#define kS 400
#define kH 150
#define NSPANS (10 * kT - 45)
#define TOKW 452    // padded f32 row: 150:300 A, 300:450 B (cols 0:150 unused)
#define H1P 160

typedef unsigned long long ull;

// Scratch (allocation-free rule: __device__ globals; zero-initialized)
__device__ float g_tok[(size_t)kT * TOKW];
__device__ float g_E[(size_t)kT * kH];
__device__ float g_attn[kT];
__device__ __nv_bfloat16 g_Ss[2 * (size_t)kT * kS];        // split states
__device__ __nv_bfloat16 g_Es[2 * (size_t)kT * 304];       // split embeds (pad 304)
__device__ __nv_bfloat16 g_Has[(size_t)kT * H1P];          // Ha hi
__device__ __nv_bfloat16 g_Hal[(size_t)kT * H1P];          // Ha lo
__device__ __nv_bfloat16 g_Wtok[2 * 400 * 480];            // [aW1|sW1A|sW1B] padded
__device__ __nv_bfloat16 g_WE[2 * 304 * 160];
__device__ __nv_bfloat16 g_Wa2[2 * 160 * 160];
__device__ __nv_bfloat16 g_W2s[2 * 160 * 160];
__device__ float g_ab2p[H1P];
__device__ float g_aw3p[H1P];
__device__ float g_sb2p[H1P];
__device__ float g_sw3p[H1P];

static __device__ __forceinline__ unsigned sm_u32(const void* p) {
    return (unsigned)__cvta_generic_to_shared(p);
}
static __device__ __forceinline__ unsigned pack_bf2(__nv_bfloat16 a, __nv_bfloat16 b) {
    unsigned r;
    unsigned short ua = *(unsigned short*)&a, ub = *(unsigned short*)&b;
    asm("mov.b32 %0, {%1, %2};" : "=r"(r) : "h"(ua), "h"(ub));
    return r;
}

#define CP_ASYNC16(dst, src) \
    asm volatile("cp.async.cg.shared.global [%0], [%1], 16;" \
                 :: "r"(dst), "l"(src))
#define CP_COMMIT() asm volatile("cp.async.commit_group;" ::: "memory")
#define CP_WAIT(n)  asm volatile("cp.async.wait_group %0;" :: "n"(n) : "memory")

#define MMA6(c0, c1, A0, A1, BH, BL)                                          \
    asm volatile("mma.sync.aligned.m16n8k16.row.col.f32.bf16.bf16.f32 "       \
                 "{%0,%1,%2,%3},{%4,%5,%6,%7},{%8,%9},{%0,%1,%2,%3};"         \
                 : "+f"(c0[0]), "+f"(c0[1]), "+f"(c0[2]), "+f"(c0[3])         \
                 : "r"(A0[0]), "r"(A0[1]), "r"(A0[2]), "r"(A0[3]),            \
                   "r"(BH[0]), "r"(BH[1]));                                   \
    asm volatile("mma.sync.aligned.m16n8k16.row.col.f32.bf16.bf16.f32 "       \
                 "{%0,%1,%2,%3},{%4,%5,%6,%7},{%8,%9},{%0,%1,%2,%3};"         \
                 : "+f"(c1[0]), "+f"(c1[1]), "+f"(c1[2]), "+f"(c1[3])         \
                 : "r"(A0[0]), "r"(A0[1]), "r"(A0[2]), "r"(A0[3]),            \
                   "r"(BH[2]), "r"(BH[3]));                                   \
    asm volatile("mma.sync.aligned.m16n8k16.row.col.f32.bf16.bf16.f32 "       \
                 "{%0,%1,%2,%3},{%4,%5,%6,%7},{%8,%9},{%0,%1,%2,%3};"         \
                 : "+f"(c0[0]), "+f"(c0[1]), "+f"(c0[2]), "+f"(c0[3])         \
                 : "r"(A1[0]), "r"(A1[1]), "r"(A1[2]), "r"(A1[3]),            \
                   "r"(BH[0]), "r"(BH[1]));                                   \
    asm volatile("mma.sync.aligned.m16n8k16.row.col.f32.bf16.bf16.f32 "       \
                 "{%0,%1,%2,%3},{%4,%5,%6,%7},{%8,%9},{%0,%1,%2,%3};"         \
                 : "+f"(c1[0]), "+f"(c1[1]), "+f"(c1[2]), "+f"(c1[3])         \
                 : "r"(A1[0]), "r"(A1[1]), "r"(A1[2]), "r"(A1[3]),            \
                   "r"(BH[2]), "r"(BH[3]));                                   \
    asm volatile("mma.sync.aligned.m16n8k16.row.col.f32.bf16.bf16.f32 "       \
                 "{%0,%1,%2,%3},{%4,%5,%6,%7},{%8,%9},{%0,%1,%2,%3};"         \
                 : "+f"(c0[0]), "+f"(c0[1]), "+f"(c0[2]), "+f"(c0[3])         \
                 : "r"(A0[0]), "r"(A0[1]), "r"(A0[2]), "r"(A0[3]),            \
                   "r"(BL[0]), "r"(BL[1]));                                   \
    asm volatile("mma.sync.aligned.m16n8k16.row.col.f32.bf16.bf16.f32 "       \
                 "{%0,%1,%2,%3},{%4,%5,%6,%7},{%8,%9},{%0,%1,%2,%3};"         \
                 : "+f"(c1[0]), "+f"(c1[1]), "+f"(c1[2]), "+f"(c1[3])         \
                 : "r"(A0[0]), "r"(A0[1]), "r"(A0[2]), "r"(A0[3]),            \
                   "r"(BL[2]), "r"(BL[3]));

// ---------------------------------------------------------------------------
// One-shot prep: all weight splits + padded vectors in a single launch.
// ---------------------------------------------------------------------------
static __device__ __forceinline__ void wsplit(
    float w, __nv_bfloat16* dh, __nv_bfloat16* dl, size_t idx)
{
    __nv_bfloat16 hi = __float2bfloat16_rn(w);
    dh[idx] = hi;
    dl[idx] = __float2bfloat16_rn(w - __bfloat162float(hi));
}

__global__ void prep_all(
    const float* __restrict__ aW1, const float* __restrict__ sW1,
    const float* __restrict__ aW2, const float* __restrict__ sW2,
    const float* __restrict__ ab2, const float* __restrict__ aW3,
    const float* __restrict__ sb2, const float* __restrict__ sW3,
    __nv_bfloat16* __restrict__ Wtok, __nv_bfloat16* __restrict__ WE,
    __nv_bfloat16* __restrict__ Wa2, __nv_bfloat16* __restrict__ W2s,
    float* __restrict__ ab2p, float* __restrict__ aw3p,
    float* __restrict__ sb2p, float* __restrict__ sw3p)
{
    const int NT = 400 * 160, NE = 304 * 160, N2 = 160 * 160;
    int i = blockIdx.x * blockDim.x + threadIdx.x;
    if (i < 3 * NT) {
        int t = i / NT, r = i - t * NT;
        int k = r / 160, c = r - k * 160;
        const float* src = (t == 0) ? aW1 : ((t == 1) ? sW1 : sW1 + 400 * 150);
        float w = (c < 150) ? src[(size_t)k * 150 + c] : 0.f;
        wsplit(w, Wtok, Wtok + (size_t)400 * 480, (size_t)k * 480 + t * 160 + c);
        return;
    }
    i -= 3 * NT;
    if (i < NE) {
        int k = i / 160, c = i - k * 160;
        float w = (k < 300 && c < 150) ? sW1[(size_t)(800 + k) * 150 + c] : 0.f;
        wsplit(w, WE, WE + (size_t)304 * 160, i);
        return;
    }
    i -= NE;
    if (i < N2) {
        int k = i / 160, c = i - k * 160;
        float w = (k < 150 && c < 150) ? aW2[(size_t)k * 150 + c] : 0.f;
        wsplit(w, Wa2, Wa2 + N2, i);
        return;
    }
    i -= N2;
    if (i < N2) {
        int k = i / 160, c = i - k * 160;
        float w = (k < 150 && c < 150) ? sW2[(size_t)k * 150 + c] : 0.f;
        wsplit(w, W2s, W2s + N2, i);
        return;
    }
    i -= N2;
    if (i < H1P) {
        ab2p[i] = (i < 150) ? ab2[i] : 0.f;
        aw3p[i] = (i < 150) ? aW3[i] : 0.f;
        sb2p[i] = (i < 150) ? sb2[i] : 0.f;
        sw3p[i] = (i < 150) ? sW3[i] : 0.f;
    }
}

// ---------------------------------------------------------------------------
// Split activation matrix f32 [M x K] -> bf16 hi/lo [M x ldd]
// ---------------------------------------------------------------------------
__global__ void conv_split(const float* __restrict__ src, int M, int K, int ldd,
                           __nv_bfloat16* __restrict__ dh,
                           __nv_bfloat16* __restrict__ dl)
{
    int i = blockIdx.x * blockDim.x + threadIdx.x;
    int q4 = K >> 2;
    if (i >= M * q4) return;
    int row = i / q4, q = i - row * q4;
    float4 v = *(const float4*)&src[(size_t)row * K + q * 4];
    float* vp = (float*)&v;
    __nv_bfloat16 h[4], l[4];
    #pragma unroll
    for (int j = 0; j < 4; j++) {
        h[j] = __float2bfloat16_rn(vp[j]);
        l[j] = __float2bfloat16_rn(vp[j] - __bfloat162float(h[j]));
    }
    uint2 sh = {pack_bf2(h[0], h[1]), pack_bf2(h[2], h[3])};
    uint2 sl = {pack_bf2(l[0], l[1]), pack_bf2(l[2], l[3])};
    *(uint2*)&dh[(size_t)row * ldd + q * 4] = sh;
    *(uint2*)&dl[(size_t)row * ldd + q * 4] = sl;
}

// ---------------------------------------------------------------------------
// Combined token-level GEMM, cp.async 4-stage pipeline.
// blockIdx.y: 0 -> E = embeds@WE (19 steps); 1..3 -> tok segments (25 steps):
//   y=1: Ha (+ab1, relu) -> split bf16 Has/Hal; y=2: A (+sb1) -> tok f32;
//   y=3: B -> tok f32.
// Dynamic smem: As 4*2*1536*2 = 24576 | Bs 4*2*2688*2 = 43008  => 67584 B.
// ---------------------------------------------------------------------------
#define MBM 64
#define GSTG 4

__global__ __launch_bounds__(256, 2) void tokE_gemm(
    const __nv_bfloat16* __restrict__ Ss, const __nv_bfloat16* __restrict__ Es,
    const __nv_bfloat16* __restrict__ Wtok, const __nv_bfloat16* __restrict__ WE,
    const float* __restrict__ ab1, const float* __restrict__ sb1,
    float* __restrict__ tok, float* __restrict__ Eout,
    __nv_bfloat16* __restrict__ Has, __nv_bfloat16* __restrict__ Hal)
{
    extern __shared__ __align__(16) char smem[];
    __nv_bfloat16* As = (__nv_bfloat16*)smem;             // [4][2][1536]
    __nv_bfloat16* Bs = (__nv_bfloat16*)(smem + 24576);   // [4][2][2688]

    int tid = threadIdx.x;
    int m0 = blockIdx.x * MBM;
    int y = blockIdx.y;

    const __nv_bfloat16 *Ah, *Al, *Bh, *Bl;
    int lda, ldb, n0, nsteps;
    if (y == 0) {
        Ah = Es; Al = Es + (size_t)kT * 304; lda = 304;
        Bh = WE; Bl = WE + (size_t)304 * 160; ldb = 160; n0 = 0; nsteps = 19;
    } else {
        Ah = Ss; Al = Ss + (size_t)kT * kS; lda = kS;
        Bh = Wtok; Bl = Wtok + (size_t)400 * 480; ldb = 480;
        n0 = (y - 1) * 160; nsteps = 25;
    }

    int wid = tid >> 5, lane = tid & 31;
    int warpM = wid & 3, warpN = wid >> 2;
    float Cr[10][4] = {};

    // fixed per-thread A chunk
    int a_sp = tid >> 7, a_tt = tid & 127, a_r = a_tt >> 1, a_half = a_tt & 1;
    int a_row = min(m0 + a_r, kT - 1);
    const __nv_bfloat16* a_base = (a_sp ? Al : Ah) + (size_t)a_row * lda + a_half * 8;
    unsigned a_dst0 = sm_u32(&As[a_sp * 1536 + a_r * 24 + a_half * 8]);

    auto stage = [&](int ks, int buf) {
        int k0 = ks * 16;
        CP_ASYNC16(a_dst0 + buf * 6144, a_base + k0);
        #pragma unroll 3
        for (int c = tid; c < 640; c += 256) {
            int sp = c / 320, cc = c % 320, row = cc / 20, offc = cc % 20;
            const __nv_bfloat16* src =
                (sp ? Bl : Bh) + (size_t)(k0 + row) * ldb + n0 + offc * 8;
            unsigned dst = sm_u32(&Bs[(buf * 2 + sp) * 2688 + row * 168 + offc * 8]);
            CP_ASYNC16(dst, src);
        }
    };

    #pragma unroll
    for (int s = 0; s < GSTG - 1; s++) { stage(s, s); CP_COMMIT(); }

    for (int ks = 0; ks < nsteps; ks++) {
        int buf = ks & 3;
        CP_WAIT(GSTG - 2);
        __syncthreads();
        if (ks + GSTG - 1 < nsteps) stage(ks + GSTG - 1, (ks + GSTG - 1) & 3);
        CP_COMMIT();

        unsigned a[2][4];
        #pragma unroll
        for (int sp = 0; sp < 2; sp++) {
            unsigned addr = sm_u32(
                &As[buf * 3072 + sp * 1536 +
                    (warpM * 16 + (lane & 15)) * 24 + (lane >> 4) * 8]);
            asm volatile(
                "ldmatrix.sync.aligned.m8n8.x4.shared.b16 {%0,%1,%2,%3}, [%4];"
                : "=r"(a[sp][0]), "=r"(a[sp][1]), "=r"(a[sp][2]), "=r"(a[sp][3])
                : "r"(addr));
        }
        #pragma unroll
        for (int np = 0; np < 5; np++) {
            int nbase = warpN * 80 + np * 16;
            unsigned bh[4], bl[4];
            {
                unsigned addr = sm_u32(
                    &Bs[(buf * 2 + 0) * 2688 + (lane & 15) * 168 + nbase +
                        (lane >> 4) * 8]);
                asm volatile(
                    "ldmatrix.sync.aligned.m8n8.x4.trans.shared.b16 {%0,%1,%2,%3}, [%4];"
                    : "=r"(bh[0]), "=r"(bh[1]), "=r"(bh[2]), "=r"(bh[3])
                    : "r"(addr));
            }
            {
                unsigned addr = sm_u32(
                    &Bs[(buf * 2 + 1) * 2688 + (lane & 15) * 168 + nbase +
                        (lane >> 4) * 8]);
                asm volatile(
                    "ldmatrix.sync.aligned.m8n8.x4.trans.shared.b16 {%0,%1,%2,%3}, [%4];"
                    : "=r"(bl[0]), "=r"(bl[1]), "=r"(bl[2]), "=r"(bl[3])
                    : "r"(addr));
            }
            float* c0 = Cr[2 * np];
            float* c1 = Cr[2 * np + 1];
            MMA6(c0, c1, a[0], a[1], bh, bl);
        }
    }

    // epilogue
    int tq = lane & 3, g = lane >> 2;
    int mr0 = m0 + warpM * 16 + g;
    #pragma unroll
    for (int nf = 0; nf < 10; nf++) {
        int nloc = warpN * 80 + nf * 8 + tq * 2;
        float* c = Cr[nf];
        if (nloc >= 150) {
            if (y == 1) {   // zero Has/Hal pad cols
                __nv_bfloat16 z = __float2bfloat16(0.f);
                if (mr0 < kT) {
                    Has[(size_t)mr0 * H1P + nloc] = z;  Hal[(size_t)mr0 * H1P + nloc] = z;
                    Has[(size_t)mr0 * H1P + nloc + 1] = z; Hal[(size_t)mr0 * H1P + nloc + 1] = z;
                }
                if (mr0 + 8 < kT) {
                    Has[(size_t)(mr0 + 8) * H1P + nloc] = z;  Hal[(size_t)(mr0 + 8) * H1P + nloc] = z;
                    Has[(size_t)(mr0 + 8) * H1P + nloc + 1] = z; Hal[(size_t)(mr0 + 8) * H1P + nloc + 1] = z;
                }
            }
            continue;
        }
        float bb0 = 0.f, bb1 = 0.f;
        if (y == 1) { bb0 = ab1[nloc]; bb1 = ab1[nloc + 1]; }
        if (y == 2) { bb0 = sb1[nloc]; bb1 = sb1[nloc + 1]; }
        float v0 = c[0] + bb0, v1 = c[1] + bb1;
        float v2 = c[2] + bb0, v3 = c[3] + bb1;
        if (y == 1) {
            v0 = fmaxf(v0, 0.f); v1 = fmaxf(v1, 0.f);
            v2 = fmaxf(v2, 0.f); v3 = fmaxf(v3, 0.f);
            float vv[4] = {v0, v1, v2, v3};
            #pragma unroll
            for (int q = 0; q < 4; q++) {
                int m = (q < 2) ? mr0 : mr0 + 8;
                if (m >= kT) continue;
                int n = nloc + (q & 1);
                __nv_bfloat16 hi = __float2bfloat16_rn(vv[q]);
                __nv_bfloat16 lo = __float2bfloat16_rn(vv[q] - __bfloat162float(hi));
                Has[(size_t)m * H1P + n] = hi;
                Hal[(size_t)m * H1P + n] = lo;
            }
        } else if (y == 0) {
            if (mr0 < kT) {
                Eout[(size_t)mr0 * kH + nloc] = v0;
                Eout[(size_t)mr0 * kH + nloc + 1] = v1;
            }
            if (mr0 + 8 < kT) {
                Eout[(size_t)(mr0 + 8) * kH + nloc] = v2;
                Eout[(size_t)(mr0 + 8) * kH + nloc + 1] = v3;
            }
        } else {
            int n = (y == 2 ? 150 : 300) + nloc;
            if (mr0 < kT) {
                tok[(size_t)mr0 * TOKW + n] = v0;
                tok[(size_t)mr0 * TOKW + n + 1] = v1;
            }
            if (mr0 + 8 < kT) {
                tok[(size_t)(mr0 + 8) * TOKW + n] = v2;
                tok[(size_t)(mr0 + 8) * TOKW + n + 1] = v3;
            }
        }
    }
}

// ---------------------------------------------------------------------------
// score_mma: attention tail. attn[t] = sum_col relu(Ha·Wa2 + ab2)·aW3 + ab3.
// ---------------------------------------------------------------------------
#define SCBM 64

__global__ __launch_bounds__(256, 2) void score_mma(
    const __nv_bfloat16* __restrict__ H1h, const __nv_bfloat16* __restrict__ H1l,
    const __nv_bfloat16* __restrict__ W2s,
    const float* __restrict__ b2p, const float* __restrict__ w3p,
    const float* __restrict__ b3,
    float* __restrict__ out, int M)
{
    __shared__ __align__(16) __nv_bfloat16 As[2][2][SCBM * 24];
    __shared__ __align__(16) __nv_bfloat16 Bs[2][2][16 * 168];
    __shared__ float red[SCBM][2];

    int tid = threadIdx.x;
    int m0 = blockIdx.x * SCBM;
    int wid = tid >> 5, lane = tid & 31;
    int warpM = wid & 3, warpN = wid >> 2;

    float C[10][4] = {};

    auto stage = [&](int ks, int buf) {
        int k0 = ks * 16;
        {
            int sp = tid >> 7, tt = tid & 127, r = tt >> 1, half = tt & 1;
            int mrow = min(m0 + r, M - 1);
            const __nv_bfloat16* src =
                (sp ? H1l : H1h) + (size_t)mrow * H1P + k0 + half * 8;
            *(int4*)&As[buf][sp][r * 24 + half * 8] = *(const int4*)src;
        }
        for (int c = tid; c < 640; c += 256) {
            int sp = c / 320, cc = c % 320, row = cc / 20, offc = cc % 20;
            const __nv_bfloat16* src =
                W2s + (size_t)sp * H1P * H1P + (size_t)(k0 + row) * H1P + offc * 8;
            *(int4*)&Bs[buf][sp][row * 168 + offc * 8] = *(const int4*)src;
        }
    };

    stage(0, 0);
    __syncthreads();

    for (int ks = 0; ks < 10; ks++) {
        int buf = ks & 1;
        if (ks < 9) stage(ks + 1, buf ^ 1);

        unsigned a[2][4];
        #pragma unroll
        for (int sp = 0; sp < 2; sp++) {
            unsigned addr = sm_u32(
                &As[buf][sp][(warpM * 16 + (lane & 15)) * 24 + (lane >> 4) * 8]);
            asm volatile(
                "ldmatrix.sync.aligned.m8n8.x4.shared.b16 {%0,%1,%2,%3}, [%4];"
                : "=r"(a[sp][0]), "=r"(a[sp][1]), "=r"(a[sp][2]), "=r"(a[sp][3])
                : "r"(addr));
        }
        #pragma unroll
        for (int np = 0; np < 5; np++) {
            int nbase = warpN * 80 + np * 16;
            unsigned bh[4], bl[4];
            {
                unsigned addr = sm_u32(
                    &Bs[buf][0][(lane & 15) * 168 + nbase + (lane >> 4) * 8]);
                asm volatile(
                    "ldmatrix.sync.aligned.m8n8.x4.trans.shared.b16 {%0,%1,%2,%3}, [%4];"
                    : "=r"(bh[0]), "=r"(bh[1]), "=r"(bh[2]), "=r"(bh[3])
                    : "r"(addr));
            }
            {
                unsigned addr = sm_u32(
                    &Bs[buf][1][(lane & 15) * 168 + nbase + (lane >> 4) * 8]);
                asm volatile(
                    "ldmatrix.sync.aligned.m8n8.x4.trans.shared.b16 {%0,%1,%2,%3}, [%4];"
                    : "=r"(bl[0]), "=r"(bl[1]), "=r"(bl[2]), "=r"(bl[3])
                    : "r"(addr));
            }
            float* c0 = C[2 * np];
            float* c1 = C[2 * np + 1];
            MMA6(c0, c1, a[0], a[1], bh, bl);
        }
        __syncthreads();
    }

    int tq = lane & 3, g = lane >> 2;
    float v0 = 0.f, v1 = 0.f;
    #pragma unroll
    for (int nf = 0; nf < 10; nf++) {
        int col = warpN * 80 + nf * 8 + tq * 2;
        float bb0 = __ldg(&b2p[col]), bb1 = __ldg(&b2p[col + 1]);
        float ww0 = __ldg(&w3p[col]), ww1 = __ldg(&w3p[col + 1]);
        float* c = C[nf];
        v0 = fmaf(fmaxf(c[0] + bb0, 0.f), ww0, v0);
        v0 = fmaf(fmaxf(c[1] + bb1, 0.f), ww1, v0);
        v1 = fmaf(fmaxf(c[2] + bb0, 0.f), ww0, v1);
        v1 = fmaf(fmaxf(c[3] + bb1, 0.f), ww1, v1);
    }
    v0 += __shfl_xor_sync(0xffffffffu, v0, 1);
    v0 += __shfl_xor_sync(0xffffffffu, v0, 2);
    v1 += __shfl_xor_sync(0xffffffffu, v1, 1);
    v1 += __shfl_xor_sync(0xffffffffu, v1, 2);
    if (tq == 0) {
        red[warpM * 16 + g][warpN] = v0;
        red[warpM * 16 + g + 8][warpN] = v1;
    }
    __syncthreads();
    if (tid < SCBM) {
        int m = m0 + tid;
        if (m < M) out[m] = red[tid][0] + red[tid][1] + b3[0];
    }
}

// ---------------------------------------------------------------------------
// Fused span kernel: 64 same-width spans per block.
// Phase 1: softmax pool + h1 into smem (split-bf16 ldmatrix layout).
// Phase 2: 10-step MMA vs W2 with cp.async 4-stage B ring + fused epilogue.
// Dynamic smem: As_all 61440 | Bs 43008 | red 512 = 104960 B (2 blocks/SM).
// ---------------------------------------------------------------------------
#define AS_SP 15360   // bf16 elems per split plane: 10*64*24
#define BS_OFF 61440
#define RED_OFF 104448

__global__ __launch_bounds__(256, 2) void fused_span(
    const float* __restrict__ attn,
    const float* __restrict__ tok,
    const float* __restrict__ E,
    const __nv_bfloat16* __restrict__ W2s,
    const float* __restrict__ b2p, const float* __restrict__ w3p,
    const float* __restrict__ b3,
    float* __restrict__ out)
{
    extern __shared__ __align__(16) char smem[];
    __nv_bfloat16* As_all = (__nv_bfloat16*)smem;
    __nv_bfloat16* Bs = (__nv_bfloat16*)(smem + BS_OFF);   // [4][2][2688]
    float* red = (float*)(smem + RED_OFF);                 // [64][2]

    int tid = threadIdx.x;
    int wid = tid >> 5, lane = tid & 31;
    int n = blockIdx.y + 1;
    int S = kT - n + 1;
    int base = blockIdx.x * 64;
    int off = (n - 1) * (kT + 1) - (n * (n - 1)) / 2;

    auto stageB = [&](int ks, int buf) {
        int k0 = ks * 16;
        for (int c = tid; c < 640; c += 256) {
            int sp = c / 320, cc = c % 320, row = cc / 20, offc = cc % 20;
            const __nv_bfloat16* src =
                W2s + (size_t)sp * (H1P * H1P) + (size_t)(k0 + row) * H1P + offc * 8;
            unsigned dst = sm_u32(&Bs[(buf * 2 + sp) * 2688 + row * 168 + offc * 8]);
            CP_ASYNC16(dst, src);
        }
    };
    #pragma unroll
    for (int s = 0; s < GSTG - 1; s++) { stageB(s, s); CP_COMMIT(); }

    // ---- phase 1: build split-bf16 h1 tile (warp = 8 spans, lanes = cols) ----
    for (int i = 0; i < 8; i++) {
        int sl = wid * 8 + i;
        int s = base + sl;
        bool valid = s < S;
        float acc[5];
        if (valid) {
            int e = s + n - 1;
            float av = (lane < n) ? attn[s + lane] : -1e30f;
            float mx = av;
            #pragma unroll
            for (int o = 16; o > 0; o >>= 1)
                mx = fmaxf(mx, __shfl_xor_sync(0xffffffffu, mx, o));
            float ev = (lane < n) ? __expf(av - mx) : 0.f;
            float sum = ev;
            #pragma unroll
            for (int o = 16; o > 0; o >>= 1)
                sum += __shfl_xor_sync(0xffffffffu, sum, o);
            float wv = ev / sum;
            #pragma unroll
            for (int ch = 0; ch < 5; ch++) {
                int c = ch * 32 + lane;
                acc[ch] = (c < 150)
                    ? tok[(size_t)s * TOKW + 150 + c] + tok[(size_t)e * TOKW + 300 + c]
                    : 0.f;
            }
            for (int j = 0; j < n; j++) {
                float wj = __shfl_sync(0xffffffffu, wv, j);
                const float* Er = E + (size_t)(s + j) * kH;
                #pragma unroll
                for (int ch = 0; ch < 5; ch++) {
                    int c = ch * 32 + lane;
                    if (c < 150) acc[ch] = fmaf(wj, Er[c], acc[ch]);
                }
            }
        } else {
            #pragma unroll
            for (int ch = 0; ch < 5; ch++) acc[ch] = 0.f;
        }
        #pragma unroll
        for (int ch = 0; ch < 5; ch++) {
            int c = ch * 32 + lane;
            float v = (c < 150 && valid) ? fmaxf(acc[ch], 0.f) : 0.f;
            __nv_bfloat16 hi = __float2bfloat16_rn(v);
            __nv_bfloat16 lo = __float2bfloat16_rn(v - __bfloat162float(hi));
            int idx = (c >> 4) * 1536 + sl * 24 + ((c >> 3) & 1) * 8 + (c & 7);
            As_all[idx] = hi;
            As_all[AS_SP + idx] = lo;
        }
    }

    // ---- phase 2: MMA vs W2 ----
    int warpM = wid & 3, warpN = wid >> 2;
    float C[10][4] = {};

    for (int ks = 0; ks < 10; ks++) {
        int buf = ks & 3;
        CP_WAIT(GSTG - 2);
        __syncthreads();
        if (ks + GSTG - 1 < 10) stageB(ks + GSTG - 1, (ks + GSTG - 1) & 3);
        CP_COMMIT();

        unsigned a[2][4];
        #pragma unroll
        for (int sp = 0; sp < 2; sp++) {
            unsigned addr = sm_u32(
                &As_all[sp * AS_SP + ks * 1536 +
                        (warpM * 16 + (lane & 15)) * 24 + (lane >> 4) * 8]);
            asm volatile(
                "ldmatrix.sync.aligned.m8n8.x4.shared.b16 {%0,%1,%2,%3}, [%4];"
                : "=r"(a[sp][0]), "=r"(a[sp][1]), "=r"(a[sp][2]), "=r"(a[sp][3])
                : "r"(addr));
        }
        #pragma unroll
        for (int np = 0; np < 5; np++) {
            int nbase = warpN * 80 + np * 16;
            unsigned bh[4], bl[4];
            {
                unsigned addr = sm_u32(
                    &Bs[(buf * 2 + 0) * 2688 + (lane & 15) * 168 + nbase +
                        (lane >> 4) * 8]);
                asm volatile(
                    "ldmatrix.sync.aligned.m8n8.x4.trans.shared.b16 {%0,%1,%2,%3}, [%4];"
                    : "=r"(bh[0]), "=r"(bh[1]), "=r"(bh[2]), "=r"(bh[3])
                    : "r"(addr));
            }
            {
                unsigned addr = sm_u32(
                    &Bs[(buf * 2 + 1) * 2688 + (lane & 15) * 168 + nbase +
                        (lane >> 4) * 8]);
                asm volatile(
                    "ldmatrix.sync.aligned.m8n8.x4.trans.shared.b16 {%0,%1,%2,%3}, [%4];"
                    : "=r"(bl[0]), "=r"(bl[1]), "=r"(bl[2]), "=r"(bl[3])
                    : "r"(addr));
            }
            float* c0 = C[2 * np];
            float* c1 = C[2 * np + 1];
            MMA6(c0, c1, a[0], a[1], bh, bl);
        }
    }

    // ---- fused epilogue ----
    int tq = lane & 3, g = lane >> 2;
    float v0 = 0.f, v1 = 0.f;
    #pragma unroll
    for (int nf = 0; nf < 10; nf++) {
        int col = warpN * 80 + nf * 8 + tq * 2;
        float bb0 = __ldg(&b2p[col]), bb1 = __ldg(&b2p[col + 1]);
        float ww0 = __ldg(&w3p[col]), ww1 = __ldg(&w3p[col + 1]);
        float* c = C[nf];
        v0 = fmaf(fmaxf(c[0] + bb0, 0.f), ww0, v0);
        v0 = fmaf(fmaxf(c[1] + bb1, 0.f), ww1, v0);
        v1 = fmaf(fmaxf(c[2] + bb0, 0.f), ww0, v1);
        v1 = fmaf(fmaxf(c[3] + bb1, 0.f), ww1, v1);
    }
    v0 += __shfl_xor_sync(0xffffffffu, v0, 1);
    v0 += __shfl_xor_sync(0xffffffffu, v0, 2);
    v1 += __shfl_xor_sync(0xffffffffu, v1, 1);
    v1 += __shfl_xor_sync(0xffffffffu, v1, 2);
    if (tq == 0) {
        red[(warpM * 16 + g) * 2 + warpN] = v0;
        red[(warpM * 16 + g + 8) * 2 + warpN] = v1;
    }
    __syncthreads();
    if (tid < 64) {
        int m = base + tid;
        if (m < S) out[off + m] = red[tid * 2] + red[tid * 2 + 1] + b3[0];
    }
}

// ---------------------------------------------------------------------------
extern "C" void kernel_launch(void* const* d_in, const int* in_sizes, int n_in,
                              void* d_out, int out_size)
{
    const float* embeds = (const float*)d_in[0];
    const float* states = (const float*)d_in[1];
    const float* aW1 = (const float*)d_in[2];
    const float* ab1 = (const float*)d_in[3];
    const float* aW2 = (const float*)d_in[4];
    const float* ab2 = (const float*)d_in[5];
    const float* aW3 = (const float*)d_in[6];
    const float* ab3 = (const float*)d_in[7];
    const float* sW1 = (const float*)d_in[8];
    const float* sb1 = (const float*)d_in[9];
    const float* sW2 = (const float*)d_in[10];
    const float* sb2 = (const float*)d_in[11];
    const float* sW3 = (const float*)d_in[12];
    const float* sb3 = (const float*)d_in[13];
    float* out = (float*)d_out;

    float *tok, *E, *attn, *ab2p, *aw3p, *sb2p, *sw3p;
    __nv_bfloat16 *Ss, *Es, *Has, *Hal, *Wtok, *WE, *Wa2, *W2s;
    cudaGetSymbolAddress((void**)&tok, g_tok);
    cudaGetSymbolAddress((void**)&E, g_E);
    cudaGetSymbolAddress((void**)&attn, g_attn);
    cudaGetSymbolAddress((void**)&Ss, g_Ss);
    cudaGetSymbolAddress((void**)&Es, g_Es);
    cudaGetSymbolAddress((void**)&Has, g_Has);
    cudaGetSymbolAddress((void**)&Hal, g_Hal);
    cudaGetSymbolAddress((void**)&Wtok, g_Wtok);
    cudaGetSymbolAddress((void**)&WE, g_WE);
    cudaGetSymbolAddress((void**)&Wa2, g_Wa2);
    cudaGetSymbolAddress((void**)&W2s, g_W2s);
    cudaGetSymbolAddress((void**)&ab2p, g_ab2p);
    cudaGetSymbolAddress((void**)&aw3p, g_aw3p);
    cudaGetSymbolAddress((void**)&sb2p, g_sb2p);
    cudaGetSymbolAddress((void**)&sw3p, g_sw3p);

    cudaFuncSetAttribute(tokE_gemm,
                         cudaFuncAttributeMaxDynamicSharedMemorySize, 67584);
    cudaFuncSetAttribute(fused_span,
                         cudaFuncAttributeMaxDynamicSharedMemorySize, 104960);

    // 1. all weight prep
    {
        int total = 3 * 400 * 160 + 304 * 160 + 2 * 160 * 160 + H1P;
        prep_all<<<(total + 255) / 256, 256>>>(aW1, sW1, aW2, sW2, ab2, aW3,
                                               sb2, sW3, Wtok, WE, Wa2, W2s,
                                               ab2p, aw3p, sb2p, sw3p);
    }
    // 2-3. activation splits
    conv_split<<<(kT * 100 + 255) / 256, 256>>>(states, kT, kS, kS,
                                                Ss, Ss + (size_t)kT * kS);
    conv_split<<<(kT * 75 + 255) / 256, 256>>>(embeds, kT, kE, 304,
                                               Es, Es + (size_t)kT * 304);

    int mt = (kT + MBM - 1) / MBM;  // 313

    // 4. combined E + tok GEMM (y: 0=E, 1=Ha, 2=A, 3=B)
    tokE_gemm<<<dim3(mt, 4), 256, 67584>>>(Ss, Es, Wtok, WE, ab1, sb1,
                                           tok, E, Has, Hal);
    // 5. attention tail
    score_mma<<<(kT + SCBM - 1) / SCBM, 256>>>(Has, Hal, Wa2, ab2p, aw3p,
                                               ab3, attn, kT);
    // 6. fused span scoring
    fused_span<<<dim3(313, 10), 256, 104960>>>(attn, tok, E, W2s, sb2p, sw3p,
                                               sb3, out);
}

// round 12
// speedup vs baseline: 3.1582x; 1.1259x over previous
#include <cuda_runtime.h>
#include <cuda_bf16.h>

#define kT 20000
#define kE 300
#define kS 400
#define kH 150
#define NSPANS (10 * kT - 45)
#define TOKW 452    // padded f32 row: 150:300 A, 300:450 B
#define H1P 160
#define SKP 416     // states K padded (13*32)
#define EKP 320     // embeds K padded (10*32)

typedef unsigned long long ull;

// Scratch (allocation-free rule: __device__ globals; zero-initialized — pad
// regions are never written and stay zero)
__device__ float g_tok[(size_t)kT * TOKW];
__device__ float g_E[(size_t)kT * kH];
__device__ float g_attn[kT];
__device__ __nv_bfloat16 g_Ss[2 * (size_t)kT * SKP];
__device__ __nv_bfloat16 g_Es[2 * (size_t)kT * EKP];
__device__ __nv_bfloat16 g_Has[(size_t)kT * H1P];
__device__ __nv_bfloat16 g_Hal[(size_t)kT * H1P];
__device__ __nv_bfloat16 g_Wtok[2 * SKP * 480];
__device__ __nv_bfloat16 g_WE[2 * EKP * 160];
__device__ __nv_bfloat16 g_Wa2[2 * 160 * 160];
__device__ __nv_bfloat16 g_W2s[2 * 160 * 160];
__device__ float g_ab2p[H1P];
__device__ float g_aw3p[H1P];
__device__ float g_sb2p[H1P];
__device__ float g_sw3p[H1P];

static __device__ __forceinline__ unsigned sm_u32(const void* p) {
    return (unsigned)__cvta_generic_to_shared(p);
}
static __device__ __forceinline__ unsigned pack_bf2(__nv_bfloat16 a, __nv_bfloat16 b) {
    unsigned r;
    unsigned short ua = *(unsigned short*)&a, ub = *(unsigned short*)&b;
    asm("mov.b32 %0, {%1, %2};" : "=r"(r) : "h"(ua), "h"(ub));
    return r;
}

#define CP_ASYNC16(dst, src) \
    asm volatile("cp.async.cg.shared.global [%0], [%1], 16;" \
                 :: "r"(dst), "l"(src))
#define CP_COMMIT() asm volatile("cp.async.commit_group;" ::: "memory")
#define CP_WAIT(n)  asm volatile("cp.async.wait_group %0;" :: "n"(n) : "memory")

#define MMA6(c0, c1, A0, A1, BH, BL)                                          \
    asm volatile("mma.sync.aligned.m16n8k16.row.col.f32.bf16.bf16.f32 "       \
                 "{%0,%1,%2,%3},{%4,%5,%6,%7},{%8,%9},{%0,%1,%2,%3};"         \
                 : "+f"(c0[0]), "+f"(c0[1]), "+f"(c0[2]), "+f"(c0[3])         \
                 : "r"(A0[0]), "r"(A0[1]), "r"(A0[2]), "r"(A0[3]),            \
                   "r"(BH[0]), "r"(BH[1]));                                   \
    asm volatile("mma.sync.aligned.m16n8k16.row.col.f32.bf16.bf16.f32 "       \
                 "{%0,%1,%2,%3},{%4,%5,%6,%7},{%8,%9},{%0,%1,%2,%3};"         \
                 : "+f"(c1[0]), "+f"(c1[1]), "+f"(c1[2]), "+f"(c1[3])         \
                 : "r"(A0[0]), "r"(A0[1]), "r"(A0[2]), "r"(A0[3]),            \
                   "r"(BH[2]), "r"(BH[3]));                                   \
    asm volatile("mma.sync.aligned.m16n8k16.row.col.f32.bf16.bf16.f32 "       \
                 "{%0,%1,%2,%3},{%4,%5,%6,%7},{%8,%9},{%0,%1,%2,%3};"         \
                 : "+f"(c0[0]), "+f"(c0[1]), "+f"(c0[2]), "+f"(c0[3])         \
                 : "r"(A1[0]), "r"(A1[1]), "r"(A1[2]), "r"(A1[3]),            \
                   "r"(BH[0]), "r"(BH[1]));                                   \
    asm volatile("mma.sync.aligned.m16n8k16.row.col.f32.bf16.bf16.f32 "       \
                 "{%0,%1,%2,%3},{%4,%5,%6,%7},{%8,%9},{%0,%1,%2,%3};"         \
                 : "+f"(c1[0]), "+f"(c1[1]), "+f"(c1[2]), "+f"(c1[3])         \
                 : "r"(A1[0]), "r"(A1[1]), "r"(A1[2]), "r"(A1[3]),            \
                   "r"(BH[2]), "r"(BH[3]));                                   \
    asm volatile("mma.sync.aligned.m16n8k16.row.col.f32.bf16.bf16.f32 "       \
                 "{%0,%1,%2,%3},{%4,%5,%6,%7},{%8,%9},{%0,%1,%2,%3};"         \
                 : "+f"(c0[0]), "+f"(c0[1]), "+f"(c0[2]), "+f"(c0[3])         \
                 : "r"(A0[0]), "r"(A0[1]), "r"(A0[2]), "r"(A0[3]),            \
                   "r"(BL[0]), "r"(BL[1]));                                   \
    asm volatile("mma.sync.aligned.m16n8k16.row.col.f32.bf16.bf16.f32 "       \
                 "{%0,%1,%2,%3},{%4,%5,%6,%7},{%8,%9},{%0,%1,%2,%3};"         \
                 : "+f"(c1[0]), "+f"(c1[1]), "+f"(c1[2]), "+f"(c1[3])         \
                 : "r"(A0[0]), "r"(A0[1]), "r"(A0[2]), "r"(A0[3]),            \
                   "r"(BL[2]), "r"(BL[3]));

// ---------------------------------------------------------------------------
// One-shot prep: all weight splits + padded vectors.
// ---------------------------------------------------------------------------
static __device__ __forceinline__ void wsplit(
    float w, __nv_bfloat16* dh, __nv_bfloat16* dl, size_t idx)
{
    __nv_bfloat16 hi = __float2bfloat16_rn(w);
    dh[idx] = hi;
    dl[idx] = __float2bfloat16_rn(w - __bfloat162float(hi));
}

__global__ void prep_all(
    const float* __restrict__ aW1, const float* __restrict__ sW1,
    const float* __restrict__ aW2, const float* __restrict__ sW2,
    const float* __restrict__ ab2, const float* __restrict__ aW3,
    const float* __restrict__ sb2, const float* __restrict__ sW3,
    __nv_bfloat16* __restrict__ Wtok, __nv_bfloat16* __restrict__ WE,
    __nv_bfloat16* __restrict__ Wa2, __nv_bfloat16* __restrict__ W2s,
    float* __restrict__ ab2p, float* __restrict__ aw3p,
    float* __restrict__ sb2p, float* __restrict__ sw3p)
{
    const int NT = 400 * 160, NE = 304 * 160, N2 = 160 * 160;
    int i = blockIdx.x * blockDim.x + threadIdx.x;
    if (i < 3 * NT) {
        int t = i / NT, r = i - t * NT;
        int k = r / 160, c = r - k * 160;
        const float* src = (t == 0) ? aW1 : ((t == 1) ? sW1 : sW1 + 400 * 150);
        float w = (c < 150) ? src[(size_t)k * 150 + c] : 0.f;
        wsplit(w, Wtok, Wtok + (size_t)SKP * 480, (size_t)k * 480 + t * 160 + c);
        return;
    }
    i -= 3 * NT;
    if (i < NE) {
        int k = i / 160, c = i - k * 160;
        float w = (k < 300 && c < 150) ? sW1[(size_t)(800 + k) * 150 + c] : 0.f;
        wsplit(w, WE, WE + (size_t)EKP * 160, i);
        return;
    }
    i -= NE;
    if (i < N2) {
        int k = i / 160, c = i - k * 160;
        float w = (k < 150 && c < 150) ? aW2[(size_t)k * 150 + c] : 0.f;
        wsplit(w, Wa2, Wa2 + N2, i);
        return;
    }
    i -= N2;
    if (i < N2) {
        int k = i / 160, c = i - k * 160;
        float w = (k < 150 && c < 150) ? sW2[(size_t)k * 150 + c] : 0.f;
        wsplit(w, W2s, W2s + N2, i);
        return;
    }
    i -= N2;
    if (i < H1P) {
        ab2p[i] = (i < 150) ? ab2[i] : 0.f;
        aw3p[i] = (i < 150) ? aW3[i] : 0.f;
        sb2p[i] = (i < 150) ? sb2[i] : 0.f;
        sw3p[i] = (i < 150) ? sW3[i] : 0.f;
    }
}

// ---------------------------------------------------------------------------
// Split activation matrix f32 [M x K] -> bf16 hi/lo [M x ldd]
// ---------------------------------------------------------------------------
__global__ void conv_split(const float* __restrict__ src, int M, int K, int ldd,
                           __nv_bfloat16* __restrict__ dh,
                           __nv_bfloat16* __restrict__ dl)
{
    int i = blockIdx.x * blockDim.x + threadIdx.x;
    int q4 = K >> 2;
    if (i >= M * q4) return;
    int row = i / q4, q = i - row * q4;
    float4 v = *(const float4*)&src[(size_t)row * K + q * 4];
    float* vp = (float*)&v;
    __nv_bfloat16 h[4], l[4];
    #pragma unroll
    for (int j = 0; j < 4; j++) {
        h[j] = __float2bfloat16_rn(vp[j]);
        l[j] = __float2bfloat16_rn(vp[j] - __bfloat162float(h[j]));
    }
    uint2 sh = {pack_bf2(h[0], h[1]), pack_bf2(h[2], h[3])};
    uint2 sl = {pack_bf2(l[0], l[1]), pack_bf2(l[2], l[3])};
    *(uint2*)&dh[(size_t)row * ldd + q * 4] = sh;
    *(uint2*)&dl[(size_t)row * ldd + q * 4] = sl;
}

// ---------------------------------------------------------------------------
// Combined token-level GEMM, cp.async 3-stage ring, K=32 per stage.
// blockIdx.y: 0 -> E (10 K32 steps); 1..3 -> tok segments (13 K32 steps).
// Dynamic smem: As 3*2*2*1536*2 = 36864 | Bs 3*2*2*2688*2 = 64512 => 101376 B
// ---------------------------------------------------------------------------
#define MBM 64

__global__ __launch_bounds__(256, 2) void tokE_gemm(
    const __nv_bfloat16* __restrict__ Ss, const __nv_bfloat16* __restrict__ Es,
    const __nv_bfloat16* __restrict__ Wtok, const __nv_bfloat16* __restrict__ WE,
    const float* __restrict__ ab1, const float* __restrict__ sb1,
    float* __restrict__ tok, float* __restrict__ Eout,
    __nv_bfloat16* __restrict__ Has, __nv_bfloat16* __restrict__ Hal)
{
    extern __shared__ __align__(16) char smem[];
    __nv_bfloat16* As = (__nv_bfloat16*)smem;             // [3][2sub][2sp][1536]
    __nv_bfloat16* Bs = (__nv_bfloat16*)(smem + 36864);   // [3][2sub][2sp][2688]

    int tid = threadIdx.x;
    int m0 = blockIdx.x * MBM;
    int y = blockIdx.y;

    const __nv_bfloat16 *Ah, *Al, *Bh, *Bl;
    int lda, ldb, n0, nsteps2;
    if (y == 0) {
        Ah = Es; Al = Es + (size_t)kT * EKP; lda = EKP;
        Bh = WE; Bl = WE + (size_t)EKP * 160; ldb = 160; n0 = 0; nsteps2 = 10;
    } else {
        Ah = Ss; Al = Ss + (size_t)kT * SKP; lda = SKP;
        Bh = Wtok; Bl = Wtok + (size_t)SKP * 480; ldb = 480;
        n0 = (y - 1) * 160; nsteps2 = 13;
    }

    int wid = tid >> 5, lane = tid & 31;
    int warpM = wid & 3, warpN = wid >> 2;
    float Cr[10][4] = {};

    // fixed per-thread A chunk
    int a_sp = tid >> 7, a_tt = tid & 127, a_r = a_tt >> 1, a_half = a_tt & 1;
    int a_row = min(m0 + a_r, kT - 1);
    const __nv_bfloat16* a_base = (a_sp ? Al : Ah) + (size_t)a_row * lda + a_half * 8;
    unsigned a_smem0 = sm_u32(&As[a_r * 24 + a_half * 8]);

    auto stage32 = [&](int ks2, int st) {
        #pragma unroll
        for (int sub = 0; sub < 2; sub++) {
            int k0 = (ks2 * 2 + sub) * 16;
            CP_ASYNC16(a_smem0 + ((st * 2 + sub) * 2 + a_sp) * 3072, a_base + k0);
        }
        #pragma unroll 5
        for (int c = tid; c < 1280; c += 256) {
            int sub = c / 640, cc = c % 640;
            int sp = cc / 320, c2 = cc % 320, row = c2 / 20, offc = c2 % 20;
            int kk = (ks2 * 2 + sub) * 16 + row;
            const __nv_bfloat16* src =
                (sp ? Bl : Bh) + (size_t)kk * ldb + n0 + offc * 8;
            unsigned dst = sm_u32(
                &Bs[((st * 2 + sub) * 2 + sp) * 2688 + row * 168 + offc * 8]);
            CP_ASYNC16(dst, src);
        }
    };

    stage32(0, 0); CP_COMMIT();
    stage32(1, 1); CP_COMMIT();

    for (int ks2 = 0; ks2 < nsteps2; ks2++) {
        int st = ks2 % 3;
        CP_WAIT(1);
        __syncthreads();
        if (ks2 + 2 < nsteps2) stage32(ks2 + 2, (ks2 + 2) % 3);
        CP_COMMIT();

        #pragma unroll
        for (int sub = 0; sub < 2; sub++) {
            unsigned a[2][4];
            #pragma unroll
            for (int sp = 0; sp < 2; sp++) {
                unsigned addr = sm_u32(
                    &As[((st * 2 + sub) * 2 + sp) * 1536 +
                        (warpM * 16 + (lane & 15)) * 24 + (lane >> 4) * 8]);
                asm volatile(
                    "ldmatrix.sync.aligned.m8n8.x4.shared.b16 {%0,%1,%2,%3}, [%4];"
                    : "=r"(a[sp][0]), "=r"(a[sp][1]), "=r"(a[sp][2]), "=r"(a[sp][3])
                    : "r"(addr));
            }
            #pragma unroll
            for (int np = 0; np < 5; np++) {
                int nbase = warpN * 80 + np * 16;
                unsigned bh[4], bl[4];
                {
                    unsigned addr = sm_u32(
                        &Bs[((st * 2 + sub) * 2 + 0) * 2688 + (lane & 15) * 168 +
                            nbase + (lane >> 4) * 8]);
                    asm volatile(
                        "ldmatrix.sync.aligned.m8n8.x4.trans.shared.b16 {%0,%1,%2,%3}, [%4];"
                        : "=r"(bh[0]), "=r"(bh[1]), "=r"(bh[2]), "=r"(bh[3])
                        : "r"(addr));
                }
                {
                    unsigned addr = sm_u32(
                        &Bs[((st * 2 + sub) * 2 + 1) * 2688 + (lane & 15) * 168 +
                            nbase + (lane >> 4) * 8]);
                    asm volatile(
                        "ldmatrix.sync.aligned.m8n8.x4.trans.shared.b16 {%0,%1,%2,%3}, [%4];"
                        : "=r"(bl[0]), "=r"(bl[1]), "=r"(bl[2]), "=r"(bl[3])
                        : "r"(addr));
                }
                float* c0 = Cr[2 * np];
                float* c1 = Cr[2 * np + 1];
                MMA6(c0, c1, a[0], a[1], bh, bl);
            }
        }
    }

    // epilogue
    int tq = lane & 3, g = lane >> 2;
    int mr0 = m0 + warpM * 16 + g;
    #pragma unroll
    for (int nf = 0; nf < 10; nf++) {
        int nloc = warpN * 80 + nf * 8 + tq * 2;
        float* c = Cr[nf];
        if (nloc >= 150) {
            if (y == 1) {
                __nv_bfloat16 z = __float2bfloat16(0.f);
                if (mr0 < kT) {
                    Has[(size_t)mr0 * H1P + nloc] = z;  Hal[(size_t)mr0 * H1P + nloc] = z;
                    Has[(size_t)mr0 * H1P + nloc + 1] = z; Hal[(size_t)mr0 * H1P + nloc + 1] = z;
                }
                if (mr0 + 8 < kT) {
                    Has[(size_t)(mr0 + 8) * H1P + nloc] = z;  Hal[(size_t)(mr0 + 8) * H1P + nloc] = z;
                    Has[(size_t)(mr0 + 8) * H1P + nloc + 1] = z; Hal[(size_t)(mr0 + 8) * H1P + nloc + 1] = z;
                }
            }
            continue;
        }
        float bb0 = 0.f, bb1 = 0.f;
        if (y == 1) { bb0 = ab1[nloc]; bb1 = ab1[nloc + 1]; }
        if (y == 2) { bb0 = sb1[nloc]; bb1 = sb1[nloc + 1]; }
        float v0 = c[0] + bb0, v1 = c[1] + bb1;
        float v2 = c[2] + bb0, v3 = c[3] + bb1;
        if (y == 1) {
            v0 = fmaxf(v0, 0.f); v1 = fmaxf(v1, 0.f);
            v2 = fmaxf(v2, 0.f); v3 = fmaxf(v3, 0.f);
            float vv[4] = {v0, v1, v2, v3};
            #pragma unroll
            for (int q = 0; q < 4; q++) {
                int m = (q < 2) ? mr0 : mr0 + 8;
                if (m >= kT) continue;
                int n = nloc + (q & 1);
                __nv_bfloat16 hi = __float2bfloat16_rn(vv[q]);
                __nv_bfloat16 lo = __float2bfloat16_rn(vv[q] - __bfloat162float(hi));
                Has[(size_t)m * H1P + n] = hi;
                Hal[(size_t)m * H1P + n] = lo;
            }
        } else if (y == 0) {
            if (mr0 < kT) {
                Eout[(size_t)mr0 * kH + nloc] = v0;
                Eout[(size_t)mr0 * kH + nloc + 1] = v1;
            }
            if (mr0 + 8 < kT) {
                Eout[(size_t)(mr0 + 8) * kH + nloc] = v2;
                Eout[(size_t)(mr0 + 8) * kH + nloc + 1] = v3;
            }
        } else {
            int n = (y == 2 ? 150 : 300) + nloc;
            if (mr0 < kT) {
                tok[(size_t)mr0 * TOKW + n] = v0;
                tok[(size_t)mr0 * TOKW + n + 1] = v1;
            }
            if (mr0 + 8 < kT) {
                tok[(size_t)(mr0 + 8) * TOKW + n] = v2;
                tok[(size_t)(mr0 + 8) * TOKW + n + 1] = v3;
            }
        }
    }
}

// ---------------------------------------------------------------------------
// score_mma: attention tail. attn[t] = sum_col relu(Ha·Wa2 + ab2)·aW3 + ab3.
// ---------------------------------------------------------------------------
#define SCBM 64

__global__ __launch_bounds__(256, 2) void score_mma(
    const __nv_bfloat16* __restrict__ H1h, const __nv_bfloat16* __restrict__ H1l,
    const __nv_bfloat16* __restrict__ W2s,
    const float* __restrict__ b2p, const float* __restrict__ w3p,
    const float* __restrict__ b3,
    float* __restrict__ out, int M)
{
    __shared__ __align__(16) __nv_bfloat16 As[2][2][SCBM * 24];
    __shared__ __align__(16) __nv_bfloat16 Bs[2][2][16 * 168];
    __shared__ float red[SCBM][2];

    int tid = threadIdx.x;
    int m0 = blockIdx.x * SCBM;
    int wid = tid >> 5, lane = tid & 31;
    int warpM = wid & 3, warpN = wid >> 2;

    float C[10][4] = {};

    auto stage = [&](int ks, int buf) {
        int k0 = ks * 16;
        {
            int sp = tid >> 7, tt = tid & 127, r = tt >> 1, half = tt & 1;
            int mrow = min(m0 + r, M - 1);
            const __nv_bfloat16* src =
                (sp ? H1l : H1h) + (size_t)mrow * H1P + k0 + half * 8;
            *(int4*)&As[buf][sp][r * 24 + half * 8] = *(const int4*)src;
        }
        for (int c = tid; c < 640; c += 256) {
            int sp = c / 320, cc = c % 320, row = cc / 20, offc = cc % 20;
            const __nv_bfloat16* src =
                W2s + (size_t)sp * H1P * H1P + (size_t)(k0 + row) * H1P + offc * 8;
            *(int4*)&Bs[buf][sp][row * 168 + offc * 8] = *(const int4*)src;
        }
    };

    stage(0, 0);
    __syncthreads();

    for (int ks = 0; ks < 10; ks++) {
        int buf = ks & 1;
        if (ks < 9) stage(ks + 1, buf ^ 1);

        unsigned a[2][4];
        #pragma unroll
        for (int sp = 0; sp < 2; sp++) {
            unsigned addr = sm_u32(
                &As[buf][sp][(warpM * 16 + (lane & 15)) * 24 + (lane >> 4) * 8]);
            asm volatile(
                "ldmatrix.sync.aligned.m8n8.x4.shared.b16 {%0,%1,%2,%3}, [%4];"
                : "=r"(a[sp][0]), "=r"(a[sp][1]), "=r"(a[sp][2]), "=r"(a[sp][3])
                : "r"(addr));
        }
        #pragma unroll
        for (int np = 0; np < 5; np++) {
            int nbase = warpN * 80 + np * 16;
            unsigned bh[4], bl[4];
            {
                unsigned addr = sm_u32(
                    &Bs[buf][0][(lane & 15) * 168 + nbase + (lane >> 4) * 8]);
                asm volatile(
                    "ldmatrix.sync.aligned.m8n8.x4.trans.shared.b16 {%0,%1,%2,%3}, [%4];"
                    : "=r"(bh[0]), "=r"(bh[1]), "=r"(bh[2]), "=r"(bh[3])
                    : "r"(addr));
            }
            {
                unsigned addr = sm_u32(
                    &Bs[buf][1][(lane & 15) * 168 + nbase + (lane >> 4) * 8]);
                asm volatile(
                    "ldmatrix.sync.aligned.m8n8.x4.trans.shared.b16 {%0,%1,%2,%3}, [%4];"
                    : "=r"(bl[0]), "=r"(bl[1]), "=r"(bl[2]), "=r"(bl[3])
                    : "r"(addr));
            }
            float* c0 = C[2 * np];
            float* c1 = C[2 * np + 1];
            MMA6(c0, c1, a[0], a[1], bh, bl);
        }
        __syncthreads();
    }

    int tq = lane & 3, g = lane >> 2;
    float v0 = 0.f, v1 = 0.f;
    #pragma unroll
    for (int nf = 0; nf < 10; nf++) {
        int col = warpN * 80 + nf * 8 + tq * 2;
        float bb0 = __ldg(&b2p[col]), bb1 = __ldg(&b2p[col + 1]);
        float ww0 = __ldg(&w3p[col]), ww1 = __ldg(&w3p[col + 1]);
        float* c = C[nf];
        v0 = fmaf(fmaxf(c[0] + bb0, 0.f), ww0, v0);
        v0 = fmaf(fmaxf(c[1] + bb1, 0.f), ww1, v0);
        v1 = fmaf(fmaxf(c[2] + bb0, 0.f), ww0, v1);
        v1 = fmaf(fmaxf(c[3] + bb1, 0.f), ww1, v1);
    }
    v0 += __shfl_xor_sync(0xffffffffu, v0, 1);
    v0 += __shfl_xor_sync(0xffffffffu, v0, 2);
    v1 += __shfl_xor_sync(0xffffffffu, v1, 1);
    v1 += __shfl_xor_sync(0xffffffffu, v1, 2);
    if (tq == 0) {
        red[warpM * 16 + g][warpN] = v0;
        red[warpM * 16 + g + 8][warpN] = v1;
    }
    __syncthreads();
    if (tid < SCBM) {
        int m = m0 + tid;
        if (m < M) out[m] = red[tid][0] + red[tid][1] + b3[0];
    }
}

// ---------------------------------------------------------------------------
// Fused span kernel: 64 same-width spans per block.
// Phase 1 (v2): warp-shared E-row pooling — 8 span accumulators in registers,
//   softmax weights in warp-private smem, each E row loaded once per warp.
// Phase 2: 10-step MMA vs W2, cp.async 4-stage B ring, fused epilogue.
// Dynamic smem: As_all 61440 | Bs 43008 | red 512 | sw 2560 = 107520 B
// ---------------------------------------------------------------------------
#define AS_SP 15360
#define BS_OFF 61440
#define RED_OFF 104448
#define SW_OFF 104960
#define GSTG 4

__global__ __launch_bounds__(256, 2) void fused_span(
    const float* __restrict__ attn,
    const float* __restrict__ tok,
    const float* __restrict__ E,
    const __nv_bfloat16* __restrict__ W2s,
    const float* __restrict__ b2p, const float* __restrict__ w3p,
    const float* __restrict__ b3,
    float* __restrict__ out)
{
    extern __shared__ __align__(16) char smem[];
    __nv_bfloat16* As_all = (__nv_bfloat16*)smem;
    __nv_bfloat16* Bs = (__nv_bfloat16*)(smem + BS_OFF);   // [4][2][2688]
    float* red = (float*)(smem + RED_OFF);                 // [64][2]

    int tid = threadIdx.x;
    int wid = tid >> 5, lane = tid & 31;
    int n = blockIdx.y + 1;
    int S = kT - n + 1;
    int base = blockIdx.x * 64;
    int off = (n - 1) * (kT + 1) - (n * (n - 1)) / 2;

    auto stageB = [&](int ks, int buf) {
        int k0 = ks * 16;
        for (int c = tid; c < 640; c += 256) {
            int sp = c / 320, cc = c % 320, row = cc / 20, offc = cc % 20;
            const __nv_bfloat16* src =
                W2s + (size_t)sp * (H1P * H1P) + (size_t)(k0 + row) * H1P + offc * 8;
            unsigned dst = sm_u32(&Bs[(buf * 2 + sp) * 2688 + row * 168 + offc * 8]);
            CP_ASYNC16(dst, src);
        }
    };
    #pragma unroll
    for (int s = 0; s < GSTG - 1; s++) { stageB(s, s); CP_COMMIT(); }

    // ---- phase 1 v2 ----
    int warp_s0 = base + wid * 8;
    float* swp = (float*)(smem + SW_OFF) + wid * 80;

    // softmax weights for the warp's 8 spans
    for (int sl = 0; sl < 8; sl++) {
        int s = warp_s0 + sl;
        bool valid = s < S;
        float av = (valid && lane < n) ? attn[s + lane] : -1e30f;
        float mx = av;
        #pragma unroll
        for (int o = 16; o > 0; o >>= 1)
            mx = fmaxf(mx, __shfl_xor_sync(0xffffffffu, mx, o));
        float ev = (valid && lane < n) ? __expf(av - mx) : 0.f;
        float sum = ev;
        #pragma unroll
        for (int o = 16; o > 0; o >>= 1)
            sum += __shfl_xor_sync(0xffffffffu, sum, o);
        if (lane < 10)
            swp[sl * 10 + lane] = (valid && lane < n) ? ev / sum : 0.f;
    }
    __syncwarp();

    // boundary terms A[s] + B[e]
    float acc[8][5];
    #pragma unroll
    for (int sl = 0; sl < 8; sl++) {
        int s = warp_s0 + sl;
        bool valid = s < S;
        int sc = valid ? s : 0;
        int e = sc + n - 1;
        #pragma unroll
        for (int ch = 0; ch < 5; ch++) {
            int c = ch * 32 + lane;
            float v = 0.f;
            if (valid && c < 150)
                v = tok[(size_t)sc * TOKW + 150 + c] + tok[(size_t)e * TOKW + 300 + c];
            acc[sl][ch] = v;
        }
    }
    // shared E-row pooling: each row loaded once per warp
    for (int r = 0; r < n + 7; r++) {
        int row = min(warp_s0 + r, kT - 1);
        float er[5];
        #pragma unroll
        for (int ch = 0; ch < 5; ch++) {
            int c = ch * 32 + lane;
            er[ch] = (c < 150) ? E[(size_t)row * kH + c] : 0.f;
        }
        #pragma unroll
        for (int sl = 0; sl < 8; sl++) {
            int j = r - sl;
            if (j >= 0 && j < n) {
                float wj = swp[sl * 10 + j];
                #pragma unroll
                for (int ch = 0; ch < 5; ch++)
                    acc[sl][ch] = fmaf(wj, er[ch], acc[sl][ch]);
            }
        }
    }
    // store split-bf16 into ldmatrix layout
    #pragma unroll
    for (int sl = 0; sl < 8; sl++) {
        int slg = wid * 8 + sl;
        #pragma unroll
        for (int ch = 0; ch < 5; ch++) {
            int c = ch * 32 + lane;
            float v = (c < 150) ? fmaxf(acc[sl][ch], 0.f) : 0.f;
            __nv_bfloat16 hi = __float2bfloat16_rn(v);
            __nv_bfloat16 lo = __float2bfloat16_rn(v - __bfloat162float(hi));
            int idx = (c >> 4) * 1536 + slg * 24 + ((c >> 3) & 1) * 8 + (c & 7);
            As_all[idx] = hi;
            As_all[AS_SP + idx] = lo;
        }
    }

    // ---- phase 2: MMA vs W2 ----
    int warpM = wid & 3, warpN = wid >> 2;
    float C[10][4] = {};

    for (int ks = 0; ks < 10; ks++) {
        int buf = ks & 3;
        CP_WAIT(GSTG - 2);
        __syncthreads();
        if (ks + GSTG - 1 < 10) stageB(ks + GSTG - 1, (ks + GSTG - 1) & 3);
        CP_COMMIT();

        unsigned a[2][4];
        #pragma unroll
        for (int sp = 0; sp < 2; sp++) {
            unsigned addr = sm_u32(
                &As_all[sp * AS_SP + ks * 1536 +
                        (warpM * 16 + (lane & 15)) * 24 + (lane >> 4) * 8]);
            asm volatile(
                "ldmatrix.sync.aligned.m8n8.x4.shared.b16 {%0,%1,%2,%3}, [%4];"
                : "=r"(a[sp][0]), "=r"(a[sp][1]), "=r"(a[sp][2]), "=r"(a[sp][3])
                : "r"(addr));
        }
        #pragma unroll
        for (int np = 0; np < 5; np++) {
            int nbase = warpN * 80 + np * 16;
            unsigned bh[4], bl[4];
            {
                unsigned addr = sm_u32(
                    &Bs[(buf * 2 + 0) * 2688 + (lane & 15) * 168 + nbase +
                        (lane >> 4) * 8]);
                asm volatile(
                    "ldmatrix.sync.aligned.m8n8.x4.trans.shared.b16 {%0,%1,%2,%3}, [%4];"
                    : "=r"(bh[0]), "=r"(bh[1]), "=r"(bh[2]), "=r"(bh[3])
                    : "r"(addr));
            }
            {
                unsigned addr = sm_u32(
                    &Bs[(buf * 2 + 1) * 2688 + (lane & 15) * 168 + nbase +
                        (lane >> 4) * 8]);
                asm volatile(
                    "ldmatrix.sync.aligned.m8n8.x4.trans.shared.b16 {%0,%1,%2,%3}, [%4];"
                    : "=r"(bl[0]), "=r"(bl[1]), "=r"(bl[2]), "=r"(bl[3])
                    : "r"(addr));
            }
            float* c0 = C[2 * np];
            float* c1 = C[2 * np + 1];
            MMA6(c0, c1, a[0], a[1], bh, bl);
        }
    }

    // ---- fused epilogue ----
    int tq = lane & 3, g = lane >> 2;
    float v0 = 0.f, v1 = 0.f;
    #pragma unroll
    for (int nf = 0; nf < 10; nf++) {
        int col = warpN * 80 + nf * 8 + tq * 2;
        float bb0 = __ldg(&b2p[col]), bb1 = __ldg(&b2p[col + 1]);
        float ww0 = __ldg(&w3p[col]), ww1 = __ldg(&w3p[col + 1]);
        float* c = C[nf];
        v0 = fmaf(fmaxf(c[0] + bb0, 0.f), ww0, v0);
        v0 = fmaf(fmaxf(c[1] + bb1, 0.f), ww1, v0);
        v1 = fmaf(fmaxf(c[2] + bb0, 0.f), ww0, v1);
        v1 = fmaf(fmaxf(c[3] + bb1, 0.f), ww1, v1);
    }
    v0 += __shfl_xor_sync(0xffffffffu, v0, 1);
    v0 += __shfl_xor_sync(0xffffffffu, v0, 2);
    v1 += __shfl_xor_sync(0xffffffffu, v1, 1);
    v1 += __shfl_xor_sync(0xffffffffu, v1, 2);
    if (tq == 0) {
        red[(warpM * 16 + g) * 2 + warpN] = v0;
        red[(warpM * 16 + g + 8) * 2 + warpN] = v1;
    }
    __syncthreads();
    if (tid < 64) {
        int m = base + tid;
        if (m < S) out[off + m] = red[tid * 2] + red[tid * 2 + 1] + b3[0];
    }
}

// ---------------------------------------------------------------------------
extern "C" void kernel_launch(void* const* d_in, const int* in_sizes, int n_in,
                              void* d_out, int out_size)
{
    const float* embeds = (const float*)d_in[0];
    const float* states = (const float*)d_in[1];
    const float* aW1 = (const float*)d_in[2];
    const float* ab1 = (const float*)d_in[3];
    const float* aW2 = (const float*)d_in[4];
    const float* ab2 = (const float*)d_in[5];
    const float* aW3 = (const float*)d_in[6];
    const float* ab3 = (const float*)d_in[7];
    const float* sW1 = (const float*)d_in[8];
    const float* sb1 = (const float*)d_in[9];
    const float* sW2 = (const float*)d_in[10];
    const float* sb2 = (const float*)d_in[11];
    const float* sW3 = (const float*)d_in[12];
    const float* sb3 = (const float*)d_in[13];
    float* out = (float*)d_out;

    float *tok, *E, *attn, *ab2p, *aw3p, *sb2p, *sw3p;
    __nv_bfloat16 *Ss, *Es, *Has, *Hal, *Wtok, *WE, *Wa2, *W2s;
    cudaGetSymbolAddress((void**)&tok, g_tok);
    cudaGetSymbolAddress((void**)&E, g_E);
    cudaGetSymbolAddress((void**)&attn, g_attn);
    cudaGetSymbolAddress((void**)&Ss, g_Ss);
    cudaGetSymbolAddress((void**)&Es, g_Es);
    cudaGetSymbolAddress((void**)&Has, g_Has);
    cudaGetSymbolAddress((void**)&Hal, g_Hal);
    cudaGetSymbolAddress((void**)&Wtok, g_Wtok);
    cudaGetSymbolAddress((void**)&WE, g_WE);
    cudaGetSymbolAddress((void**)&Wa2, g_Wa2);
    cudaGetSymbolAddress((void**)&W2s, g_W2s);
    cudaGetSymbolAddress((void**)&ab2p, g_ab2p);
    cudaGetSymbolAddress((void**)&aw3p, g_aw3p);
    cudaGetSymbolAddress((void**)&sb2p, g_sb2p);
    cudaGetSymbolAddress((void**)&sw3p, g_sw3p);

    cudaFuncSetAttribute(tokE_gemm,
                         cudaFuncAttributeMaxDynamicSharedMemorySize, 101376);
    cudaFuncSetAttribute(fused_span,
                         cudaFuncAttributeMaxDynamicSharedMemorySize, 107520);

    // 1. all weight prep
    {
        int total = 3 * 400 * 160 + 304 * 160 + 2 * 160 * 160 + H1P;
        prep_all<<<(total + 255) / 256, 256>>>(aW1, sW1, aW2, sW2, ab2, aW3,
                                               sb2, sW3, Wtok, WE, Wa2, W2s,
                                               ab2p, aw3p, sb2p, sw3p);
    }
    // 2-3. activation splits (pad cols stay zero via zero-init globals)
    conv_split<<<(kT * 100 + 255) / 256, 256>>>(states, kT, kS, SKP,
                                                Ss, Ss + (size_t)kT * SKP);
    conv_split<<<(kT * 75 + 255) / 256, 256>>>(embeds, kT, kE, EKP,
                                               Es, Es + (size_t)kT * EKP);

    int mt = (kT + MBM - 1) / MBM;  // 313

    // 4. combined E + tok GEMM (y: 0=E, 1=Ha, 2=A, 3=B)
    tokE_gemm<<<dim3(mt, 4), 256, 101376>>>(Ss, Es, Wtok, WE, ab1, sb1,
                                            tok, E, Has, Hal);
    // 5. attention tail
    score_mma<<<(kT + SCBM - 1) / SCBM, 256>>>(Has, Hal, Wa2, ab2p, aw3p,
                                               ab3, attn, kT);
    // 6. fused span scoring
    fused_span<<<dim3(313, 10), 256, 107520>>>(attn, tok, E, W2s, sb2p, sw3p,
                                               sb3, out);
}

// round 16
// speedup vs baseline: 3.1762x; 1.0057x over previous
#include <cuda_runtime.h>
#include <cuda_bf16.h>

#define kT 20000
#define kE 300
#define kS 400
#define kH 150
#define NSPANS (10 * kT - 45)
#define TOKW 452    // padded f32 row: 150:300 A, 300:450 B
#define H1P 160
#define SKP 416     // states K padded (13*32)
#define EKP 320     // embeds K padded (10*32)

typedef unsigned long long ull;

// Scratch (allocation-free rule: __device__ globals; zero-initialized — pad
// regions are never written and stay zero)
__device__ float g_tok[(size_t)kT * TOKW];
__device__ float g_E[(size_t)kT * kH];
__device__ float g_attn[kT];
__device__ __nv_bfloat16 g_Ss[2 * (size_t)kT * SKP];
__device__ __nv_bfloat16 g_Es[2 * (size_t)kT * EKP];
__device__ __nv_bfloat16 g_Has[(size_t)kT * H1P];
__device__ __nv_bfloat16 g_Hal[(size_t)kT * H1P];
__device__ __nv_bfloat16 g_Wtok[2 * SKP * 480];
__device__ __nv_bfloat16 g_WE[2 * EKP * 160];
__device__ __nv_bfloat16 g_Wa2[2 * 160 * 160];
__device__ __nv_bfloat16 g_W2s[2 * 160 * 160];
__device__ float g_ab2p[H1P];
__device__ float g_aw3p[H1P];
__device__ float g_sb2p[H1P];
__device__ float g_sw3p[H1P];

static __device__ __forceinline__ unsigned sm_u32(const void* p) {
    return (unsigned)__cvta_generic_to_shared(p);
}
static __device__ __forceinline__ unsigned pack_bf2(__nv_bfloat16 a, __nv_bfloat16 b) {
    unsigned r;
    unsigned short ua = *(unsigned short*)&a, ub = *(unsigned short*)&b;
    asm("mov.b32 %0, {%1, %2};" : "=r"(r) : "h"(ua), "h"(ub));
    return r;
}

#define CP_ASYNC16(dst, src) \
    asm volatile("cp.async.cg.shared.global [%0], [%1], 16;" \
                 :: "r"(dst), "l"(src))
#define CP_COMMIT() asm volatile("cp.async.commit_group;" ::: "memory")
#define CP_WAIT(n)  asm volatile("cp.async.wait_group %0;" :: "n"(n) : "memory")

#define MMA_ONE(c, A, b0, b1)                                                 \
    asm volatile("mma.sync.aligned.m16n8k16.row.col.f32.bf16.bf16.f32 "       \
                 "{%0,%1,%2,%3},{%4,%5,%6,%7},{%8,%9},{%0,%1,%2,%3};"         \
                 : "+f"((c)[0]), "+f"((c)[1]), "+f"((c)[2]), "+f"((c)[3])     \
                 : "r"((A)[0]), "r"((A)[1]), "r"((A)[2]), "r"((A)[3]),        \
                   "r"(b0), "r"(b1));

// 12 MMAs over 4 accumulators (dep distance 4). Per-accumulator order is
// AhiBh -> AloBh -> AhiBl, identical to MMA6 (bitwise-same results).
#define MMA12(c00, c01, c10, c11, A0, A1, BH0, BH1, BL0, BL1)                 \
    MMA_ONE(c00, A0, BH0[0], BH0[1]); MMA_ONE(c01, A0, BH0[2], BH0[3]);       \
    MMA_ONE(c10, A0, BH1[0], BH1[1]); MMA_ONE(c11, A0, BH1[2], BH1[3]);       \
    MMA_ONE(c00, A1, BH0[0], BH0[1]); MMA_ONE(c01, A1, BH0[2], BH0[3]);       \
    MMA_ONE(c10, A1, BH1[0], BH1[1]); MMA_ONE(c11, A1, BH1[2], BH1[3]);       \
    MMA_ONE(c00, A0, BL0[0], BL0[1]); MMA_ONE(c01, A0, BL0[2], BL0[3]);       \
    MMA_ONE(c10, A0, BL1[0], BL1[1]); MMA_ONE(c11, A0, BL1[2], BL1[3]);

#define MMA6(c0, c1, A0, A1, BH, BL)                                          \
    MMA_ONE(c0, A0, BH[0], BH[1]); MMA_ONE(c1, A0, BH[2], BH[3]);             \
    MMA_ONE(c0, A1, BH[0], BH[1]); MMA_ONE(c1, A1, BH[2], BH[3]);             \
    MMA_ONE(c0, A0, BL[0], BL[1]); MMA_ONE(c1, A0, BL[2], BL[3]);

#define LDSM(dst, addr)                                                       \
    asm volatile("ldmatrix.sync.aligned.m8n8.x4.shared.b16 {%0,%1,%2,%3}, [%4];" \
                 : "=r"(dst[0]), "=r"(dst[1]), "=r"(dst[2]), "=r"(dst[3])     \
                 : "r"(addr));
#define LDSMT(dst, addr)                                                      \
    asm volatile("ldmatrix.sync.aligned.m8n8.x4.trans.shared.b16 {%0,%1,%2,%3}, [%4];" \
                 : "=r"(dst[0]), "=r"(dst[1]), "=r"(dst[2]), "=r"(dst[3])     \
                 : "r"(addr));

// ---------------------------------------------------------------------------
// One-shot prep: all weight splits + padded vectors.
// ---------------------------------------------------------------------------
static __device__ __forceinline__ void wsplit(
    float w, __nv_bfloat16* dh, __nv_bfloat16* dl, size_t idx)
{
    __nv_bfloat16 hi = __float2bfloat16_rn(w);
    dh[idx] = hi;
    dl[idx] = __float2bfloat16_rn(w - __bfloat162float(hi));
}

__global__ void prep_all(
    const float* __restrict__ aW1, const float* __restrict__ sW1,
    const float* __restrict__ aW2, const float* __restrict__ sW2,
    const float* __restrict__ ab2, const float* __restrict__ aW3,
    const float* __restrict__ sb2, const float* __restrict__ sW3,
    __nv_bfloat16* __restrict__ Wtok, __nv_bfloat16* __restrict__ WE,
    __nv_bfloat16* __restrict__ Wa2, __nv_bfloat16* __restrict__ W2s,
    float* __restrict__ ab2p, float* __restrict__ aw3p,
    float* __restrict__ sb2p, float* __restrict__ sw3p)
{
    const int NT = 400 * 160, NE = 304 * 160, N2 = 160 * 160;
    int i = blockIdx.x * blockDim.x + threadIdx.x;
    if (i < 3 * NT) {
        int t = i / NT, r = i - t * NT;
        int k = r / 160, c = r - k * 160;
        const float* src = (t == 0) ? aW1 : ((t == 1) ? sW1 : sW1 + 400 * 150);
        float w = (c < 150) ? src[(size_t)k * 150 + c] : 0.f;
        wsplit(w, Wtok, Wtok + (size_t)SKP * 480, (size_t)k * 480 + t * 160 + c);
        return;
    }
    i -= 3 * NT;
    if (i < NE) {
        int k = i / 160, c = i - k * 160;
        float w = (k < 300 && c < 150) ? sW1[(size_t)(800 + k) * 150 + c] : 0.f;
        wsplit(w, WE, WE + (size_t)EKP * 160, i);
        return;
    }
    i -= NE;
    if (i < N2) {
        int k = i / 160, c = i - k * 160;
        float w = (k < 150 && c < 150) ? aW2[(size_t)k * 150 + c] : 0.f;
        wsplit(w, Wa2, Wa2 + N2, i);
        return;
    }
    i -= N2;
    if (i < N2) {
        int k = i / 160, c = i - k * 160;
        float w = (k < 150 && c < 150) ? sW2[(size_t)k * 150 + c] : 0.f;
        wsplit(w, W2s, W2s + N2, i);
        return;
    }
    i -= N2;
    if (i < H1P) {
        ab2p[i] = (i < 150) ? ab2[i] : 0.f;
        aw3p[i] = (i < 150) ? aW3[i] : 0.f;
        sb2p[i] = (i < 150) ? sb2[i] : 0.f;
        sw3p[i] = (i < 150) ? sW3[i] : 0.f;
    }
}

// ---------------------------------------------------------------------------
// Split activation matrix f32 [M x K] -> bf16 hi/lo [M x ldd]
// ---------------------------------------------------------------------------
__global__ void conv_split(const float* __restrict__ src, int M, int K, int ldd,
                           __nv_bfloat16* __restrict__ dh,
                           __nv_bfloat16* __restrict__ dl)
{
    int i = blockIdx.x * blockDim.x + threadIdx.x;
    int q4 = K >> 2;
    if (i >= M * q4) return;
    int row = i / q4, q = i - row * q4;
    float4 v = *(const float4*)&src[(size_t)row * K + q * 4];
    float* vp = (float*)&v;
    __nv_bfloat16 h[4], l[4];
    #pragma unroll
    for (int j = 0; j < 4; j++) {
        h[j] = __float2bfloat16_rn(vp[j]);
        l[j] = __float2bfloat16_rn(vp[j] - __bfloat162float(h[j]));
    }
    uint2 sh = {pack_bf2(h[0], h[1]), pack_bf2(h[2], h[3])};
    uint2 sl = {pack_bf2(l[0], l[1]), pack_bf2(l[2], l[3])};
    *(uint2*)&dh[(size_t)row * ldd + q * 4] = sh;
    *(uint2*)&dl[(size_t)row * ldd + q * 4] = sl;
}

// ---------------------------------------------------------------------------
// Combined token-level GEMM, cp.async 3-stage ring, K=32 per stage.
// blockIdx.y: 0 -> E (10 K32 steps); 1..3 -> tok segments (13 K32 steps).
// ---------------------------------------------------------------------------
#define MBM 64

__global__ __launch_bounds__(256, 2) void tokE_gemm(
    const __nv_bfloat16* __restrict__ Ss, const __nv_bfloat16* __restrict__ Es,
    const __nv_bfloat16* __restrict__ Wtok, const __nv_bfloat16* __restrict__ WE,
    const float* __restrict__ ab1, const float* __restrict__ sb1,
    float* __restrict__ tok, float* __restrict__ Eout,
    __nv_bfloat16* __restrict__ Has, __nv_bfloat16* __restrict__ Hal)
{
    extern __shared__ __align__(16) char smem[];
    __nv_bfloat16* As = (__nv_bfloat16*)smem;             // [3][2sub][2sp][1536]
    __nv_bfloat16* Bs = (__nv_bfloat16*)(smem + 36864);   // [3][2sub][2sp][2688]

    int tid = threadIdx.x;
    int m0 = blockIdx.x * MBM;
    int y = blockIdx.y;

    const __nv_bfloat16 *Ah, *Al, *Bh, *Bl;
    int lda, ldb, n0, nsteps2;
    if (y == 0) {
        Ah = Es; Al = Es + (size_t)kT * EKP; lda = EKP;
        Bh = WE; Bl = WE + (size_t)EKP * 160; ldb = 160; n0 = 0; nsteps2 = 10;
    } else {
        Ah = Ss; Al = Ss + (size_t)kT * SKP; lda = SKP;
        Bh = Wtok; Bl = Wtok + (size_t)SKP * 480; ldb = 480;
        n0 = (y - 1) * 160; nsteps2 = 13;
    }

    int wid = tid >> 5, lane = tid & 31;
    int warpM = wid & 3, warpN = wid >> 2;
    float Cr[10][4] = {};

    int a_sp = tid >> 7, a_tt = tid & 127, a_r = a_tt >> 1, a_half = a_tt & 1;
    int a_row = min(m0 + a_r, kT - 1);
    const __nv_bfloat16* a_base = (a_sp ? Al : Ah) + (size_t)a_row * lda + a_half * 8;
    unsigned a_smem0 = sm_u32(&As[a_r * 24 + a_half * 8]);

    auto stage32 = [&](int ks2, int st) {
        #pragma unroll
        for (int sub = 0; sub < 2; sub++) {
            int k0 = (ks2 * 2 + sub) * 16;
            CP_ASYNC16(a_smem0 + ((st * 2 + sub) * 2 + a_sp) * 3072, a_base + k0);
        }
        #pragma unroll 5
        for (int c = tid; c < 1280; c += 256) {
            int sub = c / 640, cc = c % 640;
            int sp = cc / 320, c2 = cc % 320, row = c2 / 20, offc = c2 % 20;
            int kk = (ks2 * 2 + sub) * 16 + row;
            const __nv_bfloat16* src =
                (sp ? Bl : Bh) + (size_t)kk * ldb + n0 + offc * 8;
            unsigned dst = sm_u32(
                &Bs[((st * 2 + sub) * 2 + sp) * 2688 + row * 168 + offc * 8]);
            CP_ASYNC16(dst, src);
        }
    };

    stage32(0, 0); CP_COMMIT();
    stage32(1, 1); CP_COMMIT();

    for (int ks2 = 0; ks2 < nsteps2; ks2++) {
        int st = ks2 % 3;
        CP_WAIT(1);
        __syncthreads();
        if (ks2 + 2 < nsteps2) stage32(ks2 + 2, (ks2 + 2) % 3);
        CP_COMMIT();

        #pragma unroll
        for (int sub = 0; sub < 2; sub++) {
            unsigned a[2][4];
            #pragma unroll
            for (int sp = 0; sp < 2; sp++) {
                unsigned addr = sm_u32(
                    &As[((st * 2 + sub) * 2 + sp) * 1536 +
                        (warpM * 16 + (lane & 15)) * 24 + (lane >> 4) * 8]);
                LDSM(a[sp], addr);
            }
            int brow = (lane & 15) * 168 + (lane >> 4) * 8;
            const __nv_bfloat16* bsh = &Bs[((st * 2 + sub) * 2 + 0) * 2688];
            const __nv_bfloat16* bsl = &Bs[((st * 2 + sub) * 2 + 1) * 2688];
            #pragma unroll
            for (int gp = 0; gp < 2; gp++) {
                int np0 = gp * 2, np1 = np0 + 1;
                int nb0 = warpN * 80 + np0 * 16, nb1 = warpN * 80 + np1 * 16;
                unsigned bh0[4], bl0[4], bh1[4], bl1[4];
                LDSMT(bh0, sm_u32(bsh + brow + nb0));
                LDSMT(bh1, sm_u32(bsh + brow + nb1));
                LDSMT(bl0, sm_u32(bsl + brow + nb0));
                LDSMT(bl1, sm_u32(bsl + brow + nb1));
                MMA12(Cr[2 * np0], Cr[2 * np0 + 1], Cr[2 * np1], Cr[2 * np1 + 1],
                      a[0], a[1], bh0, bh1, bl0, bl1);
            }
            {
                int nb = warpN * 80 + 64;
                unsigned bh[4], bl[4];
                LDSMT(bh, sm_u32(bsh + brow + nb));
                LDSMT(bl, sm_u32(bsl + brow + nb));
                MMA6(Cr[8], Cr[9], a[0], a[1], bh, bl);
            }
        }
    }

    // epilogue
    int tq = lane & 3, g = lane >> 2;
    int mr0 = m0 + warpM * 16 + g;
    #pragma unroll
    for (int nf = 0; nf < 10; nf++) {
        int nloc = warpN * 80 + nf * 8 + tq * 2;
        float* c = Cr[nf];
        if (nloc >= 150) {
            if (y == 1) {
                __nv_bfloat16 z = __float2bfloat16(0.f);
                if (mr0 < kT) {
                    Has[(size_t)mr0 * H1P + nloc] = z;  Hal[(size_t)mr0 * H1P + nloc] = z;
                    Has[(size_t)mr0 * H1P + nloc + 1] = z; Hal[(size_t)mr0 * H1P + nloc + 1] = z;
                }
                if (mr0 + 8 < kT) {
                    Has[(size_t)(mr0 + 8) * H1P + nloc] = z;  Hal[(size_t)(mr0 + 8) * H1P + nloc] = z;
                    Has[(size_t)(mr0 + 8) * H1P + nloc + 1] = z; Hal[(size_t)(mr0 + 8) * H1P + nloc + 1] = z;
                }
            }
            continue;
        }
        float bb0 = 0.f, bb1 = 0.f;
        if (y == 1) { bb0 = ab1[nloc]; bb1 = ab1[nloc + 1]; }
        if (y == 2) { bb0 = sb1[nloc]; bb1 = sb1[nloc + 1]; }
        float v0 = c[0] + bb0, v1 = c[1] + bb1;
        float v2 = c[2] + bb0, v3 = c[3] + bb1;
        if (y == 1) {
            v0 = fmaxf(v0, 0.f); v1 = fmaxf(v1, 0.f);
            v2 = fmaxf(v2, 0.f); v3 = fmaxf(v3, 0.f);
            float vv[4] = {v0, v1, v2, v3};
            #pragma unroll
            for (int q = 0; q < 4; q++) {
                int m = (q < 2) ? mr0 : mr0 + 8;
                if (m >= kT) continue;
                int n = nloc + (q & 1);
                __nv_bfloat16 hi = __float2bfloat16_rn(vv[q]);
                __nv_bfloat16 lo = __float2bfloat16_rn(vv[q] - __bfloat162float(hi));
                Has[(size_t)m * H1P + n] = hi;
                Hal[(size_t)m * H1P + n] = lo;
            }
        } else if (y == 0) {
            if (mr0 < kT) {
                Eout[(size_t)mr0 * kH + nloc] = v0;
                Eout[(size_t)mr0 * kH + nloc + 1] = v1;
            }
            if (mr0 + 8 < kT) {
                Eout[(size_t)(mr0 + 8) * kH + nloc] = v2;
                Eout[(size_t)(mr0 + 8) * kH + nloc + 1] = v3;
            }
        } else {
            int n = (y == 2 ? 150 : 300) + nloc;
            if (mr0 < kT) {
                tok[(size_t)mr0 * TOKW + n] = v0;
                tok[(size_t)mr0 * TOKW + n + 1] = v1;
            }
            if (mr0 + 8 < kT) {
                tok[(size_t)(mr0 + 8) * TOKW + n] = v2;
                tok[(size_t)(mr0 + 8) * TOKW + n + 1] = v3;
            }
        }
    }
}

// ---------------------------------------------------------------------------
// score_mma: attention tail.
// ---------------------------------------------------------------------------
#define SCBM 64

__global__ __launch_bounds__(256, 2) void score_mma(
    const __nv_bfloat16* __restrict__ H1h, const __nv_bfloat16* __restrict__ H1l,
    const __nv_bfloat16* __restrict__ W2s,
    const float* __restrict__ b2p, const float* __restrict__ w3p,
    const float* __restrict__ b3,
    float* __restrict__ out, int M)
{
    __shared__ __align__(16) __nv_bfloat16 As[2][2][SCBM * 24];
    __shared__ __align__(16) __nv_bfloat16 Bs[2][2][16 * 168];
    __shared__ float red[SCBM][2];

    int tid = threadIdx.x;
    int m0 = blockIdx.x * SCBM;
    int wid = tid >> 5, lane = tid & 31;
    int warpM = wid & 3, warpN = wid >> 2;

    float C[10][4] = {};

    auto stage = [&](int ks, int buf) {
        int k0 = ks * 16;
        {
            int sp = tid >> 7, tt = tid & 127, r = tt >> 1, half = tt & 1;
            int mrow = min(m0 + r, M - 1);
            const __nv_bfloat16* src =
                (sp ? H1l : H1h) + (size_t)mrow * H1P + k0 + half * 8;
            *(int4*)&As[buf][sp][r * 24 + half * 8] = *(const int4*)src;
        }
        for (int c = tid; c < 640; c += 256) {
            int sp = c / 320, cc = c % 320, row = cc / 20, offc = cc % 20;
            const __nv_bfloat16* src =
                W2s + (size_t)sp * H1P * H1P + (size_t)(k0 + row) * H1P + offc * 8;
            *(int4*)&Bs[buf][sp][row * 168 + offc * 8] = *(const int4*)src;
        }
    };

    stage(0, 0);
    __syncthreads();

    for (int ks = 0; ks < 10; ks++) {
        int buf = ks & 1;
        if (ks < 9) stage(ks + 1, buf ^ 1);

        unsigned a[2][4];
        #pragma unroll
        for (int sp = 0; sp < 2; sp++) {
            unsigned addr = sm_u32(
                &As[buf][sp][(warpM * 16 + (lane & 15)) * 24 + (lane >> 4) * 8]);
            LDSM(a[sp], addr);
        }
        int brow = (lane & 15) * 168 + (lane >> 4) * 8;
        const __nv_bfloat16* bsh = &Bs[buf][0][0];
        const __nv_bfloat16* bsl = &Bs[buf][1][0];
        #pragma unroll
        for (int gp = 0; gp < 2; gp++) {
            int np0 = gp * 2, np1 = np0 + 1;
            int nb0 = warpN * 80 + np0 * 16, nb1 = warpN * 80 + np1 * 16;
            unsigned bh0[4], bl0[4], bh1[4], bl1[4];
            LDSMT(bh0, sm_u32(bsh + brow + nb0));
            LDSMT(bh1, sm_u32(bsh + brow + nb1));
            LDSMT(bl0, sm_u32(bsl + brow + nb0));
            LDSMT(bl1, sm_u32(bsl + brow + nb1));
            MMA12(C[2 * np0], C[2 * np0 + 1], C[2 * np1], C[2 * np1 + 1],
                  a[0], a[1], bh0, bh1, bl0, bl1);
        }
        {
            int nb = warpN * 80 + 64;
            unsigned bh[4], bl[4];
            LDSMT(bh, sm_u32(bsh + brow + nb));
            LDSMT(bl, sm_u32(bsl + brow + nb));
            MMA6(C[8], C[9], a[0], a[1], bh, bl);
        }
        __syncthreads();
    }

    int tq = lane & 3, g = lane >> 2;
    float v0 = 0.f, v1 = 0.f;
    #pragma unroll
    for (int nf = 0; nf < 10; nf++) {
        int col = warpN * 80 + nf * 8 + tq * 2;
        float bb0 = __ldg(&b2p[col]), bb1 = __ldg(&b2p[col + 1]);
        float ww0 = __ldg(&w3p[col]), ww1 = __ldg(&w3p[col + 1]);
        float* c = C[nf];
        v0 = fmaf(fmaxf(c[0] + bb0, 0.f), ww0, v0);
        v0 = fmaf(fmaxf(c[1] + bb1, 0.f), ww1, v0);
        v1 = fmaf(fmaxf(c[2] + bb0, 0.f), ww0, v1);
        v1 = fmaf(fmaxf(c[3] + bb1, 0.f), ww1, v1);
    }
    v0 += __shfl_xor_sync(0xffffffffu, v0, 1);
    v0 += __shfl_xor_sync(0xffffffffu, v0, 2);
    v1 += __shfl_xor_sync(0xffffffffu, v1, 1);
    v1 += __shfl_xor_sync(0xffffffffu, v1, 2);
    if (tq == 0) {
        red[warpM * 16 + g][warpN] = v0;
        red[warpM * 16 + g + 8][warpN] = v1;
    }
    __syncthreads();
    if (tid < SCBM) {
        int m = m0 + tid;
        if (m < M) out[m] = red[tid][0] + red[tid][1] + b3[0];
    }
}

// ---------------------------------------------------------------------------
// Fused span kernel: 64 same-width spans per block.
// ---------------------------------------------------------------------------
#define AS_SP 15360
#define BS_OFF 61440
#define RED_OFF 104448
#define SW_OFF 104960
#define GSTG 4

__global__ __launch_bounds__(256, 2) void fused_span(
    const float* __restrict__ attn,
    const float* __restrict__ tok,
    const float* __restrict__ E,
    const __nv_bfloat16* __restrict__ W2s,
    const float* __restrict__ b2p, const float* __restrict__ w3p,
    const float* __restrict__ b3,
    float* __restrict__ out)
{
    extern __shared__ __align__(16) char smem[];
    __nv_bfloat16* As_all = (__nv_bfloat16*)smem;
    __nv_bfloat16* Bs = (__nv_bfloat16*)(smem + BS_OFF);   // [4][2][2688]
    float* red = (float*)(smem + RED_OFF);                 // [64][2]

    int tid = threadIdx.x;
    int wid = tid >> 5, lane = tid & 31;
    int n = blockIdx.y + 1;
    int S = kT - n + 1;
    int base = blockIdx.x * 64;
    int off = (n - 1) * (kT + 1) - (n * (n - 1)) / 2;

    auto stageB = [&](int ks, int buf) {
        int k0 = ks * 16;
        for (int c = tid; c < 640; c += 256) {
            int sp = c / 320, cc = c % 320, row = cc / 20, offc = cc % 20;
            const __nv_bfloat16* src =
                W2s + (size_t)sp * (H1P * H1P) + (size_t)(k0 + row) * H1P + offc * 8;
            unsigned dst = sm_u32(&Bs[(buf * 2 + sp) * 2688 + row * 168 + offc * 8]);
            CP_ASYNC16(dst, src);
        }
    };
    #pragma unroll
    for (int s = 0; s < GSTG - 1; s++) { stageB(s, s); CP_COMMIT(); }

    // ---- phase 1: warp-shared E pooling ----
    int warp_s0 = base + wid * 8;
    float* swp = (float*)(smem + SW_OFF) + wid * 80;

    for (int sl = 0; sl < 8; sl++) {
        int s = warp_s0 + sl;
        bool valid = s < S;
        float av = (valid && lane < n) ? attn[s + lane] : -1e30f;
        float mx = av;
        #pragma unroll
        for (int o = 16; o > 0; o >>= 1)
            mx = fmaxf(mx, __shfl_xor_sync(0xffffffffu, mx, o));
        float ev = (valid && lane < n) ? __expf(av - mx) : 0.f;
        float sum = ev;
        #pragma unroll
        for (int o = 16; o > 0; o >>= 1)
            sum += __shfl_xor_sync(0xffffffffu, sum, o);
        if (lane < 10)
            swp[sl * 10 + lane] = (valid && lane < n) ? ev / sum : 0.f;
    }
    __syncwarp();

    float acc[8][5];
    #pragma unroll
    for (int sl = 0; sl < 8; sl++) {
        int s = warp_s0 + sl;
        bool valid = s < S;
        int sc = valid ? s : 0;
        int e = sc + n - 1;
        #pragma unroll
        for (int ch = 0; ch < 5; ch++) {
            int c = ch * 32 + lane;
            float v = 0.f;
            if (valid && c < 150)
                v = tok[(size_t)sc * TOKW + 150 + c] + tok[(size_t)e * TOKW + 300 + c];
            acc[sl][ch] = v;
        }
    }
    for (int r = 0; r < n + 7; r++) {
        int row = min(warp_s0 + r, kT - 1);
        float er[5];
        #pragma unroll
        for (int ch = 0; ch < 5; ch++) {
            int c = ch * 32 + lane;
            er[ch] = (c < 150) ? E[(size_t)row * kH + c] : 0.f;
        }
        #pragma unroll
        for (int sl = 0; sl < 8; sl++) {
            int j = r - sl;
            if (j >= 0 && j < n) {
                float wj = swp[sl * 10 + j];
                #pragma unroll
                for (int ch = 0; ch < 5; ch++)
                    acc[sl][ch] = fmaf(wj, er[ch], acc[sl][ch]);
            }
        }
    }
    #pragma unroll
    for (int sl = 0; sl < 8; sl++) {
        int slg = wid * 8 + sl;
        #pragma unroll
        for (int ch = 0; ch < 5; ch++) {
            int c = ch * 32 + lane;
            float v = (c < 150) ? fmaxf(acc[sl][ch], 0.f) : 0.f;
            __nv_bfloat16 hi = __float2bfloat16_rn(v);
            __nv_bfloat16 lo = __float2bfloat16_rn(v - __bfloat162float(hi));
            int idx = (c >> 4) * 1536 + slg * 24 + ((c >> 3) & 1) * 8 + (c & 7);
            As_all[idx] = hi;
            As_all[AS_SP + idx] = lo;
        }
    }

    // ---- phase 2: MMA vs W2 ----
    int warpM = wid & 3, warpN = wid >> 2;
    float C[10][4] = {};

    for (int ks = 0; ks < 10; ks++) {
        int buf = ks & 3;
        CP_WAIT(GSTG - 2);
        __syncthreads();
        if (ks + GSTG - 1 < 10) stageB(ks + GSTG - 1, (ks + GSTG - 1) & 3);
        CP_COMMIT();

        unsigned a[2][4];
        #pragma unroll
        for (int sp = 0; sp < 2; sp++) {
            unsigned addr = sm_u32(
                &As_all[sp * AS_SP + ks * 1536 +
                        (warpM * 16 + (lane & 15)) * 24 + (lane >> 4) * 8]);
            LDSM(a[sp], addr);
        }
        int brow = (lane & 15) * 168 + (lane >> 4) * 8;
        const __nv_bfloat16* bsh = &Bs[(buf * 2 + 0) * 2688];
        const __nv_bfloat16* bsl = &Bs[(buf * 2 + 1) * 2688];
        #pragma unroll
        for (int gp = 0; gp < 2; gp++) {
            int np0 = gp * 2, np1 = np0 + 1;
            int nb0 = warpN * 80 + np0 * 16, nb1 = warpN * 80 + np1 * 16;
            unsigned bh0[4], bl0[4], bh1[4], bl1[4];
            LDSMT(bh0, sm_u32(bsh + brow + nb0));
            LDSMT(bh1, sm_u32(bsh + brow + nb1));
            LDSMT(bl0, sm_u32(bsl + brow + nb0));
            LDSMT(bl1, sm_u32(bsl + brow + nb1));
            MMA12(C[2 * np0], C[2 * np0 + 1], C[2 * np1], C[2 * np1 + 1],
                  a[0], a[1], bh0, bh1, bl0, bl1);
        }
        {
            int nb = warpN * 80 + 64;
            unsigned bh[4], bl[4];
            LDSMT(bh, sm_u32(bsh + brow + nb));
            LDSMT(bl, sm_u32(bsl + brow + nb));
            MMA6(C[8], C[9], a[0], a[1], bh, bl);
        }
    }

    // ---- fused epilogue ----
    int tq = lane & 3, g = lane >> 2;
    float v0 = 0.f, v1 = 0.f;
    #pragma unroll
    for (int nf = 0; nf < 10; nf++) {
        int col = warpN * 80 + nf * 8 + tq * 2;
        float bb0 = __ldg(&b2p[col]), bb1 = __ldg(&b2p[col + 1]);
        float ww0 = __ldg(&w3p[col]), ww1 = __ldg(&w3p[col + 1]);
        float* c = C[nf];
        v0 = fmaf(fmaxf(c[0] + bb0, 0.f), ww0, v0);
        v0 = fmaf(fmaxf(c[1] + bb1, 0.f), ww1, v0);
        v1 = fmaf(fmaxf(c[2] + bb0, 0.f), ww0, v1);
        v1 = fmaf(fmaxf(c[3] + bb1, 0.f), ww1, v1);
    }
    v0 += __shfl_xor_sync(0xffffffffu, v0, 1);
    v0 += __shfl_xor_sync(0xffffffffu, v0, 2);
    v1 += __shfl_xor_sync(0xffffffffu, v1, 1);
    v1 += __shfl_xor_sync(0xffffffffu, v1, 2);
    if (tq == 0) {
        red[(warpM * 16 + g) * 2 + warpN] = v0;
        red[(warpM * 16 + g + 8) * 2 + warpN] = v1;
    }
    __syncthreads();
    if (tid < 64) {
        int m = base + tid;
        if (m < S) out[off + m] = red[tid * 2] + red[tid * 2 + 1] + b3[0];
    }
}

// ---------------------------------------------------------------------------
extern "C" void kernel_launch(void* const* d_in, const int* in_sizes, int n_in,
                              void* d_out, int out_size)
{
    const float* embeds = (const float*)d_in[0];
    const float* states = (const float*)d_in[1];
    const float* aW1 = (const float*)d_in[2];
    const float* ab1 = (const float*)d_in[3];
    const float* aW2 = (const float*)d_in[4];
    const float* ab2 = (const float*)d_in[5];
    const float* aW3 = (const float*)d_in[6];
    const float* ab3 = (const float*)d_in[7];
    const float* sW1 = (const float*)d_in[8];
    const float* sb1 = (const float*)d_in[9];
    const float* sW2 = (const float*)d_in[10];
    const float* sb2 = (const float*)d_in[11];
    const float* sW3 = (const float*)d_in[12];
    const float* sb3 = (const float*)d_in[13];
    float* out = (float*)d_out;

    float *tok, *E, *attn, *ab2p, *aw3p, *sb2p, *sw3p;
    __nv_bfloat16 *Ss, *Es, *Has, *Hal, *Wtok, *WE, *Wa2, *W2s;
    cudaGetSymbolAddress((void**)&tok, g_tok);
    cudaGetSymbolAddress((void**)&E, g_E);
    cudaGetSymbolAddress((void**)&attn, g_attn);
    cudaGetSymbolAddress((void**)&Ss, g_Ss);
    cudaGetSymbolAddress((void**)&Es, g_Es);
    cudaGetSymbolAddress((void**)&Has, g_Has);
    cudaGetSymbolAddress((void**)&Hal, g_Hal);
    cudaGetSymbolAddress((void**)&Wtok, g_Wtok);
    cudaGetSymbolAddress((void**)&WE, g_WE);
    cudaGetSymbolAddress((void**)&Wa2, g_Wa2);
    cudaGetSymbolAddress((void**)&W2s, g_W2s);
    cudaGetSymbolAddress((void**)&ab2p, g_ab2p);
    cudaGetSymbolAddress((void**)&aw3p, g_aw3p);
    cudaGetSymbolAddress((void**)&sb2p, g_sb2p);
    cudaGetSymbolAddress((void**)&sw3p, g_sw3p);

    cudaFuncSetAttribute(tokE_gemm,
                         cudaFuncAttributeMaxDynamicSharedMemorySize, 101376);
    cudaFuncSetAttribute(fused_span,
                         cudaFuncAttributeMaxDynamicSharedMemorySize, 107520);

    // 1. all weight prep
    {
        int total = 3 * 400 * 160 + 304 * 160 + 2 * 160 * 160 + H1P;
        prep_all<<<(total + 255) / 256, 256>>>(aW1, sW1, aW2, sW2, ab2, aW3,
                                               sb2, sW3, Wtok, WE, Wa2, W2s,
                                               ab2p, aw3p, sb2p, sw3p);
    }
    // 2-3. activation splits
    conv_split<<<(kT * 100 + 255) / 256, 256>>>(states, kT, kS, SKP,
                                                Ss, Ss + (size_t)kT * SKP);
    conv_split<<<(kT * 75 + 255) / 256, 256>>>(embeds, kT, kE, EKP,
                                               Es, Es + (size_t)kT * EKP);

    int mt = (kT + MBM - 1) / MBM;  // 313

    // 4. combined E + tok GEMM (y: 0=E, 1=Ha, 2=A, 3=B)
    tokE_gemm<<<dim3(mt, 4), 256, 101376>>>(Ss, Es, Wtok, WE, ab1, sb1,
                                            tok, E, Has, Hal);
    // 5. attention tail
    score_mma<<<(kT + SCBM - 1) / SCBM, 256>>>(Has, Hal, Wa2, ab2p, aw3p,
                                               ab3, attn, kT);
    // 6. fused span scoring
    fused_span<<<dim3(313, 10), 256, 107520>>>(attn, tok, E, W2s, sb2p, sw3p,
                                               sb3, out);
}